// round 5
// baseline (speedup 1.0000x reference)
#include <cuda_runtime.h>
#include <cuda_fp16.h>
#include <math.h>
#include <stdint.h>

// Problem dims
#define B_   256
#define T_   200
#define E_   512
#define H_   8
#define DH_  64
#define FF_  2048
#define BT_  (B_*T_)

#define NEGV (-4294967295.0f)

// ---------------------------------------------------------------------------
// GEMM config: 128x128 CTA tile, BK=32, 16 warps (4x4), warp tile 32x32.
// 512 threads -> ~110 regs/thread -> 1 CTA/SM but 16 warps resident.
// ---------------------------------------------------------------------------
#define GBM 128
#define GBN 128
#define GBK 32
#define PADH 40
#define PLANE_B (GBM * PADH * 2)
#define STAGE_B (4 * PLANE_B)
#define GEMM_DSMEM (2 * STAGE_B)

__device__ __forceinline__ void mma16816(float* c, const uint32_t* a, const uint32_t* b) {
    asm volatile(
        "mma.sync.aligned.m16n8k16.row.col.f32.f16.f16.f32 "
        "{%0,%1,%2,%3}, {%4,%5,%6,%7}, {%8,%9}, {%0,%1,%2,%3};"
        : "+f"(c[0]), "+f"(c[1]), "+f"(c[2]), "+f"(c[3])
        : "r"(a[0]), "r"(a[1]), "r"(a[2]), "r"(a[3]), "r"(b[0]), "r"(b[1]));
}

__device__ __forceinline__ void split2(float x, float y, uint32_t& hi, uint32_t& lo) {
    __half hx = __float2half_rn(x);
    __half hy = __float2half_rn(y);
    __half lx = __float2half_rn(x - __half2float(hx));
    __half ly = __float2half_rn(y - __half2float(hy));
    hi = (uint32_t)__half_as_ushort(hx) | ((uint32_t)__half_as_ushort(hy) << 16);
    lo = (uint32_t)__half_as_ushort(lx) | ((uint32_t)__half_as_ushort(ly) << 16);
}

template <bool RELU, bool ADD>
__global__ void __launch_bounds__(512)
hgemm_kernel(const float* __restrict__ A, const float* __restrict__ Bt,
             const float* __restrict__ C0, float* __restrict__ C,
             int M, int N, int K) {
    extern __shared__ char smem[];

    const int tid = threadIdx.x;
    const int wid = tid >> 5, lane = tid & 31;
    const int m0 = blockIdx.y * GBM;
    const int n0 = blockIdx.x * GBN;
    const int wm = (wid >> 2) * 32;      // warp row: 0,32,64,96
    const int wn = (wid & 3) * 32;       // warp col: 0,32,64,96
    const int g = lane >> 2, t = lane & 3;

    float acc[2][4][4];
#pragma unroll
    for (int i = 0; i < 2; i++)
#pragma unroll
        for (int j = 0; j < 4; j++)
#pragma unroll
            for (int k = 0; k < 4; k++) acc[i][j][k] = 0.f;

    const int nt = K / GBK;
    float4 la[2], lb[2];

    auto LDG = [&](int k0) {
#pragma unroll
        for (int j = 0; j < 2; j++) {
            int f4 = tid + j * 512;
            int r = f4 >> 3, c4 = f4 & 7;
            la[j] = *(const float4*)(A + (size_t)(m0 + r) * K + k0 + c4 * 4);
            lb[j] = *(const float4*)(Bt + (size_t)(n0 + r) * K + k0 + c4 * 4);
        }
    };
    auto STS = [&](int s) {
        char* ahi = smem + s * STAGE_B;
        char* alo = ahi + PLANE_B;
        char* bhi = alo + PLANE_B;
        char* blo = bhi + PLANE_B;
#pragma unroll
        for (int j = 0; j < 2; j++) {
            int f4 = tid + j * 512;
            int r = f4 >> 3, c4 = f4 & 7;
            uint32_t off = r * (PADH * 2) + c4 * 8;
            uint32_t h01, l01, h23, l23;
            split2(la[j].x, la[j].y, h01, l01);
            split2(la[j].z, la[j].w, h23, l23);
            *(uint2*)(ahi + off) = make_uint2(h01, h23);
            *(uint2*)(alo + off) = make_uint2(l01, l23);
            split2(lb[j].x, lb[j].y, h01, l01);
            split2(lb[j].z, lb[j].w, h23, l23);
            *(uint2*)(bhi + off) = make_uint2(h01, h23);
            *(uint2*)(blo + off) = make_uint2(l01, l23);
        }
    };

    LDG(0);
    STS(0);

    for (int it = 0; it < nt; it++) {
        __syncthreads();
        if (it + 1 < nt) LDG((it + 1) * GBK);

        const char* ahi = smem + (it & 1) * STAGE_B;
        const char* alo = ahi + PLANE_B;
        const char* bhi = alo + PLANE_B;
        const char* blo = bhi + PLANE_B;

#pragma unroll
        for (int ks = 0; ks < GBK; ks += 16) {
            uint32_t ah[2][4], al[2][4], bh[4][2], bl[4][2];
#pragma unroll
            for (int mt = 0; mt < 2; mt++) {
                int row = wm + mt * 16 + g;
                uint32_t o0 = row * (PADH * 2) + (ks + 2 * t) * 2;
                uint32_t o1 = (row + 8) * (PADH * 2) + (ks + 2 * t) * 2;
                ah[mt][0] = *(const uint32_t*)(ahi + o0);
                ah[mt][1] = *(const uint32_t*)(ahi + o1);
                ah[mt][2] = *(const uint32_t*)(ahi + o0 + 16);
                ah[mt][3] = *(const uint32_t*)(ahi + o1 + 16);
                al[mt][0] = *(const uint32_t*)(alo + o0);
                al[mt][1] = *(const uint32_t*)(alo + o1);
                al[mt][2] = *(const uint32_t*)(alo + o0 + 16);
                al[mt][3] = *(const uint32_t*)(alo + o1 + 16);
            }
#pragma unroll
            for (int ntl = 0; ntl < 4; ntl++) {
                int rn = wn + ntl * 8 + g;
                uint32_t ob = rn * (PADH * 2) + (ks + 2 * t) * 2;
                bh[ntl][0] = *(const uint32_t*)(bhi + ob);
                bh[ntl][1] = *(const uint32_t*)(bhi + ob + 16);
                bl[ntl][0] = *(const uint32_t*)(blo + ob);
                bl[ntl][1] = *(const uint32_t*)(blo + ob + 16);
            }
#pragma unroll
            for (int mt = 0; mt < 2; mt++)
#pragma unroll
                for (int ntl = 0; ntl < 4; ntl++) {
                    mma16816(acc[mt][ntl], ah[mt], bh[ntl]);
                    mma16816(acc[mt][ntl], ah[mt], bl[ntl]);
                    mma16816(acc[mt][ntl], al[mt], bh[ntl]);
                }
        }
        if (it + 1 < nt) STS((it + 1) & 1);
    }

#pragma unroll
    for (int mt = 0; mt < 2; mt++)
#pragma unroll
        for (int ntl = 0; ntl < 4; ntl++) {
            int row = m0 + wm + mt * 16 + g;
            int col = n0 + wn + ntl * 8 + 2 * t;
            size_t i0 = (size_t)row * N + col;
            size_t i1 = (size_t)(row + 8) * N + col;
            float2 v0 = make_float2(acc[mt][ntl][0], acc[mt][ntl][1]);
            float2 v1 = make_float2(acc[mt][ntl][2], acc[mt][ntl][3]);
            if (ADD) {
                float2 c0 = *(const float2*)&C0[i0];
                float2 c1 = *(const float2*)&C0[i1];
                v0.x += c0.x; v0.y += c0.y; v1.x += c1.x; v1.y += c1.y;
            }
            if (RELU) {
                v0.x = fmaxf(v0.x, 0.f); v0.y = fmaxf(v0.y, 0.f);
                v1.x = fmaxf(v1.x, 0.f); v1.y = fmaxf(v1.y, 0.f);
            }
            *(float2*)&C[i0] = v0;
            *(float2*)&C[i1] = v1;
        }
}

// ---------------------------------------------------------------------------
// Scratch
// ---------------------------------------------------------------------------
#define WT_FLOATS (3 * E_ * E_ + 2 * E_ * FF_)
__device__ float g_scratch[(size_t)7 * BT_ * E_ + (size_t)BT_ * FF_ + WT_FLOATS];

// ---------------------------------------------------------------------------
// positional encoding add
// ---------------------------------------------------------------------------
__global__ void add_pos_kernel(const float4* __restrict__ q,
                               const float4* __restrict__ k,
                               const float4* __restrict__ pq,
                               const float4* __restrict__ pk,
                               float4* __restrict__ qin,
                               float4* __restrict__ kin) {
    int i  = blockIdx.x * 256 + threadIdx.x;
    int pi = i % (T_ * E_ / 4);
    const float s = 22.62741699796952f;
    float4 a = q[i], p = pq[pi];
    float4 r;
    r.x = a.x + p.x * s; r.y = a.y + p.y * s;
    r.z = a.z + p.z * s; r.w = a.w + p.w * s;
    qin[i] = r;
    a = k[i]; p = pk[pi];
    r.x = a.x + p.x * s; r.y = a.y + p.y * s;
    r.z = a.z + p.z * s; r.w = a.w + p.w * s;
    kin[i] = r;
}

// ---------------------------------------------------------------------------
// all 5 weight transposes in ONE launch.  WT[n,k] = W[k,n]
// ---------------------------------------------------------------------------
__global__ void transpose_all_kernel(
    const float* __restrict__ WQ, const float* __restrict__ WK,
    const float* __restrict__ WV, const float* __restrict__ F1,
    const float* __restrict__ F2,
    float* __restrict__ wqT, float* __restrict__ wkT, float* __restrict__ wvT,
    float* __restrict__ f1T, float* __restrict__ f2T) {
    __shared__ float t[32][33];
    int bid = blockIdx.x;
    const float* W; float* WT; int K, N, tile;
    if (bid < 256)       { W = WQ; WT = wqT; K = E_;  N = E_;  tile = bid; }
    else if (bid < 512)  { W = WK; WT = wkT; K = E_;  N = E_;  tile = bid - 256; }
    else if (bid < 768)  { W = WV; WT = wvT; K = E_;  N = E_;  tile = bid - 512; }
    else if (bid < 1792) { W = F1; WT = f1T; K = E_;  N = FF_; tile = bid - 768; }
    else                 { W = F2; WT = f2T; K = FF_; N = E_;  tile = bid - 1792; }
    int ntx = N / 32;
    int bn = (tile % ntx) * 32, bk = (tile / ntx) * 32;
    for (int j = threadIdx.y; j < 32; j += 8)
        t[j][threadIdx.x] = W[(size_t)(bk + j) * N + bn + threadIdx.x];
    __syncthreads();
    for (int j = threadIdx.y; j < 32; j += 8)
        WT[(size_t)(bn + j) * K + bk + threadIdx.x] = t[threadIdx.x][j];
}

// ---------------------------------------------------------------------------
// fused masked attention per (b,h)
// ---------------------------------------------------------------------------
#define ATS 68
__global__ void __launch_bounds__(256)
attn_kernel(const int* __restrict__ qlen, const int* __restrict__ klen,
            const float* __restrict__ Q, const float* __restrict__ KV,
            const float* __restrict__ qin, float* __restrict__ ctx) {
    extern __shared__ float sm[];
    float* Ks = sm;
    float* Vs = Ks + T_ * ATS;
    float* Sc = Vs + T_ * ATS;
    float* Qs = Sc + 32 * T_;

    const int h = blockIdx.x, b = blockIdx.y;
    const int tid = threadIdx.x, w = tid >> 5, lane = tid & 31;
    const int kl = klen[b], ql = qlen[b];
    const int kbmax = (kl + 31) >> 5;

    for (int i = tid; i < T_ * 16; i += 256) {
        int t = i >> 4, d4 = (i & 15) * 4;
        size_t gk = (size_t)(b * T_ + t) * 1024 + h * DH_ + d4;
        *(float4*)&Ks[t * ATS + d4] = *(const float4*)&KV[gk];
        *(float4*)&Vs[t * ATS + d4] = *(const float4*)&KV[gk + 512];
    }
    __syncthreads();

    for (int bi = w; bi * 4 < T_; bi += 8) {
        const int qq0 = bi * 4;
        const int w4 = w * 4;

#pragma unroll
        for (int j = 0; j < 2; j++) {
            int f4 = lane + j * 32;
            int r = f4 >> 4, d4 = (f4 & 15) * 4;
            *(float4*)&Qs[(w4 + r) * 64 + d4] =
                *(const float4*)&Q[(size_t)(b * T_ + qq0 + r) * E_ + h * DH_ + d4];
        }
        __syncwarp();

        float mx[4] = {-INFINITY, -INFINITY, -INFINITY, -INFINITY};
        for (int kb = 0; kb < kbmax; kb++) {
            int kk = kb * 32 + lane;
            if (kk < T_) {
                float a0 = 0.f, a1 = 0.f, a2 = 0.f, a3 = 0.f;
                const float* kr = &Ks[kk * ATS];
                const float* q0 = &Qs[(w4 + 0) * 64];
                const float* q1 = &Qs[(w4 + 1) * 64];
                const float* q2 = &Qs[(w4 + 2) * 64];
                const float* q3 = &Qs[(w4 + 3) * 64];
#pragma unroll
                for (int d = 0; d < DH_; d += 4) {
                    float4 kv = *(const float4*)&kr[d];
                    float4 qa = *(const float4*)&q0[d];
                    a0 += kv.x * qa.x + kv.y * qa.y + kv.z * qa.z + kv.w * qa.w;
                    qa = *(const float4*)&q1[d];
                    a1 += kv.x * qa.x + kv.y * qa.y + kv.z * qa.z + kv.w * qa.w;
                    qa = *(const float4*)&q2[d];
                    a2 += kv.x * qa.x + kv.y * qa.y + kv.z * qa.z + kv.w * qa.w;
                    qa = *(const float4*)&q3[d];
                    a3 += kv.x * qa.x + kv.y * qa.y + kv.z * qa.z + kv.w * qa.w;
                }
                float sv[4] = {a0, a1, a2, a3};
#pragma unroll
                for (int r = 0; r < 4; r++) {
                    float s = (kk < kl && kk != qq0 + r) ? sv[r] * 0.125f : NEGV;
                    Sc[(w4 + r) * T_ + kk] = s;
                    mx[r] = fmaxf(mx[r], s);
                }
            }
        }
#pragma unroll
        for (int r = 0; r < 4; r++)
#pragma unroll
            for (int off = 16; off; off >>= 1)
                mx[r] = fmaxf(mx[r], __shfl_xor_sync(0xffffffff, mx[r], off));

        float sum[4] = {0.f, 0.f, 0.f, 0.f};
        for (int kb = 0; kb < kbmax; kb++) {
            int kk = kb * 32 + lane;
            if (kk < T_) {
#pragma unroll
                for (int r = 0; r < 4; r++) {
                    float e = __expf(Sc[(w4 + r) * T_ + kk] - mx[r]);
                    Sc[(w4 + r) * T_ + kk] = e;
                    sum[r] += e;
                }
            }
        }
        bool am[4];
        bool any_am = false;
#pragma unroll
        for (int r = 0; r < 4; r++) { am[r] = (mx[r] == NEGV); any_am |= am[r]; }
        if (any_am) {
            for (int kb = kbmax; kb < 7; kb++) {
                int kk = kb * 32 + lane;
                if (kk < T_) {
#pragma unroll
                    for (int r = 0; r < 4; r++) {
                        float v = am[r] ? 1.f : 0.f;
                        Sc[(w4 + r) * T_ + kk] = v;
                        sum[r] += v;
                    }
                }
            }
        }
#pragma unroll
        for (int r = 0; r < 4; r++)
#pragma unroll
            for (int off = 16; off; off >>= 1)
                sum[r] += __shfl_xor_sync(0xffffffff, sum[r], off);

        float inv[4];
#pragma unroll
        for (int r = 0; r < 4; r++)
            inv[r] = (qq0 + r < ql) ? (1.0f / sum[r]) : 0.0f;
        __syncwarp();

        int kku = any_am ? T_ : min(kbmax * 32, T_);
        float o0[4] = {0.f, 0.f, 0.f, 0.f};
        float o1[4] = {0.f, 0.f, 0.f, 0.f};
        for (int kk = 0; kk < kku; kk++) {
            float v0 = Vs[kk * ATS + lane];
            float v1 = Vs[kk * ATS + lane + 32];
#pragma unroll
            for (int r = 0; r < 4; r++) {
                float p = Sc[(w4 + r) * T_ + kk];
                o0[r] += p * v0;
                o1[r] += p * v1;
            }
        }
#pragma unroll
        for (int r = 0; r < 4; r++) {
            size_t qb = (size_t)(b * T_ + qq0 + r) * E_ + h * DH_;
            ctx[qb + lane]      = o0[r] * inv[r] + qin[qb + lane];
            ctx[qb + lane + 32] = o1[r] * inv[r] + qin[qb + lane + 32];
        }
        __syncwarp();
    }
}

// ---------------------------------------------------------------------------
// mean over T -> (B,1,E)
// ---------------------------------------------------------------------------
__global__ void mean_kernel(const float* __restrict__ o2, float* __restrict__ out) {
    int b = blockIdx.x, e = threadIdx.x;
    float s = 0.f;
    for (int t = 0; t < T_; t++)
        s += o2[(size_t)(b * T_ + t) * E_ + e];
    out[b * E_ + e] = s * (1.0f / T_);
}

// ---------------------------------------------------------------------------
// Launch
// ---------------------------------------------------------------------------
extern "C" void kernel_launch(void* const* d_in, const int* in_sizes, int n_in,
                              void* d_out, int out_size) {
    const float* queries = (const float*)d_in[0];
    const float* keys    = (const float*)d_in[1];
    const int*   qlen    = (const int*)d_in[2];
    const int*   klen    = (const int*)d_in[3];
    const float* pos_q   = (const float*)d_in[4];
    const float* pos_k   = (const float*)d_in[5];
    const float* W_Q     = (const float*)d_in[6];
    const float* W_K     = (const float*)d_in[7];
    const float* W_V     = (const float*)d_in[8];
    const float* fw1     = (const float*)d_in[9];
    const float* fw2     = (const float*)d_in[10];
    float*       out     = (float*)d_out;

    float* base = nullptr;
    cudaGetSymbolAddress((void**)&base, g_scratch);
    const size_t BTE = (size_t)BT_ * E_;
    float* qin = base;
    float* kin = base + 1 * BTE;
    float* Qp  = base + 2 * BTE;
    float* KVb = base + 3 * BTE;
    float* ctx = base + 5 * BTE;
    float* o2  = base + 6 * BTE;
    float* hid = base + 7 * BTE;
    float* wqT = hid + (size_t)BT_ * FF_;
    float* wkT = wqT + E_ * E_;
    float* wvT = wkT + E_ * E_;
    float* f1T = wvT + E_ * E_;
    float* f2T = f1T + (size_t)E_ * FF_;

    cudaFuncSetAttribute(hgemm_kernel<false, false>,
                         cudaFuncAttributeMaxDynamicSharedMemorySize, GEMM_DSMEM);
    cudaFuncSetAttribute(hgemm_kernel<true, false>,
                         cudaFuncAttributeMaxDynamicSharedMemorySize, GEMM_DSMEM);
    cudaFuncSetAttribute(hgemm_kernel<false, true>,
                         cudaFuncAttributeMaxDynamicSharedMemorySize, GEMM_DSMEM);
    const int SMEM_ATT = (2 * T_ * ATS + 32 * T_ + 32 * 64) * (int)sizeof(float);
    cudaFuncSetAttribute(attn_kernel,
                         cudaFuncAttributeMaxDynamicSharedMemorySize, SMEM_ATT);

    // 1. all weight transposes
    transpose_all_kernel<<<2816, dim3(32, 8)>>>(W_Q, W_K, W_V, fw1, fw2,
                                                wqT, wkT, wvT, f1T, f2T);
    // 2. positional encoding
    add_pos_kernel<<<(BT_ * E_ / 4) / 256, 256>>>(
        (const float4*)queries, (const float4*)keys,
        (const float4*)pos_q, (const float4*)pos_k,
        (float4*)qin, (float4*)kin);

    // 3. Q projection
    hgemm_kernel<false, false><<<dim3(E_ / GBN, BT_ / GBM), 512, GEMM_DSMEM>>>(
        qin, wqT, nullptr, Qp, BT_, E_, E_);
    // 4. merged K+V projection
    hgemm_kernel<false, false><<<dim3(2 * E_ / GBN, BT_ / GBM), 512, GEMM_DSMEM>>>(
        kin, wkT, nullptr, KVb, BT_, 2 * E_, E_);

    // 5. fused attention (+ residual)
    attn_kernel<<<dim3(H_, B_), 256, SMEM_ATT>>>(qlen, klen, Qp, KVb, qin, ctx);

    // 6. FFN up + ReLU
    hgemm_kernel<true, false><<<dim3(FF_ / GBN, BT_ / GBM), 512, GEMM_DSMEM>>>(
        ctx, f1T, nullptr, hid, BT_, FF_, E_);

    // 7. FFN down + residual
    hgemm_kernel<false, true><<<dim3(E_ / GBN, BT_ / GBM), 512, GEMM_DSMEM>>>(
        hid, f2T, ctx, o2, BT_, E_, FF_);

    // 8. mean over time
    mean_kernel<<<B_, E_>>>(o2, out);
}

// round 7
// speedup vs baseline: 1.1643x; 1.1643x over previous
#include <cuda_runtime.h>
#include <cuda_fp16.h>
#include <math.h>
#include <stdint.h>

// Problem dims
#define B_   256
#define T_   200
#define E_   512
#define H_   8
#define DH_  64
#define FF_  2048
#define BT_  (B_*T_)

#define NEGV (-4294967295.0f)

// ---------------------------------------------------------------------------
// GEMM config: 128x128 CTA tile, BK=32, 8 warps (2x4), warp tile 64x32.
// T3=true : 3-term fp16 split (fp32-grade) for QKV.
// T3=false: 2-term (ah*(bh+bl) = fp16 activations x full weights) for FFN.
// ---------------------------------------------------------------------------
#define GBM 128
#define GBN 128
#define GBK 32
#define PADH 40
#define PLANE_B (GBM * PADH * 2)
#define STAGE_B (4 * PLANE_B)
#define GEMM_DSMEM (2 * STAGE_B)

__device__ __forceinline__ void mma16816(float* c, const uint32_t* a, const uint32_t* b) {
    asm volatile(
        "mma.sync.aligned.m16n8k16.row.col.f32.f16.f16.f32 "
        "{%0,%1,%2,%3}, {%4,%5,%6,%7}, {%8,%9}, {%0,%1,%2,%3};"
        : "+f"(c[0]), "+f"(c[1]), "+f"(c[2]), "+f"(c[3])
        : "r"(a[0]), "r"(a[1]), "r"(a[2]), "r"(a[3]), "r"(b[0]), "r"(b[1]));
}

__device__ __forceinline__ void split2(float x, float y, uint32_t& hi, uint32_t& lo) {
    __half hx = __float2half_rn(x);
    __half hy = __float2half_rn(y);
    __half lx = __float2half_rn(x - __half2float(hx));
    __half ly = __float2half_rn(y - __half2float(hy));
    hi = (uint32_t)__half_as_ushort(hx) | ((uint32_t)__half_as_ushort(hy) << 16);
    lo = (uint32_t)__half_as_ushort(lx) | ((uint32_t)__half_as_ushort(ly) << 16);
}
__device__ __forceinline__ uint32_t hi2(float x, float y) {
    __half hx = __float2half_rn(x);
    __half hy = __float2half_rn(y);
    return (uint32_t)__half_as_ushort(hx) | ((uint32_t)__half_as_ushort(hy) << 16);
}

template <bool RELU, bool ADD, bool T3>
__global__ void __launch_bounds__(256)
hgemm_kernel(const float* __restrict__ A, const float* __restrict__ Bt,
             const float* __restrict__ C0, float* __restrict__ C,
             int M, int N, int K) {
    extern __shared__ char smem[];

    const int tid = threadIdx.x;
    const int wid = tid >> 5, lane = tid & 31;
    const int m0 = blockIdx.y * GBM;
    const int n0 = blockIdx.x * GBN;
    const int wm = (wid >> 2) * 64;
    const int wn = (wid & 3) * 32;
    const int g = lane >> 2, t = lane & 3;

    float acc[4][4][4];
#pragma unroll
    for (int i = 0; i < 4; i++)
#pragma unroll
        for (int j = 0; j < 4; j++)
#pragma unroll
            for (int k = 0; k < 4; k++) acc[i][j][k] = 0.f;

    const int nt = K / GBK;
    float4 la[4], lb[4];

    auto LDG = [&](int k0) {
#pragma unroll
        for (int j = 0; j < 4; j++) {
            int f4 = tid + j * 256;
            int r = f4 >> 3, c4 = f4 & 7;
            la[j] = *(const float4*)(A + (size_t)(m0 + r) * K + k0 + c4 * 4);
            lb[j] = *(const float4*)(Bt + (size_t)(n0 + r) * K + k0 + c4 * 4);
        }
    };
    auto STS = [&](int s) {
        char* ahi = smem + s * STAGE_B;
        char* alo = ahi + PLANE_B;
        char* bhi = alo + PLANE_B;
        char* blo = bhi + PLANE_B;
#pragma unroll
        for (int j = 0; j < 4; j++) {
            int f4 = tid + j * 256;
            int r = f4 >> 3, c4 = f4 & 7;
            uint32_t off = r * (PADH * 2) + c4 * 8;
            if (T3) {
                uint32_t h01, l01, h23, l23;
                split2(la[j].x, la[j].y, h01, l01);
                split2(la[j].z, la[j].w, h23, l23);
                *(uint2*)(ahi + off) = make_uint2(h01, h23);
                *(uint2*)(alo + off) = make_uint2(l01, l23);
            } else {
                *(uint2*)(ahi + off) =
                    make_uint2(hi2(la[j].x, la[j].y), hi2(la[j].z, la[j].w));
            }
            uint32_t h01, l01, h23, l23;
            split2(lb[j].x, lb[j].y, h01, l01);
            split2(lb[j].z, lb[j].w, h23, l23);
            *(uint2*)(bhi + off) = make_uint2(h01, h23);
            *(uint2*)(blo + off) = make_uint2(l01, l23);
        }
    };

    LDG(0);
    STS(0);

    for (int it = 0; it < nt; it++) {
        __syncthreads();
        if (it + 1 < nt) LDG((it + 1) * GBK);

        const char* ahi = smem + (it & 1) * STAGE_B;
        const char* alo = ahi + PLANE_B;
        const char* bhi = alo + PLANE_B;
        const char* blo = bhi + PLANE_B;

#pragma unroll
        for (int ks = 0; ks < GBK; ks += 16) {
            uint32_t ah[4][4], al[4][4], bh[4][2], bl[4][2];
#pragma unroll
            for (int mt = 0; mt < 4; mt++) {
                int row = wm + mt * 16 + g;
                uint32_t o0 = row * (PADH * 2) + (ks + 2 * t) * 2;
                uint32_t o1 = (row + 8) * (PADH * 2) + (ks + 2 * t) * 2;
                ah[mt][0] = *(const uint32_t*)(ahi + o0);
                ah[mt][1] = *(const uint32_t*)(ahi + o1);
                ah[mt][2] = *(const uint32_t*)(ahi + o0 + 16);
                ah[mt][3] = *(const uint32_t*)(ahi + o1 + 16);
                if (T3) {
                    al[mt][0] = *(const uint32_t*)(alo + o0);
                    al[mt][1] = *(const uint32_t*)(alo + o1);
                    al[mt][2] = *(const uint32_t*)(alo + o0 + 16);
                    al[mt][3] = *(const uint32_t*)(alo + o1 + 16);
                }
            }
#pragma unroll
            for (int ntl = 0; ntl < 4; ntl++) {
                int rn = wn + ntl * 8 + g;
                uint32_t ob = rn * (PADH * 2) + (ks + 2 * t) * 2;
                bh[ntl][0] = *(const uint32_t*)(bhi + ob);
                bh[ntl][1] = *(const uint32_t*)(bhi + ob + 16);
                bl[ntl][0] = *(const uint32_t*)(blo + ob);
                bl[ntl][1] = *(const uint32_t*)(blo + ob + 16);
            }
#pragma unroll
            for (int mt = 0; mt < 4; mt++)
#pragma unroll
                for (int ntl = 0; ntl < 4; ntl++) {
                    mma16816(acc[mt][ntl], ah[mt], bh[ntl]);
                    mma16816(acc[mt][ntl], ah[mt], bl[ntl]);
                    if (T3) mma16816(acc[mt][ntl], al[mt], bh[ntl]);
                }
        }
        if (it + 1 < nt) STS((it + 1) & 1);
    }

#pragma unroll
    for (int mt = 0; mt < 4; mt++)
#pragma unroll
        for (int ntl = 0; ntl < 4; ntl++) {
            int row = m0 + wm + mt * 16 + g;
            int col = n0 + wn + ntl * 8 + 2 * t;
            size_t i0 = (size_t)row * N + col;
            size_t i1 = (size_t)(row + 8) * N + col;
            float2 v0 = make_float2(acc[mt][ntl][0], acc[mt][ntl][1]);
            float2 v1 = make_float2(acc[mt][ntl][2], acc[mt][ntl][3]);
            if (ADD) {
                float2 c0 = *(const float2*)&C0[i0];
                float2 c1 = *(const float2*)&C0[i1];
                v0.x += c0.x; v0.y += c0.y; v1.x += c1.x; v1.y += c1.y;
            }
            if (RELU) {
                v0.x = fmaxf(v0.x, 0.f); v0.y = fmaxf(v0.y, 0.f);
                v1.x = fmaxf(v1.x, 0.f); v1.y = fmaxf(v1.y, 0.f);
            }
            *(float2*)&C[i0] = v0;
            *(float2*)&C[i1] = v1;
        }
}

// ---------------------------------------------------------------------------
// Scratch
// ---------------------------------------------------------------------------
#define WT_FLOATS (3 * E_ * E_ + 2 * E_ * FF_)
__device__ float g_scratch[(size_t)7 * BT_ * E_ + (size_t)BT_ * FF_ + WT_FLOATS];

// ---------------------------------------------------------------------------
// positional encoding add
// ---------------------------------------------------------------------------
__global__ void add_pos_kernel(const float4* __restrict__ q,
                               const float4* __restrict__ k,
                               const float4* __restrict__ pq,
                               const float4* __restrict__ pk,
                               float4* __restrict__ qin,
                               float4* __restrict__ kin) {
    int i  = blockIdx.x * 256 + threadIdx.x;
    int pi = i % (T_ * E_ / 4);
    const float s = 22.62741699796952f;
    float4 a = q[i], p = pq[pi];
    float4 r;
    r.x = a.x + p.x * s; r.y = a.y + p.y * s;
    r.z = a.z + p.z * s; r.w = a.w + p.w * s;
    qin[i] = r;
    a = k[i]; p = pk[pi];
    r.x = a.x + p.x * s; r.y = a.y + p.y * s;
    r.z = a.z + p.z * s; r.w = a.w + p.w * s;
    kin[i] = r;
}

// ---------------------------------------------------------------------------
// all 5 weight transposes in ONE launch.  WT[n,k] = W[k,n]
// ---------------------------------------------------------------------------
__global__ void transpose_all_kernel(
    const float* __restrict__ WQ, const float* __restrict__ WK,
    const float* __restrict__ WV, const float* __restrict__ F1,
    const float* __restrict__ F2,
    float* __restrict__ wqT, float* __restrict__ wkT, float* __restrict__ wvT,
    float* __restrict__ f1T, float* __restrict__ f2T) {
    __shared__ float t[32][33];
    int bid = blockIdx.x;
    const float* W; float* WT; int K, N, tile;
    if (bid < 256)       { W = WQ; WT = wqT; K = E_;  N = E_;  tile = bid; }
    else if (bid < 512)  { W = WK; WT = wkT; K = E_;  N = E_;  tile = bid - 256; }
    else if (bid < 768)  { W = WV; WT = wvT; K = E_;  N = E_;  tile = bid - 512; }
    else if (bid < 1792) { W = F1; WT = f1T; K = E_;  N = FF_; tile = bid - 768; }
    else                 { W = F2; WT = f2T; K = FF_; N = E_;  tile = bid - 1792; }
    int ntx = N / 32;
    int bn = (tile % ntx) * 32, bk = (tile / ntx) * 32;
    for (int j = threadIdx.y; j < 32; j += 8)
        t[j][threadIdx.x] = W[(size_t)(bk + j) * N + bn + threadIdx.x];
    __syncthreads();
    for (int j = threadIdx.y; j < 32; j += 8)
        WT[(size_t)(bn + j) * K + bk + threadIdx.x] = t[threadIdx.x][j];
}

// ---------------------------------------------------------------------------
// fused masked attention per (b,h)
// ---------------------------------------------------------------------------
#define ATS 68
__global__ void __launch_bounds__(256)
attn_kernel(const int* __restrict__ qlen, const int* __restrict__ klen,
            const float* __restrict__ Q, const float* __restrict__ KV,
            const float* __restrict__ qin, float* __restrict__ ctx) {
    extern __shared__ float sm[];
    float* Ks = sm;
    float* Vs = Ks + T_ * ATS;
    float* Sc = Vs + T_ * ATS;
    float* Qs = Sc + 32 * T_;

    const int h = blockIdx.x, b = blockIdx.y;
    const int tid = threadIdx.x, w = tid >> 5, lane = tid & 31;
    const int kl = klen[b], ql = qlen[b];
    const int kbmax = (kl + 31) >> 5;

    for (int i = tid; i < T_ * 16; i += 256) {
        int t = i >> 4, d4 = (i & 15) * 4;
        size_t gk = (size_t)(b * T_ + t) * 1024 + h * DH_ + d4;
        *(float4*)&Ks[t * ATS + d4] = *(const float4*)&KV[gk];
        *(float4*)&Vs[t * ATS + d4] = *(const float4*)&KV[gk + 512];
    }
    __syncthreads();

    for (int bi = w; bi * 4 < T_; bi += 8) {
        const int qq0 = bi * 4;
        const int w4 = w * 4;

#pragma unroll
        for (int j = 0; j < 2; j++) {
            int f4 = lane + j * 32;
            int r = f4 >> 4, d4 = (f4 & 15) * 4;
            *(float4*)&Qs[(w4 + r) * 64 + d4] =
                *(const float4*)&Q[(size_t)(b * T_ + qq0 + r) * E_ + h * DH_ + d4];
        }
        __syncwarp();

        float mx[4] = {-INFINITY, -INFINITY, -INFINITY, -INFINITY};
        for (int kb = 0; kb < kbmax; kb++) {
            int kk = kb * 32 + lane;
            if (kk < T_) {
                float a0 = 0.f, a1 = 0.f, a2 = 0.f, a3 = 0.f;
                const float* kr = &Ks[kk * ATS];
                const float* q0 = &Qs[(w4 + 0) * 64];
                const float* q1 = &Qs[(w4 + 1) * 64];
                const float* q2 = &Qs[(w4 + 2) * 64];
                const float* q3 = &Qs[(w4 + 3) * 64];
#pragma unroll
                for (int d = 0; d < DH_; d += 4) {
                    float4 kv = *(const float4*)&kr[d];
                    float4 qa = *(const float4*)&q0[d];
                    a0 += kv.x * qa.x + kv.y * qa.y + kv.z * qa.z + kv.w * qa.w;
                    qa = *(const float4*)&q1[d];
                    a1 += kv.x * qa.x + kv.y * qa.y + kv.z * qa.z + kv.w * qa.w;
                    qa = *(const float4*)&q2[d];
                    a2 += kv.x * qa.x + kv.y * qa.y + kv.z * qa.z + kv.w * qa.w;
                    qa = *(const float4*)&q3[d];
                    a3 += kv.x * qa.x + kv.y * qa.y + kv.z * qa.z + kv.w * qa.w;
                }
                float sv[4] = {a0, a1, a2, a3};
#pragma unroll
                for (int r = 0; r < 4; r++) {
                    float s = (kk < kl && kk != qq0 + r) ? sv[r] * 0.125f : NEGV;
                    Sc[(w4 + r) * T_ + kk] = s;
                    mx[r] = fmaxf(mx[r], s);
                }
            }
        }
#pragma unroll
        for (int r = 0; r < 4; r++)
#pragma unroll
            for (int off = 16; off; off >>= 1)
                mx[r] = fmaxf(mx[r], __shfl_xor_sync(0xffffffff, mx[r], off));

        float sum[4] = {0.f, 0.f, 0.f, 0.f};
        for (int kb = 0; kb < kbmax; kb++) {
            int kk = kb * 32 + lane;
            if (kk < T_) {
#pragma unroll
                for (int r = 0; r < 4; r++) {
                    float e = __expf(Sc[(w4 + r) * T_ + kk] - mx[r]);
                    Sc[(w4 + r) * T_ + kk] = e;
                    sum[r] += e;
                }
            }
        }
        bool am[4];
        bool any_am = false;
#pragma unroll
        for (int r = 0; r < 4; r++) { am[r] = (mx[r] == NEGV); any_am |= am[r]; }
        if (any_am) {
            for (int kb = kbmax; kb < 7; kb++) {
                int kk = kb * 32 + lane;
                if (kk < T_) {
#pragma unroll
                    for (int r = 0; r < 4; r++) {
                        float v = am[r] ? 1.f : 0.f;
                        Sc[(w4 + r) * T_ + kk] = v;
                        sum[r] += v;
                    }
                }
            }
        }
#pragma unroll
        for (int r = 0; r < 4; r++)
#pragma unroll
            for (int off = 16; off; off >>= 1)
                sum[r] += __shfl_xor_sync(0xffffffff, sum[r], off);

        float inv[4];
#pragma unroll
        for (int r = 0; r < 4; r++)
            inv[r] = (qq0 + r < ql) ? (1.0f / sum[r]) : 0.0f;
        __syncwarp();

        int kku = any_am ? T_ : min(kbmax * 32, T_);
        float o0[4] = {0.f, 0.f, 0.f, 0.f};
        float o1[4] = {0.f, 0.f, 0.f, 0.f};
        for (int kk = 0; kk < kku; kk++) {
            float v0 = Vs[kk * ATS + lane];
            float v1 = Vs[kk * ATS + lane + 32];
#pragma unroll
            for (int r = 0; r < 4; r++) {
                float p = Sc[(w4 + r) * T_ + kk];
                o0[r] += p * v0;
                o1[r] += p * v1;
            }
        }
#pragma unroll
        for (int r = 0; r < 4; r++) {
            size_t qb = (size_t)(b * T_ + qq0 + r) * E_ + h * DH_;
            ctx[qb + lane]      = o0[r] * inv[r] + qin[qb + lane];
            ctx[qb + lane + 32] = o1[r] * inv[r] + qin[qb + lane + 32];
        }
        __syncwarp();
    }
}

// ---------------------------------------------------------------------------
// mean over T -> (B,1,E)
// ---------------------------------------------------------------------------
__global__ void mean_kernel(const float* __restrict__ o2, float* __restrict__ out) {
    int b = blockIdx.x, e = threadIdx.x;
    float s = 0.f;
    for (int t = 0; t < T_; t++)
        s += o2[(size_t)(b * T_ + t) * E_ + e];
    out[b * E_ + e] = s * (1.0f / T_);
}

// ---------------------------------------------------------------------------
// Launch
// ---------------------------------------------------------------------------
extern "C" void kernel_launch(void* const* d_in, const int* in_sizes, int n_in,
                              void* d_out, int out_size) {
    const float* queries = (const float*)d_in[0];
    const float* keys    = (const float*)d_in[1];
    const int*   qlen    = (const int*)d_in[2];
    const int*   klen    = (const int*)d_in[3];
    const float* pos_q   = (const float*)d_in[4];
    const float* pos_k   = (const float*)d_in[5];
    const float* W_Q     = (const float*)d_in[6];
    const float* W_K     = (const float*)d_in[7];
    const float* W_V     = (const float*)d_in[8];
    const float* fw1     = (const float*)d_in[9];
    const float* fw2     = (const float*)d_in[10];
    float*       out     = (float*)d_out;

    float* base = nullptr;
    cudaGetSymbolAddress((void**)&base, g_scratch);
    const size_t BTE = (size_t)BT_ * E_;
    float* qin = base;
    float* kin = base + 1 * BTE;
    float* Qp  = base + 2 * BTE;
    float* KVb = base + 3 * BTE;
    float* ctx = base + 5 * BTE;
    float* o2  = base + 6 * BTE;
    float* hid = base + 7 * BTE;
    float* wqT = hid + (size_t)BT_ * FF_;
    float* wkT = wqT + E_ * E_;
    float* wvT = wkT + E_ * E_;
    float* f1T = wvT + E_ * E_;
    float* f2T = f1T + (size_t)E_ * FF_;

    cudaFuncSetAttribute(hgemm_kernel<false, false, true>,
                         cudaFuncAttributeMaxDynamicSharedMemorySize, GEMM_DSMEM);
    cudaFuncSetAttribute(hgemm_kernel<true, false, false>,
                         cudaFuncAttributeMaxDynamicSharedMemorySize, GEMM_DSMEM);
    cudaFuncSetAttribute(hgemm_kernel<false, true, false>,
                         cudaFuncAttributeMaxDynamicSharedMemorySize, GEMM_DSMEM);
    const int SMEM_ATT = (2 * T_ * ATS + 32 * T_ + 32 * 64) * (int)sizeof(float);
    cudaFuncSetAttribute(attn_kernel,
                         cudaFuncAttributeMaxDynamicSharedMemorySize, SMEM_ATT);

    // 1. all weight transposes
    transpose_all_kernel<<<2816, dim3(32, 8)>>>(W_Q, W_K, W_V, fw1, fw2,
                                                wqT, wkT, wvT, f1T, f2T);
    // 2. positional encoding
    add_pos_kernel<<<(BT_ * E_ / 4) / 256, 256>>>(
        (const float4*)queries, (const float4*)keys,
        (const float4*)pos_q, (const float4*)pos_k,
        (float4*)qin, (float4*)kin);

    // 3. Q projection (3-term, accuracy-critical)
    hgemm_kernel<false, false, true><<<dim3(E_ / GBN, BT_ / GBM), 256, GEMM_DSMEM>>>(
        qin, wqT, nullptr, Qp, BT_, E_, E_);
    // 4. merged K+V projection (3-term)
    hgemm_kernel<false, false, true><<<dim3(2 * E_ / GBN, BT_ / GBM), 256, GEMM_DSMEM>>>(
        kin, wkT, nullptr, KVb, BT_, 2 * E_, E_);

    // 5. fused attention (+ residual)
    attn_kernel<<<dim3(H_, B_), 256, SMEM_ATT>>>(qlen, klen, Qp, KVb, qin, ctx);

    // 6. FFN up + ReLU (2-term: fp16 activations x full weights)
    hgemm_kernel<true, false, false><<<dim3(FF_ / GBN, BT_ / GBM), 256, GEMM_DSMEM>>>(
        ctx, f1T, nullptr, hid, BT_, FF_, E_);

    // 7. FFN down + residual (2-term)
    hgemm_kernel<false, true, false><<<dim3(E_ / GBN, BT_ / GBM), 256, GEMM_DSMEM>>>(
        hid, f2T, ctx, o2, BT_, E_, FF_);

    // 8. mean over time
    mean_kernel<<<B_, E_>>>(o2, out);
}

// round 8
// speedup vs baseline: 1.2692x; 1.0901x over previous
#include <cuda_runtime.h>
#include <cuda_fp16.h>
#include <math.h>
#include <stdint.h>

// Problem dims
#define B_   256
#define T_   200
#define E_   512
#define H_   8
#define DH_  64
#define FF_  2048
#define BT_  (B_*T_)

#define NEGV (-4294967295.0f)

// ---------------------------------------------------------------------------
// GEMM config: 128x128 CTA tile, BK=32, 8 warps (2x4), warp tile 64x32.
// MODE=3: ah*bh + ah*bl + al*bh  (fp32-grade, QKV)
// MODE=2: ah*bh + ah*bl          (fp16 acts x full weights)
// MODE=1: ah*bh                  (pure fp16, FFN)
// ---------------------------------------------------------------------------
#define GBM 128
#define GBN 128
#define GBK 32
#define PADH 40
#define PLANE_B (GBM * PADH * 2)
#define STAGE_B (4 * PLANE_B)
#define GEMM_DSMEM (2 * STAGE_B)

__device__ __forceinline__ void mma16816(float* c, const uint32_t* a, const uint32_t* b) {
    asm volatile(
        "mma.sync.aligned.m16n8k16.row.col.f32.f16.f16.f32 "
        "{%0,%1,%2,%3}, {%4,%5,%6,%7}, {%8,%9}, {%0,%1,%2,%3};"
        : "+f"(c[0]), "+f"(c[1]), "+f"(c[2]), "+f"(c[3])
        : "r"(a[0]), "r"(a[1]), "r"(a[2]), "r"(a[3]), "r"(b[0]), "r"(b[1]));
}

__device__ __forceinline__ void split2(float x, float y, uint32_t& hi, uint32_t& lo) {
    __half hx = __float2half_rn(x);
    __half hy = __float2half_rn(y);
    __half lx = __float2half_rn(x - __half2float(hx));
    __half ly = __float2half_rn(y - __half2float(hy));
    hi = (uint32_t)__half_as_ushort(hx) | ((uint32_t)__half_as_ushort(hy) << 16);
    lo = (uint32_t)__half_as_ushort(lx) | ((uint32_t)__half_as_ushort(ly) << 16);
}
__device__ __forceinline__ uint32_t hi2(float x, float y) {
    __half hx = __float2half_rn(x);
    __half hy = __float2half_rn(y);
    return (uint32_t)__half_as_ushort(hx) | ((uint32_t)__half_as_ushort(hy) << 16);
}

template <bool RELU, bool ADD, int MODE>
__global__ void __launch_bounds__(256)
hgemm_kernel(const float* __restrict__ A, const float* __restrict__ Bt,
             const float* __restrict__ C0, float* __restrict__ C,
             int M, int N, int K) {
    extern __shared__ char smem[];

    const int tid = threadIdx.x;
    const int wid = tid >> 5, lane = tid & 31;
    const int m0 = blockIdx.y * GBM;
    const int n0 = blockIdx.x * GBN;
    const int wm = (wid >> 2) * 64;
    const int wn = (wid & 3) * 32;
    const int g = lane >> 2, t = lane & 3;

    float acc[4][4][4];
#pragma unroll
    for (int i = 0; i < 4; i++)
#pragma unroll
        for (int j = 0; j < 4; j++)
#pragma unroll
            for (int k = 0; k < 4; k++) acc[i][j][k] = 0.f;

    const int nt = K / GBK;
    float4 la[4], lb[4];

    auto LDG = [&](int k0) {
#pragma unroll
        for (int j = 0; j < 4; j++) {
            int f4 = tid + j * 256;
            int r = f4 >> 3, c4 = f4 & 7;
            la[j] = *(const float4*)(A + (size_t)(m0 + r) * K + k0 + c4 * 4);
            lb[j] = *(const float4*)(Bt + (size_t)(n0 + r) * K + k0 + c4 * 4);
        }
    };
    auto STS = [&](int s) {
        char* ahi = smem + s * STAGE_B;
        char* alo = ahi + PLANE_B;
        char* bhi = alo + PLANE_B;
        char* blo = bhi + PLANE_B;
#pragma unroll
        for (int j = 0; j < 4; j++) {
            int f4 = tid + j * 256;
            int r = f4 >> 3, c4 = f4 & 7;
            uint32_t off = r * (PADH * 2) + c4 * 8;
            if (MODE >= 3) {
                uint32_t h01, l01, h23, l23;
                split2(la[j].x, la[j].y, h01, l01);
                split2(la[j].z, la[j].w, h23, l23);
                *(uint2*)(ahi + off) = make_uint2(h01, h23);
                *(uint2*)(alo + off) = make_uint2(l01, l23);
            } else {
                *(uint2*)(ahi + off) =
                    make_uint2(hi2(la[j].x, la[j].y), hi2(la[j].z, la[j].w));
            }
            if (MODE >= 2) {
                uint32_t h01, l01, h23, l23;
                split2(lb[j].x, lb[j].y, h01, l01);
                split2(lb[j].z, lb[j].w, h23, l23);
                *(uint2*)(bhi + off) = make_uint2(h01, h23);
                *(uint2*)(blo + off) = make_uint2(l01, l23);
            } else {
                *(uint2*)(bhi + off) =
                    make_uint2(hi2(lb[j].x, lb[j].y), hi2(lb[j].z, lb[j].w));
            }
        }
    };

    LDG(0);
    STS(0);

    for (int it = 0; it < nt; it++) {
        __syncthreads();
        if (it + 1 < nt) LDG((it + 1) * GBK);

        const char* ahi = smem + (it & 1) * STAGE_B;
        const char* alo = ahi + PLANE_B;
        const char* bhi = alo + PLANE_B;
        const char* blo = bhi + PLANE_B;

#pragma unroll
        for (int ks = 0; ks < GBK; ks += 16) {
            uint32_t ah[4][4], al[4][4], bh[4][2], bl[4][2];
#pragma unroll
            for (int mt = 0; mt < 4; mt++) {
                int row = wm + mt * 16 + g;
                uint32_t o0 = row * (PADH * 2) + (ks + 2 * t) * 2;
                uint32_t o1 = (row + 8) * (PADH * 2) + (ks + 2 * t) * 2;
                ah[mt][0] = *(const uint32_t*)(ahi + o0);
                ah[mt][1] = *(const uint32_t*)(ahi + o1);
                ah[mt][2] = *(const uint32_t*)(ahi + o0 + 16);
                ah[mt][3] = *(const uint32_t*)(ahi + o1 + 16);
                if (MODE >= 3) {
                    al[mt][0] = *(const uint32_t*)(alo + o0);
                    al[mt][1] = *(const uint32_t*)(alo + o1);
                    al[mt][2] = *(const uint32_t*)(alo + o0 + 16);
                    al[mt][3] = *(const uint32_t*)(alo + o1 + 16);
                }
            }
#pragma unroll
            for (int ntl = 0; ntl < 4; ntl++) {
                int rn = wn + ntl * 8 + g;
                uint32_t ob = rn * (PADH * 2) + (ks + 2 * t) * 2;
                bh[ntl][0] = *(const uint32_t*)(bhi + ob);
                bh[ntl][1] = *(const uint32_t*)(bhi + ob + 16);
                if (MODE >= 2) {
                    bl[ntl][0] = *(const uint32_t*)(blo + ob);
                    bl[ntl][1] = *(const uint32_t*)(blo + ob + 16);
                }
            }
#pragma unroll
            for (int mt = 0; mt < 4; mt++)
#pragma unroll
                for (int ntl = 0; ntl < 4; ntl++) {
                    mma16816(acc[mt][ntl], ah[mt], bh[ntl]);
                    if (MODE >= 2) mma16816(acc[mt][ntl], ah[mt], bl[ntl]);
                    if (MODE >= 3) mma16816(acc[mt][ntl], al[mt], bh[ntl]);
                }
        }
        if (it + 1 < nt) STS((it + 1) & 1);
    }

#pragma unroll
    for (int mt = 0; mt < 4; mt++)
#pragma unroll
        for (int ntl = 0; ntl < 4; ntl++) {
            int row = m0 + wm + mt * 16 + g;
            int col = n0 + wn + ntl * 8 + 2 * t;
            size_t i0 = (size_t)row * N + col;
            size_t i1 = (size_t)(row + 8) * N + col;
            float2 v0 = make_float2(acc[mt][ntl][0], acc[mt][ntl][1]);
            float2 v1 = make_float2(acc[mt][ntl][2], acc[mt][ntl][3]);
            if (ADD) {
                float2 c0 = *(const float2*)&C0[i0];
                float2 c1 = *(const float2*)&C0[i1];
                v0.x += c0.x; v0.y += c0.y; v1.x += c1.x; v1.y += c1.y;
            }
            if (RELU) {
                v0.x = fmaxf(v0.x, 0.f); v0.y = fmaxf(v0.y, 0.f);
                v1.x = fmaxf(v1.x, 0.f); v1.y = fmaxf(v1.y, 0.f);
            }
            *(float2*)&C[i0] = v0;
            *(float2*)&C[i1] = v1;
        }
}

// ---------------------------------------------------------------------------
// Scratch
// ---------------------------------------------------------------------------
#define WT_FLOATS (3 * E_ * E_ + 2 * E_ * FF_)
__device__ float g_scratch[(size_t)7 * BT_ * E_ + (size_t)BT_ * FF_ + WT_FLOATS];

// ---------------------------------------------------------------------------
// positional encoding add
// ---------------------------------------------------------------------------
__global__ void add_pos_kernel(const float4* __restrict__ q,
                               const float4* __restrict__ k,
                               const float4* __restrict__ pq,
                               const float4* __restrict__ pk,
                               float4* __restrict__ qin,
                               float4* __restrict__ kin) {
    int i  = blockIdx.x * 256 + threadIdx.x;
    int pi = i % (T_ * E_ / 4);
    const float s = 22.62741699796952f;
    float4 a = q[i], p = pq[pi];
    float4 r;
    r.x = a.x + p.x * s; r.y = a.y + p.y * s;
    r.z = a.z + p.z * s; r.w = a.w + p.w * s;
    qin[i] = r;
    a = k[i]; p = pk[pi];
    r.x = a.x + p.x * s; r.y = a.y + p.y * s;
    r.z = a.z + p.z * s; r.w = a.w + p.w * s;
    kin[i] = r;
}

// ---------------------------------------------------------------------------
// all 5 weight transposes in ONE launch.  WT[n,k] = W[k,n]
// ---------------------------------------------------------------------------
__global__ void transpose_all_kernel(
    const float* __restrict__ WQ, const float* __restrict__ WK,
    const float* __restrict__ WV, const float* __restrict__ F1,
    const float* __restrict__ F2,
    float* __restrict__ wqT, float* __restrict__ wkT, float* __restrict__ wvT,
    float* __restrict__ f1T, float* __restrict__ f2T) {
    __shared__ float t[32][33];
    int bid = blockIdx.x;
    const float* W; float* WT; int K, N, tile;
    if (bid < 256)       { W = WQ; WT = wqT; K = E_;  N = E_;  tile = bid; }
    else if (bid < 512)  { W = WK; WT = wkT; K = E_;  N = E_;  tile = bid - 256; }
    else if (bid < 768)  { W = WV; WT = wvT; K = E_;  N = E_;  tile = bid - 512; }
    else if (bid < 1792) { W = F1; WT = f1T; K = E_;  N = FF_; tile = bid - 768; }
    else                 { W = F2; WT = f2T; K = FF_; N = E_;  tile = bid - 1792; }
    int ntx = N / 32;
    int bn = (tile % ntx) * 32, bk = (tile / ntx) * 32;
    for (int j = threadIdx.y; j < 32; j += 8)
        t[j][threadIdx.x] = W[(size_t)(bk + j) * N + bn + threadIdx.x];
    __syncthreads();
    for (int j = threadIdx.y; j < 32; j += 8)
        WT[(size_t)(bn + j) * K + bk + threadIdx.x] = t[threadIdx.x][j];
}

// ---------------------------------------------------------------------------
// fused masked attention per (b,h)
// ---------------------------------------------------------------------------
#define ATS 68
__global__ void __launch_bounds__(256)
attn_kernel(const int* __restrict__ qlen, const int* __restrict__ klen,
            const float* __restrict__ Q, const float* __restrict__ KV,
            const float* __restrict__ qin, float* __restrict__ ctx) {
    extern __shared__ float sm[];
    float* Ks = sm;
    float* Vs = Ks + T_ * ATS;
    float* Sc = Vs + T_ * ATS;
    float* Qs = Sc + 32 * T_;

    const int h = blockIdx.x, b = blockIdx.y;
    const int tid = threadIdx.x, w = tid >> 5, lane = tid & 31;
    const int kl = klen[b], ql = qlen[b];
    const int kbmax = (kl + 31) >> 5;

    for (int i = tid; i < T_ * 16; i += 256) {
        int t = i >> 4, d4 = (i & 15) * 4;
        size_t gk = (size_t)(b * T_ + t) * 1024 + h * DH_ + d4;
        *(float4*)&Ks[t * ATS + d4] = *(const float4*)&KV[gk];
        *(float4*)&Vs[t * ATS + d4] = *(const float4*)&KV[gk + 512];
    }
    __syncthreads();

    for (int bi = w; bi * 4 < T_; bi += 8) {
        const int qq0 = bi * 4;
        const int w4 = w * 4;

#pragma unroll
        for (int j = 0; j < 2; j++) {
            int f4 = lane + j * 32;
            int r = f4 >> 4, d4 = (f4 & 15) * 4;
            *(float4*)&Qs[(w4 + r) * 64 + d4] =
                *(const float4*)&Q[(size_t)(b * T_ + qq0 + r) * E_ + h * DH_ + d4];
        }
        __syncwarp();

        float mx[4] = {-INFINITY, -INFINITY, -INFINITY, -INFINITY};
        for (int kb = 0; kb < kbmax; kb++) {
            int kk = kb * 32 + lane;
            if (kk < T_) {
                float a0 = 0.f, a1 = 0.f, a2 = 0.f, a3 = 0.f;
                const float* kr = &Ks[kk * ATS];
                const float* q0 = &Qs[(w4 + 0) * 64];
                const float* q1 = &Qs[(w4 + 1) * 64];
                const float* q2 = &Qs[(w4 + 2) * 64];
                const float* q3 = &Qs[(w4 + 3) * 64];
#pragma unroll
                for (int d = 0; d < DH_; d += 4) {
                    float4 kv = *(const float4*)&kr[d];
                    float4 qa = *(const float4*)&q0[d];
                    a0 += kv.x * qa.x + kv.y * qa.y + kv.z * qa.z + kv.w * qa.w;
                    qa = *(const float4*)&q1[d];
                    a1 += kv.x * qa.x + kv.y * qa.y + kv.z * qa.z + kv.w * qa.w;
                    qa = *(const float4*)&q2[d];
                    a2 += kv.x * qa.x + kv.y * qa.y + kv.z * qa.z + kv.w * qa.w;
                    qa = *(const float4*)&q3[d];
                    a3 += kv.x * qa.x + kv.y * qa.y + kv.z * qa.z + kv.w * qa.w;
                }
                float sv[4] = {a0, a1, a2, a3};
#pragma unroll
                for (int r = 0; r < 4; r++) {
                    float s = (kk < kl && kk != qq0 + r) ? sv[r] * 0.125f : NEGV;
                    Sc[(w4 + r) * T_ + kk] = s;
                    mx[r] = fmaxf(mx[r], s);
                }
            }
        }
#pragma unroll
        for (int r = 0; r < 4; r++)
#pragma unroll
            for (int off = 16; off; off >>= 1)
                mx[r] = fmaxf(mx[r], __shfl_xor_sync(0xffffffff, mx[r], off));

        float sum[4] = {0.f, 0.f, 0.f, 0.f};
        for (int kb = 0; kb < kbmax; kb++) {
            int kk = kb * 32 + lane;
            if (kk < T_) {
#pragma unroll
                for (int r = 0; r < 4; r++) {
                    float e = __expf(Sc[(w4 + r) * T_ + kk] - mx[r]);
                    Sc[(w4 + r) * T_ + kk] = e;
                    sum[r] += e;
                }
            }
        }
        bool am[4];
        bool any_am = false;
#pragma unroll
        for (int r = 0; r < 4; r++) { am[r] = (mx[r] == NEGV); any_am |= am[r]; }
        if (any_am) {
            for (int kb = kbmax; kb < 7; kb++) {
                int kk = kb * 32 + lane;
                if (kk < T_) {
#pragma unroll
                    for (int r = 0; r < 4; r++) {
                        float v = am[r] ? 1.f : 0.f;
                        Sc[(w4 + r) * T_ + kk] = v;
                        sum[r] += v;
                    }
                }
            }
        }
#pragma unroll
        for (int r = 0; r < 4; r++)
#pragma unroll
            for (int off = 16; off; off >>= 1)
                sum[r] += __shfl_xor_sync(0xffffffff, sum[r], off);

        float inv[4];
#pragma unroll
        for (int r = 0; r < 4; r++)
            inv[r] = (qq0 + r < ql) ? (1.0f / sum[r]) : 0.0f;
        __syncwarp();

        int kku = any_am ? T_ : min(kbmax * 32, T_);
        float o0[4] = {0.f, 0.f, 0.f, 0.f};
        float o1[4] = {0.f, 0.f, 0.f, 0.f};
        for (int kk = 0; kk < kku; kk++) {
            float v0 = Vs[kk * ATS + lane];
            float v1 = Vs[kk * ATS + lane + 32];
#pragma unroll
            for (int r = 0; r < 4; r++) {
                float p = Sc[(w4 + r) * T_ + kk];
                o0[r] += p * v0;
                o1[r] += p * v1;
            }
        }
#pragma unroll
        for (int r = 0; r < 4; r++) {
            size_t qb = (size_t)(b * T_ + qq0 + r) * E_ + h * DH_;
            ctx[qb + lane]      = o0[r] * inv[r] + qin[qb + lane];
            ctx[qb + lane + 32] = o1[r] * inv[r] + qin[qb + lane + 32];
        }
        __syncwarp();
    }
}

// ---------------------------------------------------------------------------
// mean over T -> (B,1,E)
// ---------------------------------------------------------------------------
__global__ void mean_kernel(const float* __restrict__ o2, float* __restrict__ out) {
    int b = blockIdx.x, e = threadIdx.x;
    float s = 0.f;
    for (int t = 0; t < T_; t++)
        s += o2[(size_t)(b * T_ + t) * E_ + e];
    out[b * E_ + e] = s * (1.0f / T_);
}

// ---------------------------------------------------------------------------
// Launch
// ---------------------------------------------------------------------------
extern "C" void kernel_launch(void* const* d_in, const int* in_sizes, int n_in,
                              void* d_out, int out_size) {
    const float* queries = (const float*)d_in[0];
    const float* keys    = (const float*)d_in[1];
    const int*   qlen    = (const int*)d_in[2];
    const int*   klen    = (const int*)d_in[3];
    const float* pos_q   = (const float*)d_in[4];
    const float* pos_k   = (const float*)d_in[5];
    const float* W_Q     = (const float*)d_in[6];
    const float* W_K     = (const float*)d_in[7];
    const float* W_V     = (const float*)d_in[8];
    const float* fw1     = (const float*)d_in[9];
    const float* fw2     = (const float*)d_in[10];
    float*       out     = (float*)d_out;

    float* base = nullptr;
    cudaGetSymbolAddress((void**)&base, g_scratch);
    const size_t BTE = (size_t)BT_ * E_;
    float* qin = base;
    float* kin = base + 1 * BTE;
    float* Qp  = base + 2 * BTE;
    float* KVb = base + 3 * BTE;
    float* ctx = base + 5 * BTE;
    float* o2  = base + 6 * BTE;
    float* hid = base + 7 * BTE;
    float* wqT = hid + (size_t)BT_ * FF_;
    float* wkT = wqT + E_ * E_;
    float* wvT = wkT + E_ * E_;
    float* f1T = wvT + E_ * E_;
    float* f2T = f1T + (size_t)E_ * FF_;

    cudaFuncSetAttribute(hgemm_kernel<false, false, 3>,
                         cudaFuncAttributeMaxDynamicSharedMemorySize, GEMM_DSMEM);
    cudaFuncSetAttribute(hgemm_kernel<true, false, 1>,
                         cudaFuncAttributeMaxDynamicSharedMemorySize, GEMM_DSMEM);
    cudaFuncSetAttribute(hgemm_kernel<false, true, 1>,
                         cudaFuncAttributeMaxDynamicSharedMemorySize, GEMM_DSMEM);
    const int SMEM_ATT = (2 * T_ * ATS + 32 * T_ + 32 * 64) * (int)sizeof(float);
    cudaFuncSetAttribute(attn_kernel,
                         cudaFuncAttributeMaxDynamicSharedMemorySize, SMEM_ATT);

    // 1. all weight transposes
    transpose_all_kernel<<<2816, dim3(32, 8)>>>(W_Q, W_K, W_V, fw1, fw2,
                                                wqT, wkT, wvT, f1T, f2T);
    // 2. positional encoding
    add_pos_kernel<<<(BT_ * E_ / 4) / 256, 256>>>(
        (const float4*)queries, (const float4*)keys,
        (const float4*)pos_q, (const float4*)pos_k,
        (float4*)qin, (float4*)kin);

    // 3. Q projection (3-term, accuracy-critical)
    hgemm_kernel<false, false, 3><<<dim3(E_ / GBN, BT_ / GBM), 256, GEMM_DSMEM>>>(
        qin, wqT, nullptr, Qp, BT_, E_, E_);
    // 4. merged K+V projection (3-term)
    hgemm_kernel<false, false, 3><<<dim3(2 * E_ / GBN, BT_ / GBM), 256, GEMM_DSMEM>>>(
        kin, wkT, nullptr, KVb, BT_, 2 * E_, E_);

    // 5. fused attention (+ residual)
    attn_kernel<<<dim3(H_, B_), 256, SMEM_ATT>>>(qlen, klen, Qp, KVb, qin, ctx);

    // 6. FFN up + ReLU (1-term fp16)
    hgemm_kernel<true, false, 1><<<dim3(FF_ / GBN, BT_ / GBM), 256, GEMM_DSMEM>>>(
        ctx, f1T, nullptr, hid, BT_, FF_, E_);

    // 7. FFN down + residual (1-term fp16)
    hgemm_kernel<false, true, 1><<<dim3(E_ / GBN, BT_ / GBM), 256, GEMM_DSMEM>>>(
        hid, f2T, ctx, o2, BT_, E_, FF_);

    // 8. mean over time
    mean_kernel<<<B_, E_>>>(o2, out);
}

// round 11
// speedup vs baseline: 1.6988x; 1.3384x over previous
#include <cuda_runtime.h>
#include <cuda_fp16.h>
#include <math.h>
#include <stdint.h>

// Problem dims
#define B_   256
#define T_   200
#define E_   512
#define H_   8
#define DH_  64
#define FF_  2048
#define BT_  (B_*T_)

#define NEGV (-4294967295.0f)

// ---------------------------------------------------------------------------
// GEMM config: 128x128 CTA tile, BK=32, 8 warps (2x4), warp tile 64x32.
// MODE=3: ah*bh + ah*bl + al*bh  (fp32-grade, Q/K)
// MODE=1: ah*bh                  (pure fp16, V & FFN)
// Fragment loads via ldmatrix.x4 (row pitch 80B: 16B-aligned, bank-perfect).
// ---------------------------------------------------------------------------
#define GBM 128
#define GBN 128
#define GBK 32
#define PADH 40
#define ROWB (PADH * 2)            // 80 bytes per smem row
#define PLANE_B (GBM * ROWB)
#define STAGE_B (4 * PLANE_B)
#define GEMM_DSMEM (2 * STAGE_B)

__device__ __forceinline__ void mma16816(float* c, const uint32_t* a, const uint32_t* b) {
    asm volatile(
        "mma.sync.aligned.m16n8k16.row.col.f32.f16.f16.f32 "
        "{%0,%1,%2,%3}, {%4,%5,%6,%7}, {%8,%9}, {%0,%1,%2,%3};"
        : "+f"(c[0]), "+f"(c[1]), "+f"(c[2]), "+f"(c[3])
        : "r"(a[0]), "r"(a[1]), "r"(a[2]), "r"(a[3]), "r"(b[0]), "r"(b[1]));
}

__device__ __forceinline__ void ldsm_x4(uint32_t* r, uint32_t addr) {
    asm volatile("ldmatrix.sync.aligned.m8n8.x4.shared.b16 {%0,%1,%2,%3}, [%4];"
                 : "=r"(r[0]), "=r"(r[1]), "=r"(r[2]), "=r"(r[3]) : "r"(addr));
}

__device__ __forceinline__ void split2(float x, float y, uint32_t& hi, uint32_t& lo) {
    __half hx = __float2half_rn(x);
    __half hy = __float2half_rn(y);
    __half lx = __float2half_rn(x - __half2float(hx));
    __half ly = __float2half_rn(y - __half2float(hy));
    hi = (uint32_t)__half_as_ushort(hx) | ((uint32_t)__half_as_ushort(hy) << 16);
    lo = (uint32_t)__half_as_ushort(lx) | ((uint32_t)__half_as_ushort(ly) << 16);
}
__device__ __forceinline__ uint32_t hi2(float x, float y) {
    __half hx = __float2half_rn(x);
    __half hy = __float2half_rn(y);
    return (uint32_t)__half_as_ushort(hx) | ((uint32_t)__half_as_ushort(hy) << 16);
}

// C[M,N] (row stride ldc) = A[M,K] @ Bt[N,K]^T  (+C0) (ReLU)
template <bool RELU, bool ADD, int MODE>
__global__ void __launch_bounds__(256)
hgemm_kernel(const float* __restrict__ A, const float* __restrict__ Bt,
             const float* __restrict__ C0, float* __restrict__ C,
             int M, int N, int K, int ldc) {
    extern __shared__ char smem[];
    const uint32_t smb = (uint32_t)__cvta_generic_to_shared(smem);

    const int tid = threadIdx.x;
    const int wid = tid >> 5, lane = tid & 31;
    const int m0 = blockIdx.y * GBM;
    const int n0 = blockIdx.x * GBN;
    const int wm = (wid >> 2) * 64;
    const int wn = (wid & 3) * 32;
    const int g = lane >> 2, t = lane & 3;

    // ldmatrix per-lane row geometry
    const int mat = lane >> 3, jr = lane & 7;
    const int a_r    = ((mat & 1) << 3) + jr;   // row within 16-row tile
    const int a_koff = (mat >> 1) << 3;         // k offset 0/8
    const int b_koff = (mat & 1) << 3;
    const int b_n    = ((mat >> 1) << 3) + jr;  // n within 16-col pair

    float acc[4][4][4];
#pragma unroll
    for (int i = 0; i < 4; i++)
#pragma unroll
        for (int j = 0; j < 4; j++)
#pragma unroll
            for (int k = 0; k < 4; k++) acc[i][j][k] = 0.f;

    const int nt = K / GBK;
    float4 la[4], lb[4];

    auto LDG = [&](int k0) {
#pragma unroll
        for (int j = 0; j < 4; j++) {
            int f4 = tid + j * 256;
            int r = f4 >> 3, c4 = f4 & 7;
            la[j] = *(const float4*)(A + (size_t)(m0 + r) * K + k0 + c4 * 4);
            lb[j] = *(const float4*)(Bt + (size_t)(n0 + r) * K + k0 + c4 * 4);
        }
    };
    auto STS = [&](int s) {
        char* ahi = smem + s * STAGE_B;
        char* alo = ahi + PLANE_B;
        char* bhi = alo + PLANE_B;
        char* blo = bhi + PLANE_B;
#pragma unroll
        for (int j = 0; j < 4; j++) {
            int f4 = tid + j * 256;
            int r = f4 >> 3, c4 = f4 & 7;
            uint32_t off = r * ROWB + c4 * 8;
            if (MODE >= 3) {
                uint32_t h01, l01, h23, l23;
                split2(la[j].x, la[j].y, h01, l01);
                split2(la[j].z, la[j].w, h23, l23);
                *(uint2*)(ahi + off) = make_uint2(h01, h23);
                *(uint2*)(alo + off) = make_uint2(l01, l23);
            } else {
                *(uint2*)(ahi + off) =
                    make_uint2(hi2(la[j].x, la[j].y), hi2(la[j].z, la[j].w));
            }
            if (MODE >= 2) {
                uint32_t h01, l01, h23, l23;
                split2(lb[j].x, lb[j].y, h01, l01);
                split2(lb[j].z, lb[j].w, h23, l23);
                *(uint2*)(bhi + off) = make_uint2(h01, h23);
                *(uint2*)(blo + off) = make_uint2(l01, l23);
            } else {
                *(uint2*)(bhi + off) =
                    make_uint2(hi2(lb[j].x, lb[j].y), hi2(lb[j].z, lb[j].w));
            }
        }
    };

    LDG(0);
    STS(0);

    for (int it = 0; it < nt; it++) {
        __syncthreads();
        if (it + 1 < nt) LDG((it + 1) * GBK);

        const uint32_t ahi = smb + (it & 1) * STAGE_B;
        const uint32_t alo = ahi + PLANE_B;
        const uint32_t bhi = alo + PLANE_B;
        const uint32_t blo = bhi + PLANE_B;

#pragma unroll
        for (int ks = 0; ks < GBK; ks += 16) {
            uint32_t ah[4][4], al[4][4], bh[4][2], bl[4][2];
            const uint32_t a_off = (wm + a_r) * ROWB + (ks + a_koff) * 2;
            const uint32_t b_off = (wn + b_n) * ROWB + (ks + b_koff) * 2;
#pragma unroll
            for (int mt = 0; mt < 4; mt++) {
                ldsm_x4(ah[mt], ahi + a_off + mt * (16 * ROWB));
                if (MODE >= 3) ldsm_x4(al[mt], alo + a_off + mt * (16 * ROWB));
            }
#pragma unroll
            for (int p = 0; p < 2; p++) {
                uint32_t tmp[4];
                ldsm_x4(tmp, bhi + b_off + p * (16 * ROWB));
                bh[2 * p][0] = tmp[0]; bh[2 * p][1] = tmp[1];
                bh[2 * p + 1][0] = tmp[2]; bh[2 * p + 1][1] = tmp[3];
                if (MODE >= 2) {
                    ldsm_x4(tmp, blo + b_off + p * (16 * ROWB));
                    bl[2 * p][0] = tmp[0]; bl[2 * p][1] = tmp[1];
                    bl[2 * p + 1][0] = tmp[2]; bl[2 * p + 1][1] = tmp[3];
                }
            }
#pragma unroll
            for (int mt = 0; mt < 4; mt++)
#pragma unroll
                for (int ntl = 0; ntl < 4; ntl++) {
                    mma16816(acc[mt][ntl], ah[mt], bh[ntl]);
                    if (MODE >= 2) mma16816(acc[mt][ntl], ah[mt], bl[ntl]);
                    if (MODE >= 3) mma16816(acc[mt][ntl], al[mt], bh[ntl]);
                }
        }
        if (it + 1 < nt) STS((it + 1) & 1);
    }

#pragma unroll
    for (int mt = 0; mt < 4; mt++)
#pragma unroll
        for (int ntl = 0; ntl < 4; ntl++) {
            int row = m0 + wm + mt * 16 + g;
            int col = n0 + wn + ntl * 8 + 2 * t;
            size_t i0 = (size_t)row * ldc + col;
            size_t i1 = (size_t)(row + 8) * ldc + col;
            float2 v0 = make_float2(acc[mt][ntl][0], acc[mt][ntl][1]);
            float2 v1 = make_float2(acc[mt][ntl][2], acc[mt][ntl][3]);
            if (ADD) {
                float2 c0 = *(const float2*)&C0[i0];
                float2 c1 = *(const float2*)&C0[i1];
                v0.x += c0.x; v0.y += c0.y; v1.x += c1.x; v1.y += c1.y;
            }
            if (RELU) {
                v0.x = fmaxf(v0.x, 0.f); v0.y = fmaxf(v0.y, 0.f);
                v1.x = fmaxf(v1.x, 0.f); v1.y = fmaxf(v1.y, 0.f);
            }
            *(float2*)&C[i0] = v0;
            *(float2*)&C[i1] = v1;
        }
}

// ---------------------------------------------------------------------------
// Scratch
// ---------------------------------------------------------------------------
#define WT_FLOATS (3 * E_ * E_ + 2 * E_ * FF_)
__device__ float g_scratch[(size_t)7 * BT_ * E_ + (size_t)BT_ * FF_ + WT_FLOATS];

// ---------------------------------------------------------------------------
// positional encoding add
// ---------------------------------------------------------------------------
__global__ void add_pos_kernel(const float4* __restrict__ q,
                               const float4* __restrict__ k,
                               const float4* __restrict__ pq,
                               const float4* __restrict__ pk,
                               float4* __restrict__ qin,
                               float4* __restrict__ kin) {
    int i  = blockIdx.x * 256 + threadIdx.x;
    int pi = i % (T_ * E_ / 4);
    const float s = 22.62741699796952f;
    float4 a = q[i], p = pq[pi];
    float4 r;
    r.x = a.x + p.x * s; r.y = a.y + p.y * s;
    r.z = a.z + p.z * s; r.w = a.w + p.w * s;
    qin[i] = r;
    a = k[i]; p = pk[pi];
    r.x = a.x + p.x * s; r.y = a.y + p.y * s;
    r.z = a.z + p.z * s; r.w = a.w + p.w * s;
    kin[i] = r;
}

// ---------------------------------------------------------------------------
// all 5 weight transposes in ONE launch.  WT[n,k] = W[k,n]
// ---------------------------------------------------------------------------
__global__ void transpose_all_kernel(
    const float* __restrict__ WQ, const float* __restrict__ WK,
    const float* __restrict__ WV, const float* __restrict__ F1,
    const float* __restrict__ F2,
    float* __restrict__ wqT, float* __restrict__ wkT, float* __restrict__ wvT,
    float* __restrict__ f1T, float* __restrict__ f2T) {
    __shared__ float t[32][33];
    int bid = blockIdx.x;
    const float* W; float* WT; int K, N, tile;
    if (bid < 256)       { W = WQ; WT = wqT; K = E_;  N = E_;  tile = bid; }
    else if (bid < 512)  { W = WK; WT = wkT; K = E_;  N = E_;  tile = bid - 256; }
    else if (bid < 768)  { W = WV; WT = wvT; K = E_;  N = E_;  tile = bid - 512; }
    else if (bid < 1792) { W = F1; WT = f1T; K = E_;  N = FF_; tile = bid - 768; }
    else                 { W = F2; WT = f2T; K = FF_; N = E_;  tile = bid - 1792; }
    int ntx = N / 32;
    int bn = (tile % ntx) * 32, bk = (tile / ntx) * 32;
    for (int j = threadIdx.y; j < 32; j += 8)
        t[j][threadIdx.x] = W[(size_t)(bk + j) * N + bn + threadIdx.x];
    __syncthreads();
    for (int j = threadIdx.y; j < 32; j += 8)
        WT[(size_t)(bn + j) * K + bk + threadIdx.x] = t[threadIdx.x][j];
}

// ---------------------------------------------------------------------------
// fused masked attention per (b,h)
// ---------------------------------------------------------------------------
#define ATS 68
__global__ void __launch_bounds__(256)
attn_kernel(const int* __restrict__ qlen, const int* __restrict__ klen,
            const float* __restrict__ Q, const float* __restrict__ KV,
            const float* __restrict__ qin, float* __restrict__ ctx) {
    extern __shared__ float sm[];
    float* Ks = sm;
    float* Vs = Ks + T_ * ATS;
    float* Sc = Vs + T_ * ATS;
    float* Qs = Sc + 32 * T_;

    const int h = blockIdx.x, b = blockIdx.y;
    const int tid = threadIdx.x, w = tid >> 5, lane = tid & 31;
    const int kl = klen[b], ql = qlen[b];
    const int kbmax = (kl + 31) >> 5;

    for (int i = tid; i < T_ * 16; i += 256) {
        int t = i >> 4, d4 = (i & 15) * 4;
        size_t gk = (size_t)(b * T_ + t) * 1024 + h * DH_ + d4;
        *(float4*)&Ks[t * ATS + d4] = *(const float4*)&KV[gk];
        *(float4*)&Vs[t * ATS + d4] = *(const float4*)&KV[gk + 512];
    }
    __syncthreads();

    for (int bi = w; bi * 4 < T_; bi += 8) {
        const int qq0 = bi * 4;
        const int w4 = w * 4;

#pragma unroll
        for (int j = 0; j < 2; j++) {
            int f4 = lane + j * 32;
            int r = f4 >> 4, d4 = (f4 & 15) * 4;
            *(float4*)&Qs[(w4 + r) * 64 + d4] =
                *(const float4*)&Q[(size_t)(b * T_ + qq0 + r) * E_ + h * DH_ + d4];
        }
        __syncwarp();

        float mx[4] = {-INFINITY, -INFINITY, -INFINITY, -INFINITY};
        for (int kb = 0; kb < kbmax; kb++) {
            int kk = kb * 32 + lane;
            if (kk < T_) {
                float a0 = 0.f, a1 = 0.f, a2 = 0.f, a3 = 0.f;
                const float* kr = &Ks[kk * ATS];
                const float* q0 = &Qs[(w4 + 0) * 64];
                const float* q1 = &Qs[(w4 + 1) * 64];
                const float* q2 = &Qs[(w4 + 2) * 64];
                const float* q3 = &Qs[(w4 + 3) * 64];
#pragma unroll
                for (int d = 0; d < DH_; d += 4) {
                    float4 kv = *(const float4*)&kr[d];
                    float4 qa = *(const float4*)&q0[d];
                    a0 += kv.x * qa.x + kv.y * qa.y + kv.z * qa.z + kv.w * qa.w;
                    qa = *(const float4*)&q1[d];
                    a1 += kv.x * qa.x + kv.y * qa.y + kv.z * qa.z + kv.w * qa.w;
                    qa = *(const float4*)&q2[d];
                    a2 += kv.x * qa.x + kv.y * qa.y + kv.z * qa.z + kv.w * qa.w;
                    qa = *(const float4*)&q3[d];
                    a3 += kv.x * qa.x + kv.y * qa.y + kv.z * qa.z + kv.w * qa.w;
                }
                float sv[4] = {a0, a1, a2, a3};
#pragma unroll
                for (int r = 0; r < 4; r++) {
                    float s = (kk < kl && kk != qq0 + r) ? sv[r] * 0.125f : NEGV;
                    Sc[(w4 + r) * T_ + kk] = s;
                    mx[r] = fmaxf(mx[r], s);
                }
            }
        }
#pragma unroll
        for (int r = 0; r < 4; r++)
#pragma unroll
            for (int off = 16; off; off >>= 1)
                mx[r] = fmaxf(mx[r], __shfl_xor_sync(0xffffffff, mx[r], off));

        float sum[4] = {0.f, 0.f, 0.f, 0.f};
        for (int kb = 0; kb < kbmax; kb++) {
            int kk = kb * 32 + lane;
            if (kk < T_) {
#pragma unroll
                for (int r = 0; r < 4; r++) {
                    float e = __expf(Sc[(w4 + r) * T_ + kk] - mx[r]);
                    Sc[(w4 + r) * T_ + kk] = e;
                    sum[r] += e;
                }
            }
        }
        bool am[4];
        bool any_am = false;
#pragma unroll
        for (int r = 0; r < 4; r++) { am[r] = (mx[r] == NEGV); any_am |= am[r]; }
        if (any_am) {
            for (int kb = kbmax; kb < 7; kb++) {
                int kk = kb * 32 + lane;
                if (kk < T_) {
#pragma unroll
                    for (int r = 0; r < 4; r++) {
                        float v = am[r] ? 1.f : 0.f;
                        Sc[(w4 + r) * T_ + kk] = v;
                        sum[r] += v;
                    }
                }
            }
        }
#pragma unroll
        for (int r = 0; r < 4; r++)
#pragma unroll
            for (int off = 16; off; off >>= 1)
                sum[r] += __shfl_xor_sync(0xffffffff, sum[r], off);

        float inv[4];
#pragma unroll
        for (int r = 0; r < 4; r++)
            inv[r] = (qq0 + r < ql) ? (1.0f / sum[r]) : 0.0f;
        __syncwarp();

        int kku = any_am ? T_ : min(kbmax * 32, T_);
        float o0[4] = {0.f, 0.f, 0.f, 0.f};
        float o1[4] = {0.f, 0.f, 0.f, 0.f};
        for (int kk = 0; kk < kku; kk++) {
            float v0 = Vs[kk * ATS + lane];
            float v1 = Vs[kk * ATS + lane + 32];
#pragma unroll
            for (int r = 0; r < 4; r++) {
                float p = Sc[(w4 + r) * T_ + kk];
                o0[r] += p * v0;
                o1[r] += p * v1;
            }
        }
#pragma unroll
        for (int r = 0; r < 4; r++) {
            size_t qb = (size_t)(b * T_ + qq0 + r) * E_ + h * DH_;
            ctx[qb + lane]      = o0[r] * inv[r] + qin[qb + lane];
            ctx[qb + lane + 32] = o1[r] * inv[r] + qin[qb + lane + 32];
        }
        __syncwarp();
    }
}

// ---------------------------------------------------------------------------
// mean over T -> (B,1,E)
// ---------------------------------------------------------------------------
__global__ void mean_kernel(const float* __restrict__ o2, float* __restrict__ out) {
    int b = blockIdx.x, e = threadIdx.x;
    float s = 0.f;
    for (int t = 0; t < T_; t++)
        s += o2[(size_t)(b * T_ + t) * E_ + e];
    out[b * E_ + e] = s * (1.0f / T_);
}

// ---------------------------------------------------------------------------
// Launch
// ---------------------------------------------------------------------------
extern "C" void kernel_launch(void* const* d_in, const int* in_sizes, int n_in,
                              void* d_out, int out_size) {
    const float* queries = (const float*)d_in[0];
    const float* keys    = (const float*)d_in[1];
    const int*   qlen    = (const int*)d_in[2];
    const int*   klen    = (const int*)d_in[3];
    const float* pos_q   = (const float*)d_in[4];
    const float* pos_k   = (const float*)d_in[5];
    const float* W_Q     = (const float*)d_in[6];
    const float* W_K     = (const float*)d_in[7];
    const float* W_V     = (const float*)d_in[8];
    const float* fw1     = (const float*)d_in[9];
    const float* fw2     = (const float*)d_in[10];
    float*       out     = (float*)d_out;

    float* base = nullptr;
    cudaGetSymbolAddress((void**)&base, g_scratch);
    const size_t BTE = (size_t)BT_ * E_;
    float* qin = base;
    float* kin = base + 1 * BTE;
    float* Qp  = base + 2 * BTE;
    float* KVb = base + 3 * BTE;            // merged [BT][1024]: K cols 0-511, V cols 512-1023
    float* ctx = base + 5 * BTE;
    float* o2  = base + 6 * BTE;
    float* hid = base + 7 * BTE;
    float* wqT = hid + (size_t)BT_ * FF_;
    float* wkT = wqT + E_ * E_;
    float* wvT = wkT + E_ * E_;
    float* f1T = wvT + E_ * E_;
    float* f2T = f1T + (size_t)E_ * FF_;

    cudaFuncSetAttribute(hgemm_kernel<false, false, 3>,
                         cudaFuncAttributeMaxDynamicSharedMemorySize, GEMM_DSMEM);
    cudaFuncSetAttribute(hgemm_kernel<false, false, 1>,
                         cudaFuncAttributeMaxDynamicSharedMemorySize, GEMM_DSMEM);
    cudaFuncSetAttribute(hgemm_kernel<true, false, 1>,
                         cudaFuncAttributeMaxDynamicSharedMemorySize, GEMM_DSMEM);
    cudaFuncSetAttribute(hgemm_kernel<false, true, 1>,
                         cudaFuncAttributeMaxDynamicSharedMemorySize, GEMM_DSMEM);
    const int SMEM_ATT = (2 * T_ * ATS + 32 * T_ + 32 * 64) * (int)sizeof(float);
    cudaFuncSetAttribute(attn_kernel,
                         cudaFuncAttributeMaxDynamicSharedMemorySize, SMEM_ATT);

    // 1. all weight transposes
    transpose_all_kernel<<<2816, dim3(32, 8)>>>(W_Q, W_K, W_V, fw1, fw2,
                                                wqT, wkT, wvT, f1T, f2T);
    // 2. positional encoding
    add_pos_kernel<<<(BT_ * E_ / 4) / 256, 256>>>(
        (const float4*)queries, (const float4*)keys,
        (const float4*)pos_q, (const float4*)pos_k,
        (float4*)qin, (float4*)kin);

    // 3. Q projection (3-term, score-critical)
    hgemm_kernel<false, false, 3><<<dim3(E_ / GBN, BT_ / GBM), 256, GEMM_DSMEM>>>(
        qin, wqT, nullptr, Qp, BT_, E_, E_, E_);
    // 4. K projection (3-term) -> KVb cols 0-511
    hgemm_kernel<false, false, 3><<<dim3(E_ / GBN, BT_ / GBM), 256, GEMM_DSMEM>>>(
        kin, wkT, nullptr, KVb, BT_, E_, E_, 2 * E_);
    // 5. V projection (1-term fp16; linear-path error, residual-damped) -> KVb cols 512-1023
    hgemm_kernel<false, false, 1><<<dim3(E_ / GBN, BT_ / GBM), 256, GEMM_DSMEM>>>(
        kin, wvT, nullptr, KVb + E_, BT_, E_, E_, 2 * E_);

    // 6. fused attention (+ residual)
    attn_kernel<<<dim3(H_, B_), 256, SMEM_ATT>>>(qlen, klen, Qp, KVb, qin, ctx);

    // 7. FFN up + ReLU (1-term fp16)
    hgemm_kernel<true, false, 1><<<dim3(FF_ / GBN, BT_ / GBM), 256, GEMM_DSMEM>>>(
        ctx, f1T, nullptr, hid, BT_, FF_, E_, FF_);

    // 8. FFN down + residual (1-term fp16)
    hgemm_kernel<false, true, 1><<<dim3(E_ / GBN, BT_ / GBM), 256, GEMM_DSMEM>>>(
        hid, f2T, ctx, o2, BT_, E_, FF_, E_);

    // 9. mean over time
    mean_kernel<<<B_, E_>>>(o2, out);
}

// round 12
// speedup vs baseline: 1.8889x; 1.1119x over previous
#include <cuda_runtime.h>
#include <cuda_fp16.h>
#include <math.h>
#include <stdint.h>

// Problem dims
#define B_   256
#define T_   200
#define E_   512
#define H_   8
#define DH_  64
#define FF_  2048
#define BT_  (B_*T_)

#define NEGV (-4294967295.0f)

// ---------------------------------------------------------------------------
// GEMM config: 128x128 CTA tile, BK=32, 8 warps (2x4), warp tile 64x32.
// MODE=3: ah*bh + ah*bl + al*bh  (fp32-grade, Q/K)
// MODE=1: ah*bh                  (pure fp16, V & FFN)
// ---------------------------------------------------------------------------
#define GBM 128
#define GBN 128
#define GBK 32
#define PADH 40
#define ROWB (PADH * 2)
#define PLANE_B (GBM * ROWB)
#define STAGE_B (4 * PLANE_B)
#define GEMM_DSMEM (2 * STAGE_B)

__device__ __forceinline__ void mma16816(float* c, const uint32_t* a, const uint32_t* b) {
    asm volatile(
        "mma.sync.aligned.m16n8k16.row.col.f32.f16.f16.f32 "
        "{%0,%1,%2,%3}, {%4,%5,%6,%7}, {%8,%9}, {%0,%1,%2,%3};"
        : "+f"(c[0]), "+f"(c[1]), "+f"(c[2]), "+f"(c[3])
        : "r"(a[0]), "r"(a[1]), "r"(a[2]), "r"(a[3]), "r"(b[0]), "r"(b[1]));
}

__device__ __forceinline__ void ldsm_x4(uint32_t* r, uint32_t addr) {
    asm volatile("ldmatrix.sync.aligned.m8n8.x4.shared.b16 {%0,%1,%2,%3}, [%4];"
                 : "=r"(r[0]), "=r"(r[1]), "=r"(r[2]), "=r"(r[3]) : "r"(addr));
}

__device__ __forceinline__ void split2(float x, float y, uint32_t& hi, uint32_t& lo) {
    __half hx = __float2half_rn(x);
    __half hy = __float2half_rn(y);
    __half lx = __float2half_rn(x - __half2float(hx));
    __half ly = __float2half_rn(y - __half2float(hy));
    hi = (uint32_t)__half_as_ushort(hx) | ((uint32_t)__half_as_ushort(hy) << 16);
    lo = (uint32_t)__half_as_ushort(lx) | ((uint32_t)__half_as_ushort(ly) << 16);
}
__device__ __forceinline__ uint32_t hi2(float x, float y) {
    __half hx = __float2half_rn(x);
    __half hy = __float2half_rn(y);
    return (uint32_t)__half_as_ushort(hx) | ((uint32_t)__half_as_ushort(hy) << 16);
}

// C[M,N] (row stride ldc) = A[M,K] @ Bt[N,K]^T  (+C0) (ReLU)
template <bool RELU, bool ADD, int MODE>
__global__ void __launch_bounds__(256)
hgemm_kernel(const float* __restrict__ A, const float* __restrict__ Bt,
             const float* __restrict__ C0, float* __restrict__ C,
             int M, int N, int K, int ldc) {
    extern __shared__ char smem[];
    const uint32_t smb = (uint32_t)__cvta_generic_to_shared(smem);

    const int tid = threadIdx.x;
    const int wid = tid >> 5, lane = tid & 31;
    const int m0 = blockIdx.y * GBM;
    const int n0 = blockIdx.x * GBN;
    const int wm = (wid >> 2) * 64;
    const int wn = (wid & 3) * 32;
    const int g = lane >> 2, t = lane & 3;

    const int mat = lane >> 3, jr = lane & 7;
    const int a_r    = ((mat & 1) << 3) + jr;
    const int a_koff = (mat >> 1) << 3;
    const int b_koff = (mat & 1) << 3;
    const int b_n    = ((mat >> 1) << 3) + jr;

    float acc[4][4][4];
#pragma unroll
    for (int i = 0; i < 4; i++)
#pragma unroll
        for (int j = 0; j < 4; j++)
#pragma unroll
            for (int k = 0; k < 4; k++) acc[i][j][k] = 0.f;

    const int nt = K / GBK;
    float4 la[4], lb[4];

    auto LDG = [&](int k0) {
#pragma unroll
        for (int j = 0; j < 4; j++) {
            int f4 = tid + j * 256;
            int r = f4 >> 3, c4 = f4 & 7;
            la[j] = *(const float4*)(A + (size_t)(m0 + r) * K + k0 + c4 * 4);
            lb[j] = *(const float4*)(Bt + (size_t)(n0 + r) * K + k0 + c4 * 4);
        }
    };
    auto STS = [&](int s) {
        char* ahi = smem + s * STAGE_B;
        char* alo = ahi + PLANE_B;
        char* bhi = alo + PLANE_B;
        char* blo = bhi + PLANE_B;
#pragma unroll
        for (int j = 0; j < 4; j++) {
            int f4 = tid + j * 256;
            int r = f4 >> 3, c4 = f4 & 7;
            uint32_t off = r * ROWB + c4 * 8;
            if (MODE >= 3) {
                uint32_t h01, l01, h23, l23;
                split2(la[j].x, la[j].y, h01, l01);
                split2(la[j].z, la[j].w, h23, l23);
                *(uint2*)(ahi + off) = make_uint2(h01, h23);
                *(uint2*)(alo + off) = make_uint2(l01, l23);
            } else {
                *(uint2*)(ahi + off) =
                    make_uint2(hi2(la[j].x, la[j].y), hi2(la[j].z, la[j].w));
            }
            if (MODE >= 2) {
                uint32_t h01, l01, h23, l23;
                split2(lb[j].x, lb[j].y, h01, l01);
                split2(lb[j].z, lb[j].w, h23, l23);
                *(uint2*)(bhi + off) = make_uint2(h01, h23);
                *(uint2*)(blo + off) = make_uint2(l01, l23);
            } else {
                *(uint2*)(bhi + off) =
                    make_uint2(hi2(lb[j].x, lb[j].y), hi2(lb[j].z, lb[j].w));
            }
        }
    };

    LDG(0);
    STS(0);

    for (int it = 0; it < nt; it++) {
        __syncthreads();
        if (it + 1 < nt) LDG((it + 1) * GBK);

        const uint32_t ahi = smb + (it & 1) * STAGE_B;
        const uint32_t alo = ahi + PLANE_B;
        const uint32_t bhi = alo + PLANE_B;
        const uint32_t blo = bhi + PLANE_B;

#pragma unroll
        for (int ks = 0; ks < GBK; ks += 16) {
            uint32_t ah[4][4], al[4][4], bh[4][2], bl[4][2];
            const uint32_t a_off = (wm + a_r) * ROWB + (ks + a_koff) * 2;
            const uint32_t b_off = (wn + b_n) * ROWB + (ks + b_koff) * 2;
#pragma unroll
            for (int mt = 0; mt < 4; mt++) {
                ldsm_x4(ah[mt], ahi + a_off + mt * (16 * ROWB));
                if (MODE >= 3) ldsm_x4(al[mt], alo + a_off + mt * (16 * ROWB));
            }
#pragma unroll
            for (int p = 0; p < 2; p++) {
                uint32_t tmp[4];
                ldsm_x4(tmp, bhi + b_off + p * (16 * ROWB));
                bh[2 * p][0] = tmp[0]; bh[2 * p][1] = tmp[1];
                bh[2 * p + 1][0] = tmp[2]; bh[2 * p + 1][1] = tmp[3];
                if (MODE >= 2) {
                    ldsm_x4(tmp, blo + b_off + p * (16 * ROWB));
                    bl[2 * p][0] = tmp[0]; bl[2 * p][1] = tmp[1];
                    bl[2 * p + 1][0] = tmp[2]; bl[2 * p + 1][1] = tmp[3];
                }
            }
#pragma unroll
            for (int mt = 0; mt < 4; mt++)
#pragma unroll
                for (int ntl = 0; ntl < 4; ntl++) {
                    mma16816(acc[mt][ntl], ah[mt], bh[ntl]);
                    if (MODE >= 2) mma16816(acc[mt][ntl], ah[mt], bl[ntl]);
                    if (MODE >= 3) mma16816(acc[mt][ntl], al[mt], bh[ntl]);
                }
        }
        if (it + 1 < nt) STS((it + 1) & 1);
    }

#pragma unroll
    for (int mt = 0; mt < 4; mt++)
#pragma unroll
        for (int ntl = 0; ntl < 4; ntl++) {
            int row = m0 + wm + mt * 16 + g;
            int col = n0 + wn + ntl * 8 + 2 * t;
            size_t i0 = (size_t)row * ldc + col;
            size_t i1 = (size_t)(row + 8) * ldc + col;
            float2 v0 = make_float2(acc[mt][ntl][0], acc[mt][ntl][1]);
            float2 v1 = make_float2(acc[mt][ntl][2], acc[mt][ntl][3]);
            if (ADD) {
                float2 c0 = *(const float2*)&C0[i0];
                float2 c1 = *(const float2*)&C0[i1];
                v0.x += c0.x; v0.y += c0.y; v1.x += c1.x; v1.y += c1.y;
            }
            if (RELU) {
                v0.x = fmaxf(v0.x, 0.f); v0.y = fmaxf(v0.y, 0.f);
                v1.x = fmaxf(v1.x, 0.f); v1.y = fmaxf(v1.y, 0.f);
            }
            *(float2*)&C[i0] = v0;
            *(float2*)&C[i1] = v1;
        }
}

// ---------------------------------------------------------------------------
// Scratch
// ---------------------------------------------------------------------------
#define WT_FLOATS (3 * E_ * E_ + 2 * E_ * FF_)
__device__ float g_scratch[(size_t)7 * BT_ * E_ + (size_t)BT_ * FF_ + WT_FLOATS];

// ---------------------------------------------------------------------------
// positional encoding add
// ---------------------------------------------------------------------------
__global__ void add_pos_kernel(const float4* __restrict__ q,
                               const float4* __restrict__ k,
                               const float4* __restrict__ pq,
                               const float4* __restrict__ pk,
                               float4* __restrict__ qin,
                               float4* __restrict__ kin) {
    int i  = blockIdx.x * 256 + threadIdx.x;
    int pi = i % (T_ * E_ / 4);
    const float s = 22.62741699796952f;
    float4 a = q[i], p = pq[pi];
    float4 r;
    r.x = a.x + p.x * s; r.y = a.y + p.y * s;
    r.z = a.z + p.z * s; r.w = a.w + p.w * s;
    qin[i] = r;
    a = k[i]; p = pk[pi];
    r.x = a.x + p.x * s; r.y = a.y + p.y * s;
    r.z = a.z + p.z * s; r.w = a.w + p.w * s;
    kin[i] = r;
}

// ---------------------------------------------------------------------------
// all 5 weight transposes in ONE launch.  WT[n,k] = W[k,n]
// ---------------------------------------------------------------------------
__global__ void transpose_all_kernel(
    const float* __restrict__ WQ, const float* __restrict__ WK,
    const float* __restrict__ WV, const float* __restrict__ F1,
    const float* __restrict__ F2,
    float* __restrict__ wqT, float* __restrict__ wkT, float* __restrict__ wvT,
    float* __restrict__ f1T, float* __restrict__ f2T) {
    __shared__ float t[32][33];
    int bid = blockIdx.x;
    const float* W; float* WT; int K, N, tile;
    if (bid < 256)       { W = WQ; WT = wqT; K = E_;  N = E_;  tile = bid; }
    else if (bid < 512)  { W = WK; WT = wkT; K = E_;  N = E_;  tile = bid - 256; }
    else if (bid < 768)  { W = WV; WT = wvT; K = E_;  N = E_;  tile = bid - 512; }
    else if (bid < 1792) { W = F1; WT = f1T; K = E_;  N = FF_; tile = bid - 768; }
    else                 { W = F2; WT = f2T; K = FF_; N = E_;  tile = bid - 1792; }
    int ntx = N / 32;
    int bn = (tile % ntx) * 32, bk = (tile / ntx) * 32;
    for (int j = threadIdx.y; j < 32; j += 8)
        t[j][threadIdx.x] = W[(size_t)(bk + j) * N + bn + threadIdx.x];
    __syncthreads();
    for (int j = threadIdx.y; j < 32; j += 8)
        WT[(size_t)(bn + j) * K + bk + threadIdx.x] = t[threadIdx.x][j];
}

// ---------------------------------------------------------------------------
// Tensor-core fused attention per (b,h).
// S = Q K^T via 3-term fp16-split mma (error ~|S|*2^-22, safe through exp);
// fp32 softmax with exact reference masking semantics;
// O = P V via 1-term fp16 mma (linear-path error, residual-damped).
// Query rows processed in 4 blocks of 64 (block 3: 16 valid m-rows).
// ---------------------------------------------------------------------------
#define KP 72                 // K/Q smem pitch (halves); 144B rows: conflict-free ldmatrix
#define KPB (KP * 2)
#define VP 232                // V^T / P pitch (halves); 464B rows: conflict-free
#define VPB (VP * 2)
#define SCP 224               // Sc pitch (floats)
#define TPAD 224
#define OFF_KHI 0
#define OFF_KLO (TPAD * KPB)                 // 32256
#define OFF_VT  (2 * TPAD * KPB)             // 64512
#define OFF_QHI (OFF_VT + 64 * VPB)          // 94208
#define OFF_QLO (OFF_QHI + 64 * KPB)         // 103424
#define OFF_SC  (OFF_QLO + 64 * KPB)         // 112640
#define OFF_P   (OFF_SC + 64 * SCP * 4)      // 169984
#define OFF_INV (OFF_P + 64 * VPB)           // 199680
#define OFF_AM  (OFF_INV + 64 * 4)           // 199936
#define ATT_SMEM (OFF_AM + 16)               // 199952

__global__ void __launch_bounds__(256)
attn_mma_kernel(const int* __restrict__ qlen, const int* __restrict__ klen,
                const float* __restrict__ Q, const float* __restrict__ KV,
                const float* __restrict__ qin, float* __restrict__ ctx) {
    extern __shared__ char sm[];
    const uint32_t smb = (uint32_t)__cvta_generic_to_shared(sm);
    float* Sc = (float*)(sm + OFF_SC);
    __half* Ph = (__half*)(sm + OFF_P);
    float* s_inv = (float*)(sm + OFF_INV);
    int* s_am = (int*)(sm + OFF_AM);

    const int h = blockIdx.x, b = blockIdx.y;
    const int tid = threadIdx.x, w = tid >> 5, lane = tid & 31;
    const int kl = klen[b], ql = qlen[b];
    const int kbmax = (kl + 31) >> 5;
    const int g = lane >> 2, t = lane & 3;
    const int mat = lane >> 3, jr = lane & 7;
    const int a_r    = ((mat & 1) << 3) + jr;
    const int a_koff = (mat >> 1) << 3;
    const int b_koff = (mat & 1) << 3;
    const int b_n    = ((mat >> 1) << 3) + jr;

    // ---- load K (hi/lo split) and V^T (fp16) into smem; zero-pad rows/cols
    {
        __half* vt = (__half*)(sm + OFF_VT);
        for (int i = tid; i < TPAD * 16; i += 256) {
            int tt = i >> 4, d4 = (i & 15) * 4;
            float4 kv = make_float4(0.f, 0.f, 0.f, 0.f);
            float4 vv = make_float4(0.f, 0.f, 0.f, 0.f);
            if (tt < T_) {
                size_t gk = (size_t)(b * T_ + tt) * 1024 + h * DH_ + d4;
                kv = *(const float4*)&KV[gk];
                vv = *(const float4*)&KV[gk + 512];
            }
            uint32_t h01, l01, h23, l23;
            split2(kv.x, kv.y, h01, l01);
            split2(kv.z, kv.w, h23, l23);
            *(uint2*)(sm + OFF_KHI + tt * KPB + d4 * 2) = make_uint2(h01, h23);
            *(uint2*)(sm + OFF_KLO + tt * KPB + d4 * 2) = make_uint2(l01, l23);
            vt[(d4 + 0) * VP + tt] = __float2half_rn(vv.x);
            vt[(d4 + 1) * VP + tt] = __float2half_rn(vv.y);
            vt[(d4 + 2) * VP + tt] = __float2half_rn(vv.z);
            vt[(d4 + 3) * VP + tt] = __float2half_rn(vv.w);
        }
    }

    for (int blk = 0; blk < 4; blk++) {
        const int qb0 = blk * 64;
        const int mtiles = (blk == 3) ? 1 : 4;
        const int rows = mtiles * 16;
        __syncthreads();   // K/V load (blk 0) or previous block's AV done

        // zero P region, load Q chunk (hi/lo), reset am flag
        if (tid == 0) *s_am = 0;
        for (int i = tid; i < rows * (VP / 2); i += 256)
            ((uint32_t*)(sm + OFF_P))[i] = 0u;
        for (int i = tid; i < rows * 16; i += 256) {
            int r = i >> 4, d4 = (i & 15) * 4;
            int qq = qb0 + r;
            float4 qv = make_float4(0.f, 0.f, 0.f, 0.f);
            if (qq < T_)
                qv = *(const float4*)&Q[(size_t)(b * T_ + qq) * E_ + h * DH_ + d4];
            uint32_t h01, l01, h23, l23;
            split2(qv.x, qv.y, h01, l01);
            split2(qv.z, qv.w, h23, l23);
            *(uint2*)(sm + OFF_QHI + r * KPB + d4 * 2) = make_uint2(h01, h23);
            *(uint2*)(sm + OFF_QLO + r * KPB + d4 * 2) = make_uint2(l01, l23);
        }
        __syncthreads();

        // ---- S = Q K^T (3-term), masked write to Sc
        if ((w >> 1) < mtiles) {
            const int mt = w >> 1, ns = w & 1;
            uint32_t ah[4][4], al[4][4];
            const uint32_t abase  = smb + OFF_QHI + (mt * 16 + a_r) * KPB + a_koff * 2;
            const uint32_t abasel = abase + (OFF_QLO - OFF_QHI);
#pragma unroll
            for (int ks = 0; ks < 4; ks++) {
                ldsm_x4(ah[ks], abase + ks * 32);
                ldsm_x4(al[ks], abasel + ks * 32);
            }
            const int lim = kbmax * 32;
            for (int p = 0; p < 7; p++) {
                const int np = ns * 112 + p * 16;
                if (np >= lim) break;
                float acc0[4] = {0.f, 0.f, 0.f, 0.f};
                float acc1[4] = {0.f, 0.f, 0.f, 0.f};
#pragma unroll
                for (int ks = 0; ks < 4; ks++) {
                    uint32_t bh[4], bl[4];
                    const uint32_t boff = (np + b_n) * KPB + (ks * 16 + b_koff) * 2;
                    ldsm_x4(bh, smb + OFF_KHI + boff);
                    ldsm_x4(bl, smb + OFF_KLO + boff);
                    mma16816(acc0, ah[ks], bh);
                    mma16816(acc0, ah[ks], bl);
                    mma16816(acc0, al[ks], bh);
                    mma16816(acc1, ah[ks], bh + 2);
                    mma16816(acc1, ah[ks], bl + 2);
                    mma16816(acc1, al[ks], bh + 2);
                }
                const int lr = mt * 16 + g;
                const int q0 = qb0 + lr, q1 = q0 + 8;
#pragma unroll
                for (int hf = 0; hf < 2; hf++) {
                    const float* ac = hf ? acc1 : acc0;
                    const int c = np + hf * 8 + 2 * t;
                    float2 v;
                    v.x = (c     < kl && c     != q0) ? ac[0] * 0.125f : NEGV;
                    v.y = (c + 1 < kl && c + 1 != q0) ? ac[1] * 0.125f : NEGV;
                    *(float2*)&Sc[lr * SCP + c] = v;
                    v.x = (c     < kl && c     != q1) ? ac[2] * 0.125f : NEGV;
                    v.y = (c + 1 < kl && c + 1 != q1) ? ac[3] * 0.125f : NEGV;
                    *(float2*)&Sc[(lr + 8) * SCP + c] = v;
                }
            }
        }
        __syncthreads();

        // ---- softmax rows -> P (fp16, unnormalized), inv scale
        for (int r0 = w * 4; r0 < rows; r0 += 32) {
            float mx[4] = {-INFINITY, -INFINITY, -INFINITY, -INFINITY};
            for (int kb = 0; kb < kbmax; kb++) {
                int kk = kb * 32 + lane;
#pragma unroll
                for (int r = 0; r < 4; r++)
                    mx[r] = fmaxf(mx[r], Sc[(r0 + r) * SCP + kk]);
            }
#pragma unroll
            for (int r = 0; r < 4; r++)
#pragma unroll
                for (int off = 16; off; off >>= 1)
                    mx[r] = fmaxf(mx[r], __shfl_xor_sync(0xffffffff, mx[r], off));

            float sum[4] = {0.f, 0.f, 0.f, 0.f};
            for (int kb = 0; kb < kbmax; kb++) {
                int kk = kb * 32 + lane;
#pragma unroll
                for (int r = 0; r < 4; r++) {
                    float e = __expf(Sc[(r0 + r) * SCP + kk] - mx[r]);
                    Ph[(r0 + r) * VP + kk] = __float2half_rn(e);
                    sum[r] += e;
                }
            }
            bool am[4]; bool any_am = false;
#pragma unroll
            for (int r = 0; r < 4; r++) { am[r] = (mx[r] == NEGV); any_am |= am[r]; }
            if (any_am) {
                for (int kb = kbmax; kb < 7; kb++) {
                    int kk = kb * 32 + lane;
                    if (kk < T_) {
#pragma unroll
                        for (int r = 0; r < 4; r++)
                            if (am[r]) {
                                Ph[(r0 + r) * VP + kk] = __float2half_rn(1.f);
                                sum[r] += 1.f;
                            }
                    }
                }
                if (lane == 0) atomicOr(s_am, 1);
            }
#pragma unroll
            for (int r = 0; r < 4; r++)
#pragma unroll
                for (int off = 16; off; off >>= 1)
                    sum[r] += __shfl_xor_sync(0xffffffff, sum[r], off);
            if (lane == 0) {
#pragma unroll
                for (int r = 0; r < 4; r++)
                    s_inv[r0 + r] = (qb0 + r0 + r < ql) ? (1.f / sum[r]) : 0.f;
            }
        }
        __syncthreads();

        // ---- O = P V (1-term), scale + residual + store
        if ((w >> 1) < mtiles) {
            const int mt = w >> 1, nh = w & 1;
            const int kks = (*s_am) ? 14 : kbmax * 2;
            float acc[4][4];
#pragma unroll
            for (int j = 0; j < 4; j++)
#pragma unroll
                for (int k = 0; k < 4; k++) acc[j][k] = 0.f;
            for (int ks = 0; ks < kks; ks++) {
                uint32_t ap[4];
                ldsm_x4(ap, smb + OFF_P + (mt * 16 + a_r) * VPB + (ks * 16 + a_koff) * 2);
                uint32_t bv0[4], bv1[4];
                const uint32_t vb = smb + OFF_VT + (nh * 32 + b_n) * VPB + (ks * 16 + b_koff) * 2;
                ldsm_x4(bv0, vb);
                ldsm_x4(bv1, vb + 16 * VPB);
                mma16816(acc[0], ap, bv0);
                mma16816(acc[1], ap, bv0 + 2);
                mma16816(acc[2], ap, bv1);
                mma16816(acc[3], ap, bv1 + 2);
            }
            const int lr = mt * 16 + g;
            const int q0 = qb0 + lr, q1 = q0 + 8;
            const float iv0 = s_inv[lr], iv1 = s_inv[lr + 8];
#pragma unroll
            for (int j = 0; j < 4; j++) {
                const int dh = nh * 32 + j * 8 + 2 * t;
                if (q0 < T_) {
                    size_t base = (size_t)(b * T_ + q0) * E_ + h * DH_ + dh;
                    float2 qi = *(const float2*)&qin[base];
                    float2 o = make_float2(acc[j][0] * iv0 + qi.x,
                                           acc[j][1] * iv0 + qi.y);
                    *(float2*)&ctx[base] = o;
                }
                if (q1 < T_) {
                    size_t base = (size_t)(b * T_ + q1) * E_ + h * DH_ + dh;
                    float2 qi = *(const float2*)&qin[base];
                    float2 o = make_float2(acc[j][2] * iv1 + qi.x,
                                           acc[j][3] * iv1 + qi.y);
                    *(float2*)&ctx[base] = o;
                }
            }
        }
    }
}

// ---------------------------------------------------------------------------
// mean over T -> (B,1,E)
// ---------------------------------------------------------------------------
__global__ void mean_kernel(const float* __restrict__ o2, float* __restrict__ out) {
    int b = blockIdx.x, e = threadIdx.x;
    float s = 0.f;
    for (int t = 0; t < T_; t++)
        s += o2[(size_t)(b * T_ + t) * E_ + e];
    out[b * E_ + e] = s * (1.0f / T_);
}

// ---------------------------------------------------------------------------
// Launch
// ---------------------------------------------------------------------------
extern "C" void kernel_launch(void* const* d_in, const int* in_sizes, int n_in,
                              void* d_out, int out_size) {
    const float* queries = (const float*)d_in[0];
    const float* keys    = (const float*)d_in[1];
    const int*   qlen    = (const int*)d_in[2];
    const int*   klen    = (const int*)d_in[3];
    const float* pos_q   = (const float*)d_in[4];
    const float* pos_k   = (const float*)d_in[5];
    const float* W_Q     = (const float*)d_in[6];
    const float* W_K     = (const float*)d_in[7];
    const float* W_V     = (const float*)d_in[8];
    const float* fw1     = (const float*)d_in[9];
    const float* fw2     = (const float*)d_in[10];
    float*       out     = (float*)d_out;

    float* base = nullptr;
    cudaGetSymbolAddress((void**)&base, g_scratch);
    const size_t BTE = (size_t)BT_ * E_;
    float* qin = base;
    float* kin = base + 1 * BTE;
    float* Qp  = base + 2 * BTE;
    float* KVb = base + 3 * BTE;            // merged [BT][1024]: K cols 0-511, V cols 512-1023
    float* ctx = base + 5 * BTE;
    float* o2  = base + 6 * BTE;
    float* hid = base + 7 * BTE;
    float* wqT = hid + (size_t)BT_ * FF_;
    float* wkT = wqT + E_ * E_;
    float* wvT = wkT + E_ * E_;
    float* f1T = wvT + E_ * E_;
    float* f2T = f1T + (size_t)E_ * FF_;

    cudaFuncSetAttribute(hgemm_kernel<false, false, 3>,
                         cudaFuncAttributeMaxDynamicSharedMemorySize, GEMM_DSMEM);
    cudaFuncSetAttribute(hgemm_kernel<false, false, 1>,
                         cudaFuncAttributeMaxDynamicSharedMemorySize, GEMM_DSMEM);
    cudaFuncSetAttribute(hgemm_kernel<true, false, 1>,
                         cudaFuncAttributeMaxDynamicSharedMemorySize, GEMM_DSMEM);
    cudaFuncSetAttribute(hgemm_kernel<false, true, 1>,
                         cudaFuncAttributeMaxDynamicSharedMemorySize, GEMM_DSMEM);
    cudaFuncSetAttribute(attn_mma_kernel,
                         cudaFuncAttributeMaxDynamicSharedMemorySize, ATT_SMEM);

    // 1. all weight transposes
    transpose_all_kernel<<<2816, dim3(32, 8)>>>(W_Q, W_K, W_V, fw1, fw2,
                                                wqT, wkT, wvT, f1T, f2T);
    // 2. positional encoding
    add_pos_kernel<<<(BT_ * E_ / 4) / 256, 256>>>(
        (const float4*)queries, (const float4*)keys,
        (const float4*)pos_q, (const float4*)pos_k,
        (float4*)qin, (float4*)kin);

    // 3. Q projection (3-term, score-critical)
    hgemm_kernel<false, false, 3><<<dim3(E_ / GBN, BT_ / GBM), 256, GEMM_DSMEM>>>(
        qin, wqT, nullptr, Qp, BT_, E_, E_, E_);
    // 4. K projection (3-term) -> KVb cols 0-511
    hgemm_kernel<false, false, 3><<<dim3(E_ / GBN, BT_ / GBM), 256, GEMM_DSMEM>>>(
        kin, wkT, nullptr, KVb, BT_, E_, E_, 2 * E_);
    // 5. V projection (1-term) -> KVb cols 512-1023
    hgemm_kernel<false, false, 1><<<dim3(E_ / GBN, BT_ / GBM), 256, GEMM_DSMEM>>>(
        kin, wvT, nullptr, KVb + E_, BT_, E_, E_, 2 * E_);

    // 6. tensor-core fused attention (+ residual)
    attn_mma_kernel<<<dim3(H_, B_), 256, ATT_SMEM>>>(qlen, klen, Qp, KVb, qin, ctx);

    // 7. FFN up + ReLU (1-term fp16)
    hgemm_kernel<true, false, 1><<<dim3(FF_ / GBN, BT_ / GBM), 256, GEMM_DSMEM>>>(
        ctx, f1T, nullptr, hid, BT_, FF_, E_, FF_);

    // 8. FFN down + residual (1-term fp16)
    hgemm_kernel<false, true, 1><<<dim3(E_ / GBN, BT_ / GBM), 256, GEMM_DSMEM>>>(
        hid, f2T, ctx, o2, BT_, E_, FF_, E_);

    // 9. mean over time
    mean_kernel<<<B_, E_>>>(o2, out);
}

// round 13
// speedup vs baseline: 2.0341x; 1.0768x over previous
#include <cuda_runtime.h>
#include <cuda_fp16.h>
#include <math.h>
#include <stdint.h>

// Problem dims
#define B_   256
#define T_   200
#define E_   512
#define H_   8
#define DH_  64
#define FF_  2048
#define BT_  (B_*T_)

#define NEGV (-4294967295.0f)

// ---------------------------------------------------------------------------
// GEMM config: 128x128 CTA tile, BK=32, 8 warps (2x4), warp tile 64x32.
// MODE=3: ah*bh + ah*bl + al*bh  (fp32-grade, Q/K)
// MODE=1: ah*bh                  (pure fp16, V & FFN)  + MINB=2 occupancy
// ---------------------------------------------------------------------------
#define GBM 128
#define GBN 128
#define GBK 32
#define PADH 40
#define ROWB (PADH * 2)
#define PLANE_B (GBM * ROWB)
#define STAGE_B (4 * PLANE_B)
#define GEMM_DSMEM (2 * STAGE_B)

__device__ __forceinline__ void mma16816(float* c, const uint32_t* a, const uint32_t* b) {
    asm volatile(
        "mma.sync.aligned.m16n8k16.row.col.f32.f16.f16.f32 "
        "{%0,%1,%2,%3}, {%4,%5,%6,%7}, {%8,%9}, {%0,%1,%2,%3};"
        : "+f"(c[0]), "+f"(c[1]), "+f"(c[2]), "+f"(c[3])
        : "r"(a[0]), "r"(a[1]), "r"(a[2]), "r"(a[3]), "r"(b[0]), "r"(b[1]));
}

__device__ __forceinline__ void ldsm_x4(uint32_t* r, uint32_t addr) {
    asm volatile("ldmatrix.sync.aligned.m8n8.x4.shared.b16 {%0,%1,%2,%3}, [%4];"
                 : "=r"(r[0]), "=r"(r[1]), "=r"(r[2]), "=r"(r[3]) : "r"(addr));
}

__device__ __forceinline__ void split2(float x, float y, uint32_t& hi, uint32_t& lo) {
    __half hx = __float2half_rn(x);
    __half hy = __float2half_rn(y);
    __half lx = __float2half_rn(x - __half2float(hx));
    __half ly = __float2half_rn(y - __half2float(hy));
    hi = (uint32_t)__half_as_ushort(hx) | ((uint32_t)__half_as_ushort(hy) << 16);
    lo = (uint32_t)__half_as_ushort(lx) | ((uint32_t)__half_as_ushort(ly) << 16);
}
__device__ __forceinline__ uint32_t hi2(float x, float y) {
    __half hx = __float2half_rn(x);
    __half hy = __float2half_rn(y);
    return (uint32_t)__half_as_ushort(hx) | ((uint32_t)__half_as_ushort(hy) << 16);
}

// C[M,N] (row stride ldc) = A[M,K] @ Bt[N,K]^T  (+C0) (ReLU)
template <bool RELU, bool ADD, int MODE, int MINB>
__global__ void __launch_bounds__(256, MINB)
hgemm_kernel(const float* __restrict__ A, const float* __restrict__ Bt,
             const float* __restrict__ C0, float* __restrict__ C,
             int M, int N, int K, int ldc) {
    extern __shared__ char smem[];
    const uint32_t smb = (uint32_t)__cvta_generic_to_shared(smem);

    const int tid = threadIdx.x;
    const int wid = tid >> 5, lane = tid & 31;
    const int m0 = blockIdx.y * GBM;
    const int n0 = blockIdx.x * GBN;
    const int wm = (wid >> 2) * 64;
    const int wn = (wid & 3) * 32;
    const int g = lane >> 2, t = lane & 3;

    const int mat = lane >> 3, jr = lane & 7;
    const int a_r    = ((mat & 1) << 3) + jr;
    const int a_koff = (mat >> 1) << 3;
    const int b_koff = (mat & 1) << 3;
    const int b_n    = ((mat >> 1) << 3) + jr;

    float acc[4][4][4];
#pragma unroll
    for (int i = 0; i < 4; i++)
#pragma unroll
        for (int j = 0; j < 4; j++)
#pragma unroll
            for (int k = 0; k < 4; k++) acc[i][j][k] = 0.f;

    const int nt = K / GBK;
    float4 la[4], lb[4];

    auto LDG = [&](int k0) {
#pragma unroll
        for (int j = 0; j < 4; j++) {
            int f4 = tid + j * 256;
            int r = f4 >> 3, c4 = f4 & 7;
            la[j] = *(const float4*)(A + (size_t)(m0 + r) * K + k0 + c4 * 4);
            lb[j] = *(const float4*)(Bt + (size_t)(n0 + r) * K + k0 + c4 * 4);
        }
    };
    auto STS = [&](int s) {
        char* ahi = smem + s * STAGE_B;
        char* alo = ahi + PLANE_B;
        char* bhi = alo + PLANE_B;
        char* blo = bhi + PLANE_B;
#pragma unroll
        for (int j = 0; j < 4; j++) {
            int f4 = tid + j * 256;
            int r = f4 >> 3, c4 = f4 & 7;
            uint32_t off = r * ROWB + c4 * 8;
            if (MODE >= 3) {
                uint32_t h01, l01, h23, l23;
                split2(la[j].x, la[j].y, h01, l01);
                split2(la[j].z, la[j].w, h23, l23);
                *(uint2*)(ahi + off) = make_uint2(h01, h23);
                *(uint2*)(alo + off) = make_uint2(l01, l23);
            } else {
                *(uint2*)(ahi + off) =
                    make_uint2(hi2(la[j].x, la[j].y), hi2(la[j].z, la[j].w));
            }
            if (MODE >= 2) {
                uint32_t h01, l01, h23, l23;
                split2(lb[j].x, lb[j].y, h01, l01);
                split2(lb[j].z, lb[j].w, h23, l23);
                *(uint2*)(bhi + off) = make_uint2(h01, h23);
                *(uint2*)(blo + off) = make_uint2(l01, l23);
            } else {
                *(uint2*)(bhi + off) =
                    make_uint2(hi2(lb[j].x, lb[j].y), hi2(lb[j].z, lb[j].w));
            }
        }
    };

    LDG(0);
    STS(0);

    for (int it = 0; it < nt; it++) {
        __syncthreads();
        if (it + 1 < nt) LDG((it + 1) * GBK);

        const uint32_t ahi = smb + (it & 1) * STAGE_B;
        const uint32_t alo = ahi + PLANE_B;
        const uint32_t bhi = alo + PLANE_B;
        const uint32_t blo = bhi + PLANE_B;

#pragma unroll
        for (int ks = 0; ks < GBK; ks += 16) {
            uint32_t ah[4][4], al[4][4], bh[4][2], bl[4][2];
            const uint32_t a_off = (wm + a_r) * ROWB + (ks + a_koff) * 2;
            const uint32_t b_off = (wn + b_n) * ROWB + (ks + b_koff) * 2;
#pragma unroll
            for (int mt = 0; mt < 4; mt++) {
                ldsm_x4(ah[mt], ahi + a_off + mt * (16 * ROWB));
                if (MODE >= 3) ldsm_x4(al[mt], alo + a_off + mt * (16 * ROWB));
            }
#pragma unroll
            for (int p = 0; p < 2; p++) {
                uint32_t tmp[4];
                ldsm_x4(tmp, bhi + b_off + p * (16 * ROWB));
                bh[2 * p][0] = tmp[0]; bh[2 * p][1] = tmp[1];
                bh[2 * p + 1][0] = tmp[2]; bh[2 * p + 1][1] = tmp[3];
                if (MODE >= 2) {
                    ldsm_x4(tmp, blo + b_off + p * (16 * ROWB));
                    bl[2 * p][0] = tmp[0]; bl[2 * p][1] = tmp[1];
                    bl[2 * p + 1][0] = tmp[2]; bl[2 * p + 1][1] = tmp[3];
                }
            }
#pragma unroll
            for (int mt = 0; mt < 4; mt++)
#pragma unroll
                for (int ntl = 0; ntl < 4; ntl++) {
                    mma16816(acc[mt][ntl], ah[mt], bh[ntl]);
                    if (MODE >= 2) mma16816(acc[mt][ntl], ah[mt], bl[ntl]);
                    if (MODE >= 3) mma16816(acc[mt][ntl], al[mt], bh[ntl]);
                }
        }
        if (it + 1 < nt) STS((it + 1) & 1);
    }

#pragma unroll
    for (int mt = 0; mt < 4; mt++)
#pragma unroll
        for (int ntl = 0; ntl < 4; ntl++) {
            int row = m0 + wm + mt * 16 + g;
            int col = n0 + wn + ntl * 8 + 2 * t;
            size_t i0 = (size_t)row * ldc + col;
            size_t i1 = (size_t)(row + 8) * ldc + col;
            float2 v0 = make_float2(acc[mt][ntl][0], acc[mt][ntl][1]);
            float2 v1 = make_float2(acc[mt][ntl][2], acc[mt][ntl][3]);
            if (ADD) {
                float2 c0 = *(const float2*)&C0[i0];
                float2 c1 = *(const float2*)&C0[i1];
                v0.x += c0.x; v0.y += c0.y; v1.x += c1.x; v1.y += c1.y;
            }
            if (RELU) {
                v0.x = fmaxf(v0.x, 0.f); v0.y = fmaxf(v0.y, 0.f);
                v1.x = fmaxf(v1.x, 0.f); v1.y = fmaxf(v1.y, 0.f);
            }
            *(float2*)&C[i0] = v0;
            *(float2*)&C[i1] = v1;
        }
}

// ---------------------------------------------------------------------------
// Scratch
// ---------------------------------------------------------------------------
#define WT_FLOATS (3 * E_ * E_ + 2 * E_ * FF_)
__device__ float g_scratch[(size_t)7 * BT_ * E_ + (size_t)BT_ * FF_ + WT_FLOATS];

// ---------------------------------------------------------------------------
// positional encoding add
// ---------------------------------------------------------------------------
__global__ void add_pos_kernel(const float4* __restrict__ q,
                               const float4* __restrict__ k,
                               const float4* __restrict__ pq,
                               const float4* __restrict__ pk,
                               float4* __restrict__ qin,
                               float4* __restrict__ kin) {
    int i  = blockIdx.x * 256 + threadIdx.x;
    int pi = i % (T_ * E_ / 4);
    const float s = 22.62741699796952f;
    float4 a = q[i], p = pq[pi];
    float4 r;
    r.x = a.x + p.x * s; r.y = a.y + p.y * s;
    r.z = a.z + p.z * s; r.w = a.w + p.w * s;
    qin[i] = r;
    a = k[i]; p = pk[pi];
    r.x = a.x + p.x * s; r.y = a.y + p.y * s;
    r.z = a.z + p.z * s; r.w = a.w + p.w * s;
    kin[i] = r;
}

// ---------------------------------------------------------------------------
// all 5 weight transposes in ONE launch.  WT[n,k] = W[k,n]
// ---------------------------------------------------------------------------
__global__ void transpose_all_kernel(
    const float* __restrict__ WQ, const float* __restrict__ WK,
    const float* __restrict__ WV, const float* __restrict__ F1,
    const float* __restrict__ F2,
    float* __restrict__ wqT, float* __restrict__ wkT, float* __restrict__ wvT,
    float* __restrict__ f1T, float* __restrict__ f2T) {
    __shared__ float t[32][33];
    int bid = blockIdx.x;
    const float* W; float* WT; int K, N, tile;
    if (bid < 256)       { W = WQ; WT = wqT; K = E_;  N = E_;  tile = bid; }
    else if (bid < 512)  { W = WK; WT = wkT; K = E_;  N = E_;  tile = bid - 256; }
    else if (bid < 768)  { W = WV; WT = wvT; K = E_;  N = E_;  tile = bid - 512; }
    else if (bid < 1792) { W = F1; WT = f1T; K = E_;  N = FF_; tile = bid - 768; }
    else                 { W = F2; WT = f2T; K = FF_; N = E_;  tile = bid - 1792; }
    int ntx = N / 32;
    int bn = (tile % ntx) * 32, bk = (tile / ntx) * 32;
    for (int j = threadIdx.y; j < 32; j += 8)
        t[j][threadIdx.x] = W[(size_t)(bk + j) * N + bn + threadIdx.x];
    __syncthreads();
    for (int j = threadIdx.y; j < 32; j += 8)
        WT[(size_t)(bn + j) * K + bk + threadIdx.x] = t[threadIdx.x][j];
}

// ---------------------------------------------------------------------------
// Attention kernel 1: S = Q K^T (3-term mma) + softmax -> normalized P (fp16)
// written to gmem.  32-row q-blocks, 102.4KB smem -> 2 CTAs/SM so one CTA's
// MUFU softmax overlaps the other's tensor S-mma.
// P row layout: [(b*H+h)*T + q][224] halves (cols >= kbmax*32 written only
// when kl==1, the one case an all-masked row exists).
// ---------------------------------------------------------------------------
#define A1_KPB 144             // K/Q pitch bytes (72 halves): conflict-free
#define A1_SCP 224             // Sc pitch floats
#define A1_OFF_KHI 0
#define A1_OFF_KLO 32256
#define A1_OFF_QHI 64512
#define A1_OFF_QLO 69120
#define A1_OFF_SC  73728
#define A1_SMEM    102400
#define PW  224                // P row width (halves)
#define PBH (T_ * PW)          // per-(b,h) stride

__global__ void __launch_bounds__(256, 2)
attn_sm_kernel(const int* __restrict__ qlen, const int* __restrict__ klen,
               const float* __restrict__ Q, const float* __restrict__ KV,
               __half* __restrict__ Pg) {
    extern __shared__ char sm[];
    const uint32_t smb = (uint32_t)__cvta_generic_to_shared(sm);
    float* Sc = (float*)(sm + A1_OFF_SC);

    const int h = blockIdx.x, b = blockIdx.y;
    const int tid = threadIdx.x, w = tid >> 5, lane = tid & 31;
    const int kl = klen[b], ql = qlen[b];
    const int kbmax = (kl + 31) >> 5;
    const int lim = kbmax * 32;
    const int g = lane >> 2, t = lane & 3;
    const int mat = lane >> 3, jr = lane & 7;
    const int a_r    = ((mat & 1) << 3) + jr;
    const int a_koff = (mat >> 1) << 3;
    const int b_koff = (mat & 1) << 3;
    const int b_n    = ((mat >> 1) << 3) + jr;
    const size_t pbase = (size_t)(b * H_ + h) * PBH;

    // load K hi/lo (224 rows, zero-padded)
    for (int i = tid; i < 224 * 16; i += 256) {
        int tt = i >> 4, d4 = (i & 15) * 4;
        float4 kv = make_float4(0.f, 0.f, 0.f, 0.f);
        if (tt < T_)
            kv = *(const float4*)&KV[(size_t)(b * T_ + tt) * 1024 + h * DH_ + d4];
        uint32_t h01, l01, h23, l23;
        split2(kv.x, kv.y, h01, l01);
        split2(kv.z, kv.w, h23, l23);
        *(uint2*)(sm + A1_OFF_KHI + tt * A1_KPB + d4 * 2) = make_uint2(h01, h23);
        *(uint2*)(sm + A1_OFF_KLO + tt * A1_KPB + d4 * 2) = make_uint2(l01, l23);
    }

    for (int qb = 0; qb < 7; qb++) {
        const int qb0 = qb * 32;
        __syncthreads();
        // load 32 Q rows hi/lo (zero beyond T_)
        for (int i = tid; i < 32 * 16; i += 256) {
            int r = i >> 4, d4 = (i & 15) * 4;
            int qq = qb0 + r;
            float4 qv = make_float4(0.f, 0.f, 0.f, 0.f);
            if (qq < T_)
                qv = *(const float4*)&Q[(size_t)(b * T_ + qq) * E_ + h * DH_ + d4];
            uint32_t h01, l01, h23, l23;
            split2(qv.x, qv.y, h01, l01);
            split2(qv.z, qv.w, h23, l23);
            *(uint2*)(sm + A1_OFF_QHI + r * A1_KPB + d4 * 2) = make_uint2(h01, h23);
            *(uint2*)(sm + A1_OFF_QLO + r * A1_KPB + d4 * 2) = make_uint2(l01, l23);
        }
        __syncthreads();

        // ---- S-mma: warp (mt = w>>2, ns = w&3 covering 64 cols)
        {
            const int mt = w >> 2, ns = w & 3;
            uint32_t ah[4][4], al[4][4];
            const uint32_t abase  = smb + A1_OFF_QHI + (mt * 16 + a_r) * A1_KPB + a_koff * 2;
            const uint32_t abasel = abase + (A1_OFF_QLO - A1_OFF_QHI);
#pragma unroll
            for (int ks = 0; ks < 4; ks++) {
                ldsm_x4(ah[ks], abase + ks * 32);
                ldsm_x4(al[ks], abasel + ks * 32);
            }
            for (int p = 0; p < 4; p++) {
                const int np = ns * 64 + p * 16;
                if (np >= lim) break;
                float acc0[4] = {0.f, 0.f, 0.f, 0.f};
                float acc1[4] = {0.f, 0.f, 0.f, 0.f};
#pragma unroll
                for (int ks = 0; ks < 4; ks++) {
                    uint32_t bh[4], bl[4];
                    const uint32_t boff = (np + b_n) * A1_KPB + (ks * 16 + b_koff) * 2;
                    ldsm_x4(bh, smb + A1_OFF_KHI + boff);
                    ldsm_x4(bl, smb + A1_OFF_KLO + boff);
                    mma16816(acc0, ah[ks], bh);
                    mma16816(acc0, ah[ks], bl);
                    mma16816(acc0, al[ks], bh);
                    mma16816(acc1, ah[ks], bh + 2);
                    mma16816(acc1, ah[ks], bl + 2);
                    mma16816(acc1, al[ks], bh + 2);
                }
                const int lr = mt * 16 + g;
                const int q0 = qb0 + lr, q1 = q0 + 8;
#pragma unroll
                for (int hf = 0; hf < 2; hf++) {
                    const float* ac = hf ? acc1 : acc0;
                    const int c = np + hf * 8 + 2 * t;
                    float2 v;
                    v.x = (c     < kl && c     != q0) ? ac[0] * 0.125f : NEGV;
                    v.y = (c + 1 < kl && c + 1 != q0) ? ac[1] * 0.125f : NEGV;
                    *(float2*)&Sc[lr * A1_SCP + c] = v;
                    v.x = (c     < kl && c     != q1) ? ac[2] * 0.125f : NEGV;
                    v.y = (c + 1 < kl && c + 1 != q1) ? ac[3] * 0.125f : NEGV;
                    *(float2*)&Sc[(lr + 8) * A1_SCP + c] = v;
                }
            }
        }
        __syncthreads();

        // ---- softmax + normalize + write P (warp w owns rows w*4..w*4+3)
        {
            const int r0 = w * 4;
            float mx[4] = {-INFINITY, -INFINITY, -INFINITY, -INFINITY};
            for (int kb = 0; kb < kbmax; kb++) {
                int kk = kb * 32 + lane;
#pragma unroll
                for (int r = 0; r < 4; r++)
                    mx[r] = fmaxf(mx[r], Sc[(r0 + r) * A1_SCP + kk]);
            }
#pragma unroll
            for (int r = 0; r < 4; r++)
#pragma unroll
                for (int off = 16; off; off >>= 1)
                    mx[r] = fmaxf(mx[r], __shfl_xor_sync(0xffffffff, mx[r], off));

            float sum[4] = {0.f, 0.f, 0.f, 0.f};
            for (int kb = 0; kb < kbmax; kb++) {
                int kk = kb * 32 + lane;
#pragma unroll
                for (int r = 0; r < 4; r++) {
                    float e = __expf(Sc[(r0 + r) * A1_SCP + kk] - mx[r]);
                    Sc[(r0 + r) * A1_SCP + kk] = e;
                    sum[r] += e;
                }
            }
            if (kl == 1) {
                // all-masked rows possible (row q==0 only): uniform fill
                for (int kb = 1; kb < 7; kb++) {
                    int kk = kb * 32 + lane;
#pragma unroll
                    for (int r = 0; r < 4; r++) {
                        float v = (mx[r] == NEGV && kk < T_) ? 1.f : 0.f;
                        Sc[(r0 + r) * A1_SCP + kk] = v;
                        sum[r] += v;
                    }
                }
            }
#pragma unroll
            for (int r = 0; r < 4; r++)
#pragma unroll
                for (int off = 16; off; off >>= 1)
                    sum[r] += __shfl_xor_sync(0xffffffff, sum[r], off);

            const int cmax = (kl == 1) ? 7 : kbmax;
#pragma unroll
            for (int r = 0; r < 4; r++) {
                int qq = qb0 + r0 + r;
                if (qq < T_) {
                    float inv = (qq < ql) ? (1.f / sum[r]) : 0.f;
                    for (int kb = 0; kb < cmax; kb++) {
                        int kk = kb * 32 + lane;
                        Pg[pbase + (size_t)qq * PW + kk] =
                            __float2half_rn(Sc[(r0 + r) * A1_SCP + kk] * inv);
                    }
                }
            }
        }
    }
}

// ---------------------------------------------------------------------------
// Attention kernel 2: O = P V + qin residual (pure fp16 tensor GEMM).
// ---------------------------------------------------------------------------
#define A2_VP 232              // V^T / P pitch (halves), 464B: conflict-free
#define A2_VPB (A2_VP * 2)
#define A2_OFF_VT 0
#define A2_OFF_P  29696
#define A2_SMEM   (A2_OFF_P + 32 * A2_VPB)   // 44544

__global__ void __launch_bounds__(256, 2)
attn_av_kernel(const int* __restrict__ qlen, const int* __restrict__ klen,
               const __half* __restrict__ Pg, const float* __restrict__ KV,
               const float* __restrict__ qin, float* __restrict__ ctx) {
    extern __shared__ char sm[];
    const uint32_t smb = (uint32_t)__cvta_generic_to_shared(sm);
    __half* vt = (__half*)(sm + A2_OFF_VT);

    const int h = blockIdx.x, b = blockIdx.y;
    const int tid = threadIdx.x, w = tid >> 5, lane = tid & 31;
    const int kl = klen[b];
    const int kbmax = (kl + 31) >> 5;
    const int kks = (kl == 1) ? 14 : 2 * kbmax;
    const int g = lane >> 2, t = lane & 3;
    const int mat = lane >> 3, jr = lane & 7;
    const int a_r    = ((mat & 1) << 3) + jr;
    const int a_koff = (mat >> 1) << 3;
    const int b_koff = (mat & 1) << 3;
    const int b_n    = ((mat >> 1) << 3) + jr;
    const size_t pbase = (size_t)(b * H_ + h) * PBH;

    // build V^T fp16 (64 dims x 232 cols, zero-padded)
    for (int i = tid; i < 224 * 16; i += 256) {
        int tt = i >> 4, d4 = (i & 15) * 4;
        float4 vv = make_float4(0.f, 0.f, 0.f, 0.f);
        if (tt < T_)
            vv = *(const float4*)&KV[(size_t)(b * T_ + tt) * 1024 + 512 + h * DH_ + d4];
        vt[(d4 + 0) * A2_VP + tt] = __float2half_rn(vv.x);
        vt[(d4 + 1) * A2_VP + tt] = __float2half_rn(vv.y);
        vt[(d4 + 2) * A2_VP + tt] = __float2half_rn(vv.z);
        vt[(d4 + 3) * A2_VP + tt] = __float2half_rn(vv.w);
    }

    for (int qb = 0; qb < 7; qb++) {
        const int qb0 = qb * 32;
        __syncthreads();
        // load P tile 32 rows x 224 halves (zero rows beyond T_)
        for (int i = tid; i < 32 * 28; i += 256) {
            int r = i / 28, c4 = i % 28;
            int qq = qb0 + r;
            uint4 v = make_uint4(0u, 0u, 0u, 0u);
            if (qq < T_)
                v = *(const uint4*)&Pg[pbase + (size_t)qq * PW + c4 * 8];
            *(uint4*)(sm + A2_OFF_P + r * A2_VPB + c4 * 16) = v;
        }
        __syncthreads();

        // warp (mt = w>>2, nq = w&3 covering 16 dims)
        const int mt = w >> 2, nq = w & 3;
        float acc[2][4];
#pragma unroll
        for (int j = 0; j < 2; j++)
#pragma unroll
            for (int k = 0; k < 4; k++) acc[j][k] = 0.f;
        for (int ks = 0; ks < kks; ks++) {
            uint32_t ap[4];
            ldsm_x4(ap, smb + A2_OFF_P + (mt * 16 + a_r) * A2_VPB + (ks * 16 + a_koff) * 2);
            uint32_t bv[4];
            ldsm_x4(bv, smb + A2_OFF_VT + (nq * 16 + b_n) * A2_VPB + (ks * 16 + b_koff) * 2);
            mma16816(acc[0], ap, bv);
            mma16816(acc[1], ap, bv + 2);
        }
        const int lr = mt * 16 + g;
        const int q0 = qb0 + lr, q1 = q0 + 8;
#pragma unroll
        for (int j = 0; j < 2; j++) {
            const int dh = nq * 16 + j * 8 + 2 * t;
            if (q0 < T_) {
                size_t base = (size_t)(b * T_ + q0) * E_ + h * DH_ + dh;
                float2 qi = *(const float2*)&qin[base];
                *(float2*)&ctx[base] =
                    make_float2(acc[j][0] + qi.x, acc[j][1] + qi.y);
            }
            if (q1 < T_) {
                size_t base = (size_t)(b * T_ + q1) * E_ + h * DH_ + dh;
                float2 qi = *(const float2*)&qin[base];
                *(float2*)&ctx[base] =
                    make_float2(acc[j][2] + qi.x, acc[j][3] + qi.y);
            }
        }
    }
}

// ---------------------------------------------------------------------------
// mean over T -> (B,1,E)
// ---------------------------------------------------------------------------
__global__ void mean_kernel(const float* __restrict__ o2, float* __restrict__ out) {
    int b = blockIdx.x, e = threadIdx.x;
    float s = 0.f;
    for (int t = 0; t < T_; t++)
        s += o2[(size_t)(b * T_ + t) * E_ + e];
    out[b * E_ + e] = s * (1.0f / T_);
}

// ---------------------------------------------------------------------------
// Launch
// ---------------------------------------------------------------------------
extern "C" void kernel_launch(void* const* d_in, const int* in_sizes, int n_in,
                              void* d_out, int out_size) {
    const float* queries = (const float*)d_in[0];
    const float* keys    = (const float*)d_in[1];
    const int*   qlen    = (const int*)d_in[2];
    const int*   klen    = (const int*)d_in[3];
    const float* pos_q   = (const float*)d_in[4];
    const float* pos_k   = (const float*)d_in[5];
    const float* W_Q     = (const float*)d_in[6];
    const float* W_K     = (const float*)d_in[7];
    const float* W_V     = (const float*)d_in[8];
    const float* fw1     = (const float*)d_in[9];
    const float* fw2     = (const float*)d_in[10];
    float*       out     = (float*)d_out;

    float* base = nullptr;
    cudaGetSymbolAddress((void**)&base, g_scratch);
    const size_t BTE = (size_t)BT_ * E_;
    float* qin = base;
    float* kin = base + 1 * BTE;
    float* Qp  = base + 2 * BTE;
    float* KVb = base + 3 * BTE;            // merged [BT][1024]: K 0-511, V 512-1023
    float* ctx = base + 5 * BTE;
    float* o2  = base + 6 * BTE;
    float* hid = base + 7 * BTE;
    float* wqT = hid + (size_t)BT_ * FF_;
    float* wkT = wqT + E_ * E_;
    float* wvT = wkT + E_ * E_;
    float* f1T = wvT + E_ * E_;
    float* f2T = f1T + (size_t)E_ * FF_;
    __half* Pg = (__half*)hid;              // P buffer reuses hid (free until FFN1)

    cudaFuncSetAttribute(hgemm_kernel<false, false, 3, 1>,
                         cudaFuncAttributeMaxDynamicSharedMemorySize, GEMM_DSMEM);
    cudaFuncSetAttribute(hgemm_kernel<false, false, 1, 2>,
                         cudaFuncAttributeMaxDynamicSharedMemorySize, GEMM_DSMEM);
    cudaFuncSetAttribute(hgemm_kernel<true, false, 1, 2>,
                         cudaFuncAttributeMaxDynamicSharedMemorySize, GEMM_DSMEM);
    cudaFuncSetAttribute(hgemm_kernel<false, true, 1, 2>,
                         cudaFuncAttributeMaxDynamicSharedMemorySize, GEMM_DSMEM);
    cudaFuncSetAttribute(attn_sm_kernel,
                         cudaFuncAttributeMaxDynamicSharedMemorySize, A1_SMEM);
    cudaFuncSetAttribute(attn_av_kernel,
                         cudaFuncAttributeMaxDynamicSharedMemorySize, A2_SMEM);

    // 1. all weight transposes
    transpose_all_kernel<<<2816, dim3(32, 8)>>>(W_Q, W_K, W_V, fw1, fw2,
                                                wqT, wkT, wvT, f1T, f2T);
    // 2. positional encoding
    add_pos_kernel<<<(BT_ * E_ / 4) / 256, 256>>>(
        (const float4*)queries, (const float4*)keys,
        (const float4*)pos_q, (const float4*)pos_k,
        (float4*)qin, (float4*)kin);

    // 3. Q projection (3-term)
    hgemm_kernel<false, false, 3, 1><<<dim3(E_ / GBN, BT_ / GBM), 256, GEMM_DSMEM>>>(
        qin, wqT, nullptr, Qp, BT_, E_, E_, E_);
    // 4. K projection (3-term)
    hgemm_kernel<false, false, 3, 1><<<dim3(E_ / GBN, BT_ / GBM), 256, GEMM_DSMEM>>>(
        kin, wkT, nullptr, KVb, BT_, E_, E_, 2 * E_);
    // 5. V projection (1-term)
    hgemm_kernel<false, false, 1, 2><<<dim3(E_ / GBN, BT_ / GBM), 256, GEMM_DSMEM>>>(
        kin, wvT, nullptr, KVb + E_, BT_, E_, E_, 2 * E_);

    // 6. attention scores + softmax -> P
    attn_sm_kernel<<<dim3(H_, B_), 256, A1_SMEM>>>(qlen, klen, Qp, KVb, Pg);
    // 7. attention O = P V + residual
    attn_av_kernel<<<dim3(H_, B_), 256, A2_SMEM>>>(qlen, klen, Pg, KVb, qin, ctx);

    // 8. FFN up + ReLU (1-term fp16)
    hgemm_kernel<true, false, 1, 2><<<dim3(FF_ / GBN, BT_ / GBM), 256, GEMM_DSMEM>>>(
        ctx, f1T, nullptr, hid, BT_, FF_, E_, FF_);

    // 9. FFN down + residual (1-term fp16)
    hgemm_kernel<false, true, 1, 2><<<dim3(E_ / GBN, BT_ / GBM), 256, GEMM_DSMEM>>>(
        hid, f2T, ctx, o2, BT_, E_, FF_, E_);

    // 10. mean over time
    mean_kernel<<<B_, E_>>>(o2, out);
}

// round 15
// speedup vs baseline: 2.3743x; 1.1673x over previous
#include <cuda_runtime.h>
#include <cuda_fp16.h>
#include <math.h>
#include <stdint.h>

// Problem dims
#define B_   256
#define T_   200
#define E_   512
#define H_   8
#define DH_  64
#define FF_  2048
#define BT_  (B_*T_)

#define NEGV (-4294967295.0f)

#define GBM 128
#define GBN 128
#define GBK 32
#define ROWB 80                 // smem row pitch bytes (32 halves data + pad)
#define P16 (GBM * ROWB)        // 10240 bytes per plane

__device__ __forceinline__ void mma16816(float* c, const uint32_t* a, const uint32_t* b) {
    asm volatile(
        "mma.sync.aligned.m16n8k16.row.col.f32.f16.f16.f32 "
        "{%0,%1,%2,%3}, {%4,%5,%6,%7}, {%8,%9}, {%0,%1,%2,%3};"
        : "+f"(c[0]), "+f"(c[1]), "+f"(c[2]), "+f"(c[3])
        : "r"(a[0]), "r"(a[1]), "r"(a[2]), "r"(a[3]), "r"(b[0]), "r"(b[1]));
}
__device__ __forceinline__ void ldsm_x4(uint32_t* r, uint32_t addr) {
    asm volatile("ldmatrix.sync.aligned.m8n8.x4.shared.b16 {%0,%1,%2,%3}, [%4];"
                 : "=r"(r[0]), "=r"(r[1]), "=r"(r[2]), "=r"(r[3]) : "r"(addr));
}
__device__ __forceinline__ void split2(float x, float y, uint32_t& hi, uint32_t& lo) {
    __half hx = __float2half_rn(x);
    __half hy = __float2half_rn(y);
    __half lx = __float2half_rn(x - __half2float(hx));
    __half ly = __float2half_rn(y - __half2float(hy));
    hi = (uint32_t)__half_as_ushort(hx) | ((uint32_t)__half_as_ushort(hy) << 16);
    lo = (uint32_t)__half_as_ushort(lx) | ((uint32_t)__half_as_ushort(ly) << 16);
}
__device__ __forceinline__ uint32_t hi2(float x, float y) {
    __half hx = __float2half_rn(x);
    __half hy = __float2half_rn(y);
    return (uint32_t)__half_as_ushort(hx) | ((uint32_t)__half_as_ushort(hy) << 16);
}

// ---------------------------------------------------------------------------
// fp16-plane GEMM: C = A @ B^T from pre-split fp16 operands.
// MODE=3: ah*bh + ah*bl + al*bh ; MODE=1: ah*bh.
// EPI: 0 = fp32 out (+C0 add, opt RELU), 1 = fp16-hi out (opt RELU),
//      2 = fp16 hi+lo out.
// ---------------------------------------------------------------------------
template <bool RELU, bool ADD, int MODE, int EPI, int MINB>
__global__ void __launch_bounds__(256, MINB)
hgemm16_kernel(const __half* __restrict__ Ah, const __half* __restrict__ Al,
               const __half* __restrict__ Bh, const __half* __restrict__ Bl,
               const float* __restrict__ C0,
               __half* __restrict__ Ch, __half* __restrict__ Cl,
               float* __restrict__ Cf,
               int M, int N, int K, int ldc) {
    extern __shared__ char smem[];
    const uint32_t smb = (uint32_t)__cvta_generic_to_shared(smem);
    constexpr int NP = (MODE >= 3) ? 4 : 2;
    constexpr int STG = NP * P16;
    constexpr int OA_HI = 0;
    constexpr int OA_LO = P16;
    constexpr int OB_HI = (MODE >= 3) ? 2 * P16 : P16;
    constexpr int OB_LO = OB_HI + P16;

    const int tid = threadIdx.x;
    const int wid = tid >> 5, lane = tid & 31;
    const int m0 = blockIdx.y * GBM, n0 = blockIdx.x * GBN;
    const int wm = (wid >> 2) * 64, wn = (wid & 3) * 32;
    const int g = lane >> 2, t = lane & 3;
    const int mat = lane >> 3, jr = lane & 7;
    const int a_r    = ((mat & 1) << 3) + jr;
    const int a_koff = (mat >> 1) << 3;
    const int b_koff = (mat & 1) << 3;
    const int b_n    = ((mat >> 1) << 3) + jr;

    float acc[4][4][4];
#pragma unroll
    for (int i = 0; i < 4; i++)
#pragma unroll
        for (int j = 0; j < 4; j++)
#pragma unroll
            for (int k = 0; k < 4; k++) acc[i][j][k] = 0.f;

    const int nt = K / GBK;
    uint4 la[2], lb[2], lal[2], lbl[2];

    auto LDG = [&](int k0) {
#pragma unroll
        for (int j = 0; j < 2; j++) {
            int idx = tid + j * 256;
            int r = idx >> 2, c8 = idx & 3;
            la[j] = *(const uint4*)&Ah[(size_t)(m0 + r) * K + k0 + c8 * 8];
            lb[j] = *(const uint4*)&Bh[(size_t)(n0 + r) * K + k0 + c8 * 8];
            if (MODE >= 3) {
                lal[j] = *(const uint4*)&Al[(size_t)(m0 + r) * K + k0 + c8 * 8];
                lbl[j] = *(const uint4*)&Bl[(size_t)(n0 + r) * K + k0 + c8 * 8];
            }
        }
    };
    auto STS = [&](int s) {
        char* b = smem + s * STG;
#pragma unroll
        for (int j = 0; j < 2; j++) {
            int idx = tid + j * 256;
            int r = idx >> 2, c8 = idx & 3;
            uint32_t off = r * ROWB + c8 * 16;
            *(uint4*)(b + OA_HI + off) = la[j];
            *(uint4*)(b + OB_HI + off) = lb[j];
            if (MODE >= 3) {
                *(uint4*)(b + OA_LO + off) = lal[j];
                *(uint4*)(b + OB_LO + off) = lbl[j];
            }
        }
    };

    LDG(0);
    STS(0);

    for (int it = 0; it < nt; it++) {
        __syncthreads();
        if (it + 1 < nt) LDG((it + 1) * GBK);

        const uint32_t st = smb + (it & 1) * STG;
        const uint32_t ahi = st + OA_HI, alo = st + OA_LO;
        const uint32_t bhi = st + OB_HI, blo = st + OB_LO;

#pragma unroll
        for (int ks = 0; ks < GBK; ks += 16) {
            uint32_t ah[4][4], al[4][4], bh[4][2], bl[4][2];
            const uint32_t a_off = (wm + a_r) * ROWB + (ks + a_koff) * 2;
            const uint32_t b_off = (wn + b_n) * ROWB + (ks + b_koff) * 2;
#pragma unroll
            for (int mt = 0; mt < 4; mt++) {
                ldsm_x4(ah[mt], ahi + a_off + mt * (16 * ROWB));
                if (MODE >= 3) ldsm_x4(al[mt], alo + a_off + mt * (16 * ROWB));
            }
#pragma unroll
            for (int p = 0; p < 2; p++) {
                uint32_t tmp[4];
                ldsm_x4(tmp, bhi + b_off + p * (16 * ROWB));
                bh[2 * p][0] = tmp[0]; bh[2 * p][1] = tmp[1];
                bh[2 * p + 1][0] = tmp[2]; bh[2 * p + 1][1] = tmp[3];
                if (MODE >= 3) {
                    ldsm_x4(tmp, blo + b_off + p * (16 * ROWB));
                    bl[2 * p][0] = tmp[0]; bl[2 * p][1] = tmp[1];
                    bl[2 * p + 1][0] = tmp[2]; bl[2 * p + 1][1] = tmp[3];
                }
            }
#pragma unroll
            for (int mt = 0; mt < 4; mt++)
#pragma unroll
                for (int ntl = 0; ntl < 4; ntl++) {
                    mma16816(acc[mt][ntl], ah[mt], bh[ntl]);
                    if (MODE >= 3) {
                        mma16816(acc[mt][ntl], ah[mt], bl[ntl]);
                        mma16816(acc[mt][ntl], al[mt], bh[ntl]);
                    }
                }
        }
        if (it + 1 < nt) STS((it + 1) & 1);
    }

#pragma unroll
    for (int mt = 0; mt < 4; mt++)
#pragma unroll
        for (int ntl = 0; ntl < 4; ntl++) {
            int row = m0 + wm + mt * 16 + g;
            int col = n0 + wn + ntl * 8 + 2 * t;
            size_t i0 = (size_t)row * ldc + col;
            size_t i1 = (size_t)(row + 8) * ldc + col;
            float a0 = acc[mt][ntl][0], a1 = acc[mt][ntl][1];
            float a2 = acc[mt][ntl][2], a3 = acc[mt][ntl][3];
            if (RELU) {
                a0 = fmaxf(a0, 0.f); a1 = fmaxf(a1, 0.f);
                a2 = fmaxf(a2, 0.f); a3 = fmaxf(a3, 0.f);
            }
            if (EPI == 0) {
                float2 v0 = make_float2(a0, a1), v1 = make_float2(a2, a3);
                if (ADD) {
                    float2 c0 = *(const float2*)&C0[i0];
                    float2 c1 = *(const float2*)&C0[i1];
                    v0.x += c0.x; v0.y += c0.y; v1.x += c1.x; v1.y += c1.y;
                }
                *(float2*)&Cf[i0] = v0;
                *(float2*)&Cf[i1] = v1;
            } else if (EPI == 1) {
                *(uint32_t*)&Ch[i0] = hi2(a0, a1);
                *(uint32_t*)&Ch[i1] = hi2(a2, a3);
            } else {
                uint32_t h, l;
                split2(a0, a1, h, l);
                *(uint32_t*)&Ch[i0] = h; *(uint32_t*)&Cl[i0] = l;
                split2(a2, a3, h, l);
                *(uint32_t*)&Ch[i1] = h; *(uint32_t*)&Cl[i1] = l;
            }
        }
}

// ---------------------------------------------------------------------------
// Scratch
// ---------------------------------------------------------------------------
__device__ float g_scratch[(size_t)7 * BT_ * E_ + (size_t)BT_ * FF_ +
                           (3 * E_ * E_ + 2 * E_ * FF_)];

// ---------------------------------------------------------------------------
// pos-encode: qin fp32 (residual) + qin/kin hi/lo fp16 planes
// ---------------------------------------------------------------------------
__global__ void add_pos_kernel(const float4* __restrict__ q,
                               const float4* __restrict__ k,
                               const float4* __restrict__ pq,
                               const float4* __restrict__ pk,
                               float4* __restrict__ qin,
                               __half* __restrict__ qin_h, __half* __restrict__ qin_l,
                               __half* __restrict__ kin_h, __half* __restrict__ kin_l) {
    int i  = blockIdx.x * 256 + threadIdx.x;
    int pi = i % (T_ * E_ / 4);
    const float s = 22.62741699796952f;
    size_t off = (size_t)i * 4;
    float4 a = q[i], p = pq[pi];
    float4 r;
    r.x = a.x + p.x * s; r.y = a.y + p.y * s;
    r.z = a.z + p.z * s; r.w = a.w + p.w * s;
    qin[i] = r;
    uint32_t h01, l01, h23, l23;
    split2(r.x, r.y, h01, l01); split2(r.z, r.w, h23, l23);
    *(uint2*)&qin_h[off] = make_uint2(h01, h23);
    *(uint2*)&qin_l[off] = make_uint2(l01, l23);
    a = k[i]; p = pk[pi];
    r.x = a.x + p.x * s; r.y = a.y + p.y * s;
    r.z = a.z + p.z * s; r.w = a.w + p.w * s;
    split2(r.x, r.y, h01, l01); split2(r.z, r.w, h23, l23);
    *(uint2*)&kin_h[off] = make_uint2(h01, h23);
    *(uint2*)&kin_l[off] = make_uint2(l01, l23);
}

// ---------------------------------------------------------------------------
// all weight transposes -> fp16 hi(/lo) planes.  WT[n,k] = W[k,n]
// ---------------------------------------------------------------------------
__global__ void transpose_all_kernel(
    const float* __restrict__ WQ, const float* __restrict__ WK,
    const float* __restrict__ WV, const float* __restrict__ F1,
    const float* __restrict__ F2,
    __half* __restrict__ wqT_h, __half* __restrict__ wqT_l,
    __half* __restrict__ wkT_h, __half* __restrict__ wkT_l,
    __half* __restrict__ wvT_h,
    __half* __restrict__ f1T_h, __half* __restrict__ f2T_h) {
    __shared__ float t[32][33];
    int bid = blockIdx.x;
    const float* W; __half* WTh; __half* WTl = nullptr; int K, N, tile;
    if (bid < 256)       { W = WQ; WTh = wqT_h; WTl = wqT_l; K = E_;  N = E_;  tile = bid; }
    else if (bid < 512)  { W = WK; WTh = wkT_h; WTl = wkT_l; K = E_;  N = E_;  tile = bid - 256; }
    else if (bid < 768)  { W = WV; WTh = wvT_h;              K = E_;  N = E_;  tile = bid - 512; }
    else if (bid < 1792) { W = F1; WTh = f1T_h;              K = E_;  N = FF_; tile = bid - 768; }
    else                 { W = F2; WTh = f2T_h;              K = FF_; N = E_;  tile = bid - 1792; }
    int ntx = N / 32;
    int bn = (tile % ntx) * 32, bk = (tile / ntx) * 32;
    for (int j = threadIdx.y; j < 32; j += 8)
        t[j][threadIdx.x] = W[(size_t)(bk + j) * N + bn + threadIdx.x];
    __syncthreads();
    for (int j = threadIdx.y; j < 32; j += 8) {
        float x = t[threadIdx.x][j];
        __half hx = __float2half_rn(x);
        size_t idx = (size_t)(bn + j) * K + bk + threadIdx.x;
        WTh[idx] = hx;
        if (WTl) WTl[idx] = __float2half_rn(x - __half2float(hx));
    }
}

// ---------------------------------------------------------------------------
// A1: S = Q K^T (3-term) + softmax -> normalized P fp16 in gmem.
// ---------------------------------------------------------------------------
#define A1_KPB 144
#define A1_SCP 224
#define A1_OFF_KHI 0
#define A1_OFF_KLO 32256
#define A1_OFF_QHI 64512
#define A1_OFF_QLO 69120
#define A1_OFF_SC  73728
#define A1_SMEM    102400
#define PW  224
#define PBH (T_ * PW)

__global__ void __launch_bounds__(256, 2)
attn_sm_kernel(const int* __restrict__ qlen, const int* __restrict__ klen,
               const __half* __restrict__ Qh, const __half* __restrict__ Ql,
               const __half* __restrict__ Kh, const __half* __restrict__ Kl,
               __half* __restrict__ Pg) {
    extern __shared__ char sm[];
    const uint32_t smb = (uint32_t)__cvta_generic_to_shared(sm);
    float* Sc = (float*)(sm + A1_OFF_SC);

    const int h = blockIdx.x, b = blockIdx.y;
    const int tid = threadIdx.x, w = tid >> 5, lane = tid & 31;
    const int kl = klen[b], ql = qlen[b];
    const int kbmax = (kl + 31) >> 5;
    const int lim = kbmax * 32;
    const int g = lane >> 2, t = lane & 3;
    const int mat = lane >> 3, jr = lane & 7;
    const int a_r    = ((mat & 1) << 3) + jr;
    const int a_koff = (mat >> 1) << 3;
    const int b_koff = (mat & 1) << 3;
    const int b_n    = ((mat >> 1) << 3) + jr;
    const size_t pbase = (size_t)(b * H_ + h) * PBH;

    // K planes (fp16 direct, zero-padded to 224 rows)
    for (int i = tid; i < 224 * 8; i += 256) {
        int tt = i >> 3, c8 = i & 7;
        uint4 vh = make_uint4(0u, 0u, 0u, 0u), vl = vh;
        if (tt < T_) {
            size_t gi = (size_t)(b * T_ + tt) * E_ + h * DH_ + c8 * 8;
            vh = *(const uint4*)&Kh[gi];
            vl = *(const uint4*)&Kl[gi];
        }
        *(uint4*)(sm + A1_OFF_KHI + tt * A1_KPB + c8 * 16) = vh;
        *(uint4*)(sm + A1_OFF_KLO + tt * A1_KPB + c8 * 16) = vl;
    }

    for (int qb = 0; qb < 7; qb++) {
        const int qb0 = qb * 32;
        __syncthreads();
        for (int i = tid; i < 32 * 8; i += 256) {
            int r = i >> 3, c8 = i & 7;
            int qq = qb0 + r;
            uint4 vh = make_uint4(0u, 0u, 0u, 0u), vl = vh;
            if (qq < T_) {
                size_t gi = (size_t)(b * T_ + qq) * E_ + h * DH_ + c8 * 8;
                vh = *(const uint4*)&Qh[gi];
                vl = *(const uint4*)&Ql[gi];
            }
            *(uint4*)(sm + A1_OFF_QHI + r * A1_KPB + c8 * 16) = vh;
            *(uint4*)(sm + A1_OFF_QLO + r * A1_KPB + c8 * 16) = vl;
        }
        __syncthreads();

        // S-mma
        {
            const int mt = w >> 2, ns = w & 3;
            uint32_t ah[4][4], al[4][4];
            const uint32_t abase  = smb + A1_OFF_QHI + (mt * 16 + a_r) * A1_KPB + a_koff * 2;
            const uint32_t abasel = abase + (A1_OFF_QLO - A1_OFF_QHI);
#pragma unroll
            for (int ks = 0; ks < 4; ks++) {
                ldsm_x4(ah[ks], abase + ks * 32);
                ldsm_x4(al[ks], abasel + ks * 32);
            }
            for (int p = 0; p < 4; p++) {
                const int np = ns * 64 + p * 16;
                if (np >= lim) break;
                float acc0[4] = {0.f, 0.f, 0.f, 0.f};
                float acc1[4] = {0.f, 0.f, 0.f, 0.f};
#pragma unroll
                for (int ks = 0; ks < 4; ks++) {
                    uint32_t bh[4], bl[4];
                    const uint32_t boff = (np + b_n) * A1_KPB + (ks * 16 + b_koff) * 2;
                    ldsm_x4(bh, smb + A1_OFF_KHI + boff);
                    ldsm_x4(bl, smb + A1_OFF_KLO + boff);
                    mma16816(acc0, ah[ks], bh);
                    mma16816(acc0, ah[ks], bl);
                    mma16816(acc0, al[ks], bh);
                    mma16816(acc1, ah[ks], bh + 2);
                    mma16816(acc1, ah[ks], bl + 2);
                    mma16816(acc1, al[ks], bh + 2);
                }
                const int lr = mt * 16 + g;
                const int q0 = qb0 + lr, q1 = q0 + 8;
#pragma unroll
                for (int hf = 0; hf < 2; hf++) {
                    const float* ac = hf ? acc1 : acc0;
                    const int c = np + hf * 8 + 2 * t;
                    float2 v;
                    v.x = (c     < kl && c     != q0) ? ac[0] * 0.125f : NEGV;
                    v.y = (c + 1 < kl && c + 1 != q0) ? ac[1] * 0.125f : NEGV;
                    *(float2*)&Sc[lr * A1_SCP + c] = v;
                    v.x = (c     < kl && c     != q1) ? ac[2] * 0.125f : NEGV;
                    v.y = (c + 1 < kl && c + 1 != q1) ? ac[3] * 0.125f : NEGV;
                    *(float2*)&Sc[(lr + 8) * A1_SCP + c] = v;
                }
            }
        }
        __syncthreads();

        // softmax + normalize + write P
        {
            const int r0 = w * 4;
            float mx[4] = {-INFINITY, -INFINITY, -INFINITY, -INFINITY};
            for (int kb = 0; kb < kbmax; kb++) {
                int kk = kb * 32 + lane;
#pragma unroll
                for (int r = 0; r < 4; r++)
                    mx[r] = fmaxf(mx[r], Sc[(r0 + r) * A1_SCP + kk]);
            }
#pragma unroll
            for (int r = 0; r < 4; r++)
#pragma unroll
                for (int off = 16; off; off >>= 1)
                    mx[r] = fmaxf(mx[r], __shfl_xor_sync(0xffffffff, mx[r], off));

            float sum[4] = {0.f, 0.f, 0.f, 0.f};
            for (int kb = 0; kb < kbmax; kb++) {
                int kk = kb * 32 + lane;
#pragma unroll
                for (int r = 0; r < 4; r++) {
                    float e = __expf(Sc[(r0 + r) * A1_SCP + kk] - mx[r]);
                    Sc[(r0 + r) * A1_SCP + kk] = e;
                    sum[r] += e;
                }
            }
            if (kl == 1) {
                for (int kb = 1; kb < 7; kb++) {
                    int kk = kb * 32 + lane;
#pragma unroll
                    for (int r = 0; r < 4; r++) {
                        float v = (mx[r] == NEGV && kk < T_) ? 1.f : 0.f;
                        Sc[(r0 + r) * A1_SCP + kk] = v;
                        sum[r] += v;
                    }
                }
            }
#pragma unroll
            for (int r = 0; r < 4; r++)
#pragma unroll
                for (int off = 16; off; off >>= 1)
                    sum[r] += __shfl_xor_sync(0xffffffff, sum[r], off);

            const int cmax = (kl == 1) ? 7 : kbmax;
#pragma unroll
            for (int r = 0; r < 4; r++) {
                int qq = qb0 + r0 + r;
                if (qq < T_) {
                    float inv = (qq < ql) ? (1.f / sum[r]) : 0.f;
                    for (int kb = 0; kb < cmax; kb++) {
                        int kk = kb * 32 + lane;
                        Pg[pbase + (size_t)qq * PW + kk] =
                            __float2half_rn(Sc[(r0 + r) * A1_SCP + kk] * inv);
                    }
                }
            }
        }
    }
}

// ---------------------------------------------------------------------------
// A2: O = P V + qin residual; writes ctx fp32 + ctx_h fp16.
// ---------------------------------------------------------------------------
#define A2_VP 232
#define A2_VPB (A2_VP * 2)
#define A2_OFF_VT 0
#define A2_OFF_P  29696
#define A2_SMEM   (A2_OFF_P + 32 * A2_VPB)

__global__ void __launch_bounds__(256, 2)
attn_av_kernel(const int* __restrict__ qlen, const int* __restrict__ klen,
               const __half* __restrict__ Pg, const __half* __restrict__ Vh,
               const float* __restrict__ qin,
               float* __restrict__ ctx, __half* __restrict__ ctx_h) {
    extern __shared__ char sm[];
    const uint32_t smb = (uint32_t)__cvta_generic_to_shared(sm);
    __half* vt = (__half*)(sm + A2_OFF_VT);

    const int h = blockIdx.x, b = blockIdx.y;
    const int tid = threadIdx.x, w = tid >> 5, lane = tid & 31;
    const int kl = klen[b];
    const int kbmax = (kl + 31) >> 5;
    const int kks = (kl == 1) ? 14 : 2 * kbmax;
    const int g = lane >> 2, t = lane & 3;
    const int mat = lane >> 3, jr = lane & 7;
    const int a_r    = ((mat & 1) << 3) + jr;
    const int a_koff = (mat >> 1) << 3;
    const int b_koff = (mat & 1) << 3;
    const int b_n    = ((mat >> 1) << 3) + jr;
    const size_t pbase = (size_t)(b * H_ + h) * PBH;

    // V^T fp16 from Vh
    for (int i = tid; i < 224 * 8; i += 256) {
        int tt = i >> 3, c8 = i & 7;
        uint4 v = make_uint4(0u, 0u, 0u, 0u);
        if (tt < T_)
            v = *(const uint4*)&Vh[(size_t)(b * T_ + tt) * E_ + h * DH_ + c8 * 8];
        const __half* hp = (const __half*)&v;
#pragma unroll
        for (int d = 0; d < 8; d++)
            vt[(c8 * 8 + d) * A2_VP + tt] = hp[d];
    }

    for (int qb = 0; qb < 7; qb++) {
        const int qb0 = qb * 32;
        __syncthreads();
        for (int i = tid; i < 32 * 28; i += 256) {
            int r = i / 28, c4 = i % 28;
            int qq = qb0 + r;
            uint4 v = make_uint4(0u, 0u, 0u, 0u);
            if (qq < T_)
                v = *(const uint4*)&Pg[pbase + (size_t)qq * PW + c4 * 8];
            *(uint4*)(sm + A2_OFF_P + r * A2_VPB + c4 * 16) = v;
        }
        __syncthreads();

        const int mt = w >> 2, nq = w & 3;
        float acc[2][4];
#pragma unroll
        for (int j = 0; j < 2; j++)
#pragma unroll
            for (int k = 0; k < 4; k++) acc[j][k] = 0.f;
        for (int ks = 0; ks < kks; ks++) {
            uint32_t ap[4];
            ldsm_x4(ap, smb + A2_OFF_P + (mt * 16 + a_r) * A2_VPB + (ks * 16 + a_koff) * 2);
            uint32_t bv[4];
            ldsm_x4(bv, smb + A2_OFF_VT + (nq * 16 + b_n) * A2_VPB + (ks * 16 + b_koff) * 2);
            mma16816(acc[0], ap, bv);
            mma16816(acc[1], ap, bv + 2);
        }
        const int lr = mt * 16 + g;
        const int q0 = qb0 + lr, q1 = q0 + 8;
#pragma unroll
        for (int j = 0; j < 2; j++) {
            const int dh = nq * 16 + j * 8 + 2 * t;
            if (q0 < T_) {
                size_t base = (size_t)(b * T_ + q0) * E_ + h * DH_ + dh;
                float2 qi = *(const float2*)&qin[base];
                float2 o = make_float2(acc[j][0] + qi.x, acc[j][1] + qi.y);
                *(float2*)&ctx[base] = o;
                *(uint32_t*)&ctx_h[base] = hi2(o.x, o.y);
            }
            if (q1 < T_) {
                size_t base = (size_t)(b * T_ + q1) * E_ + h * DH_ + dh;
                float2 qi = *(const float2*)&qin[base];
                float2 o = make_float2(acc[j][2] + qi.x, acc[j][3] + qi.y);
                *(float2*)&ctx[base] = o;
                *(uint32_t*)&ctx_h[base] = hi2(o.x, o.y);
            }
        }
    }
}

// ---------------------------------------------------------------------------
// mean over T -> (B,1,E)
// ---------------------------------------------------------------------------
__global__ void mean_kernel(const float* __restrict__ o2, float* __restrict__ out) {
    int b = blockIdx.x, e = threadIdx.x;
    float s = 0.f;
    for (int t = 0; t < T_; t++)
        s += o2[(size_t)(b * T_ + t) * E_ + e];
    out[b * E_ + e] = s * (1.0f / T_);
}

// ---------------------------------------------------------------------------
// Launch
// ---------------------------------------------------------------------------
extern "C" void kernel_launch(void* const* d_in, const int* in_sizes, int n_in,
                              void* d_out, int out_size) {
    const float* queries = (const float*)d_in[0];
    const float* keys    = (const float*)d_in[1];
    const int*   qlen    = (const int*)d_in[2];
    const int*   klen    = (const int*)d_in[3];
    const float* pos_q   = (const float*)d_in[4];
    const float* pos_k   = (const float*)d_in[5];
    const float* W_Q     = (const float*)d_in[6];
    const float* W_K     = (const float*)d_in[7];
    const float* W_V     = (const float*)d_in[8];
    const float* fw1     = (const float*)d_in[9];
    const float* fw2     = (const float*)d_in[10];
    float*       out     = (float*)d_out;

    float* base = nullptr;
    cudaGetSymbolAddress((void**)&base, g_scratch);
    const size_t BTE = (size_t)BT_ * E_;

    float* qin = base;                       // fp32 residual
    float* ctx = base + BTE;                 // fp32 (FFN2 C0)
    float* o2  = base + 2 * BTE;             // fp32 out of FFN2
    __half* hb = (__half*)(base + 3 * BTE);  // fp16 region
    __half* qin_h = hb + 0 * BTE;
    __half* qin_l = hb + 1 * BTE;
    __half* kin_h = hb + 2 * BTE;
    __half* kin_l = hb + 3 * BTE;
    __half* Qp_h  = hb + 4 * BTE;
    __half* Qp_l  = hb + 5 * BTE;
    __half* Kp_h  = hb + 6 * BTE;
    __half* Kp_l  = hb + 7 * BTE;
    __half* Vp_h  = hb + 8 * BTE;
    __half* ctx_h = hb + 9 * BTE;
    __half* hid_h = hb + 10 * BTE;           // BT*FF halves
    __half* Pg    = hid_h;                   // alias (free until FFN1)
    __half* wq_h  = hid_h + (size_t)BT_ * FF_;
    __half* wq_l  = wq_h + E_ * E_;
    __half* wk_h  = wq_l + E_ * E_;
    __half* wk_l  = wk_h + E_ * E_;
    __half* wv_h  = wk_l + E_ * E_;
    __half* f1_h  = wv_h + E_ * E_;
    __half* f2_h  = f1_h + (size_t)E_ * FF_;

    const int DS3 = 2 * 4 * P16;   // MODE=3 smem (81920)
    const int DS1 = 2 * 2 * P16;   // MODE=1 smem (40960)
    cudaFuncSetAttribute(hgemm16_kernel<false, false, 3, 2, 1>,
                         cudaFuncAttributeMaxDynamicSharedMemorySize, DS3);
    cudaFuncSetAttribute(hgemm16_kernel<false, false, 1, 1, 2>,
                         cudaFuncAttributeMaxDynamicSharedMemorySize, DS1);
    cudaFuncSetAttribute(hgemm16_kernel<true, false, 1, 1, 2>,
                         cudaFuncAttributeMaxDynamicSharedMemorySize, DS1);
    cudaFuncSetAttribute(hgemm16_kernel<false, true, 1, 0, 2>,
                         cudaFuncAttributeMaxDynamicSharedMemorySize, DS1);
    cudaFuncSetAttribute(attn_sm_kernel,
                         cudaFuncAttributeMaxDynamicSharedMemorySize, A1_SMEM);
    cudaFuncSetAttribute(attn_av_kernel,
                         cudaFuncAttributeMaxDynamicSharedMemorySize, A2_SMEM);

    // 1. weight transposes -> fp16 planes
    transpose_all_kernel<<<2816, dim3(32, 8)>>>(W_Q, W_K, W_V, fw1, fw2,
                                                wq_h, wq_l, wk_h, wk_l, wv_h,
                                                f1_h, f2_h);
    // 2. pos-encode -> qin fp32 + hi/lo planes
    add_pos_kernel<<<(BT_ * E_ / 4) / 256, 256>>>(
        (const float4*)queries, (const float4*)keys,
        (const float4*)pos_q, (const float4*)pos_k,
        (float4*)qin, qin_h, qin_l, kin_h, kin_l);

    dim3 gp(E_ / GBN, BT_ / GBM);
    // 3. Q projection (3-term) -> Qp hi/lo
    hgemm16_kernel<false, false, 3, 2, 1><<<gp, 256, DS3>>>(
        qin_h, qin_l, wq_h, wq_l, nullptr, Qp_h, Qp_l, nullptr, BT_, E_, E_, E_);
    // 4. K projection (3-term) -> Kp hi/lo
    hgemm16_kernel<false, false, 3, 2, 1><<<gp, 256, DS3>>>(
        kin_h, kin_l, wk_h, wk_l, nullptr, Kp_h, Kp_l, nullptr, BT_, E_, E_, E_);
    // 5. V projection (1-term) -> Vp hi
    hgemm16_kernel<false, false, 1, 1, 2><<<gp, 256, DS1>>>(
        kin_h, nullptr, wv_h, nullptr, nullptr, Vp_h, nullptr, nullptr, BT_, E_, E_, E_);

    // 6. attention scores + softmax -> P
    attn_sm_kernel<<<dim3(H_, B_), 256, A1_SMEM>>>(qlen, klen, Qp_h, Qp_l,
                                                   Kp_h, Kp_l, Pg);
    // 7. attention O = P V + residual -> ctx fp32 + ctx_h
    attn_av_kernel<<<dim3(H_, B_), 256, A2_SMEM>>>(qlen, klen, Pg, Vp_h, qin,
                                                   ctx, ctx_h);

    // 8. FFN up + ReLU (1-term) -> hid_h
    hgemm16_kernel<true, false, 1, 1, 2><<<dim3(FF_ / GBN, BT_ / GBM), 256, DS1>>>(
        ctx_h, nullptr, f1_h, nullptr, nullptr, hid_h, nullptr, nullptr,
        BT_, FF_, E_, FF_);
    // 9. FFN down + residual (1-term) -> o2 fp32
    hgemm16_kernel<false, true, 1, 0, 2><<<dim3(E_ / GBN, BT_ / GBM), 256, DS1>>>(
        hid_h, nullptr, f2_h, nullptr, ctx, nullptr, nullptr, o2,
        BT_, E_, FF_, E_);

    // 10. mean over time
    mean_kernel<<<B_, E_>>>(o2, out);
}

// round 17
// speedup vs baseline: 2.6051x; 1.0972x over previous
#include <cuda_runtime.h>
#include <cuda_fp16.h>
#include <math.h>
#include <stdint.h>

// Problem dims
#define B_   256
#define T_   200
#define E_   512
#define H_   8
#define DH_  64
#define FF_  2048
#define BT_  (B_*T_)

#define NEGV (-4294967295.0f)

#define GBM 128
#define GBN 128
#define GBK 32
#define ROWB 80                 // smem row pitch bytes (64B data + 16B pad)
#define P16 (GBM * ROWB)        // 10240 bytes per plane

__device__ __forceinline__ void mma16816(float* c, const uint32_t* a, const uint32_t* b) {
    asm volatile(
        "mma.sync.aligned.m16n8k16.row.col.f32.f16.f16.f32 "
        "{%0,%1,%2,%3}, {%4,%5,%6,%7}, {%8,%9}, {%0,%1,%2,%3};"
        : "+f"(c[0]), "+f"(c[1]), "+f"(c[2]), "+f"(c[3])
        : "r"(a[0]), "r"(a[1]), "r"(a[2]), "r"(a[3]), "r"(b[0]), "r"(b[1]));
}
__device__ __forceinline__ void ldsm_x4(uint32_t* r, uint32_t addr) {
    asm volatile("ldmatrix.sync.aligned.m8n8.x4.shared.b16 {%0,%1,%2,%3}, [%4];"
                 : "=r"(r[0]), "=r"(r[1]), "=r"(r[2]), "=r"(r[3]) : "r"(addr));
}
__device__ __forceinline__ void cp16(uint32_t saddr, const void* g) {
    asm volatile("cp.async.cg.shared.global [%0], [%1], 16;"
                 :: "r"(saddr), "l"(g) : "memory");
}
#define CP_COMMIT() asm volatile("cp.async.commit_group;" ::: "memory")

__device__ __forceinline__ void split2(float x, float y, uint32_t& hi, uint32_t& lo) {
    __half hx = __float2half_rn(x);
    __half hy = __float2half_rn(y);
    __half lx = __float2half_rn(x - __half2float(hx));
    __half ly = __float2half_rn(y - __half2float(hy));
    hi = (uint32_t)__half_as_ushort(hx) | ((uint32_t)__half_as_ushort(hy) << 16);
    lo = (uint32_t)__half_as_ushort(lx) | ((uint32_t)__half_as_ushort(ly) << 16);
}
__device__ __forceinline__ uint32_t hi2(float x, float y) {
    __half hx = __float2half_rn(x);
    __half hy = __float2half_rn(y);
    return (uint32_t)__half_as_ushort(hx) | ((uint32_t)__half_as_ushort(hy) << 16);
}

// ---------------------------------------------------------------------------
// fp16-plane GEMM with cp.async multi-stage pipeline.
// MODE=3: ah*bh + ah*bl + al*bh (3 stages); MODE=1: ah*bh (4 stages).
// EPI: 0 = fp32 out (+C0, opt RELU), 1 = fp16-hi out, 2 = fp16 hi+lo out.
// ---------------------------------------------------------------------------
template <bool RELU, bool ADD, int MODE, int EPI, int MINB>
__global__ void __launch_bounds__(256, MINB)
hgemm16_kernel(const __half* __restrict__ Ah, const __half* __restrict__ Al,
               const __half* __restrict__ Bh, const __half* __restrict__ Bl,
               const float* __restrict__ C0,
               __half* __restrict__ Ch, __half* __restrict__ Cl,
               float* __restrict__ Cf,
               int M, int N, int K, int ldc) {
    extern __shared__ char smem[];
    const uint32_t smb = (uint32_t)__cvta_generic_to_shared(smem);
    constexpr int NP  = (MODE >= 3) ? 4 : 2;
    constexpr int NST = (MODE >= 3) ? 3 : 4;
    constexpr int STG = NP * P16;
    constexpr int OA_HI = 0;
    constexpr int OA_LO = P16;
    constexpr int OB_HI = (MODE >= 3) ? 2 * P16 : P16;
    constexpr int OB_LO = OB_HI + P16;

    const int tid = threadIdx.x;
    const int wid = tid >> 5, lane = tid & 31;
    const int m0 = blockIdx.y * GBM, n0 = blockIdx.x * GBN;
    const int wm = (wid >> 2) * 64, wn = (wid & 3) * 32;
    const int g = lane >> 2, t = lane & 3;
    const int mat = lane >> 3, jr = lane & 7;
    const int a_r    = ((mat & 1) << 3) + jr;
    const int a_koff = (mat >> 1) << 3;
    const int b_koff = (mat & 1) << 3;
    const int b_n    = ((mat >> 1) << 3) + jr;

    float acc[4][4][4];
#pragma unroll
    for (int i = 0; i < 4; i++)
#pragma unroll
        for (int j = 0; j < 4; j++)
#pragma unroll
            for (int k = 0; k < 4; k++) acc[i][j][k] = 0.f;

    const int nt = K / GBK;   // >= 16 always here

    // async stage loader: 512 16B chunks per plane pair set
    auto ISSUE = [&](int s, int k0) {
        const uint32_t sb = smb + s * STG;
#pragma unroll
        for (int j = 0; j < 2; j++) {
            int c = j * 256 + tid;          // 0..511
            int r = c >> 2, c16 = c & 3;
            uint32_t soff = r * ROWB + c16 * 16;
            size_t ga = (size_t)(m0 + r) * K + k0 + c16 * 8;
            size_t gb = (size_t)(n0 + r) * K + k0 + c16 * 8;
            cp16(sb + OA_HI + soff, Ah + ga);
            cp16(sb + OB_HI + soff, Bh + gb);
            if (MODE >= 3) {
                cp16(sb + OA_LO + soff, Al + ga);
                cp16(sb + OB_LO + soff, Bl + gb);
            }
        }
    };

#pragma unroll
    for (int s = 0; s < NST - 1; s++) {     // prologue (nt >= NST-1 guaranteed)
        ISSUE(s, s * GBK);
        CP_COMMIT();
    }

    int stage = 0;
    for (int it = 0; it < nt; it++) {
        asm volatile("cp.async.wait_group %0;" :: "n"(NST - 2) : "memory");
        __syncthreads();

        const uint32_t st = smb + stage * STG;
        const uint32_t ahi = st + OA_HI, alo = st + OA_LO;
        const uint32_t bhi = st + OB_HI, blo = st + OB_LO;

#pragma unroll
        for (int ks = 0; ks < GBK; ks += 16) {
            uint32_t ah[4][4], al[4][4], bh[4][2], bl[4][2];
            const uint32_t a_off = (wm + a_r) * ROWB + (ks + a_koff) * 2;
            const uint32_t b_off = (wn + b_n) * ROWB + (ks + b_koff) * 2;
#pragma unroll
            for (int mt = 0; mt < 4; mt++) {
                ldsm_x4(ah[mt], ahi + a_off + mt * (16 * ROWB));
                if (MODE >= 3) ldsm_x4(al[mt], alo + a_off + mt * (16 * ROWB));
            }
#pragma unroll
            for (int p = 0; p < 2; p++) {
                uint32_t tmp[4];
                ldsm_x4(tmp, bhi + b_off + p * (16 * ROWB));
                bh[2 * p][0] = tmp[0]; bh[2 * p][1] = tmp[1];
                bh[2 * p + 1][0] = tmp[2]; bh[2 * p + 1][1] = tmp[3];
                if (MODE >= 3) {
                    ldsm_x4(tmp, blo + b_off + p * (16 * ROWB));
                    bl[2 * p][0] = tmp[0]; bl[2 * p][1] = tmp[1];
                    bl[2 * p + 1][0] = tmp[2]; bl[2 * p + 1][1] = tmp[3];
                }
            }
#pragma unroll
            for (int mt = 0; mt < 4; mt++)
#pragma unroll
                for (int ntl = 0; ntl < 4; ntl++) {
                    mma16816(acc[mt][ntl], ah[mt], bh[ntl]);
                    if (MODE >= 3) {
                        mma16816(acc[mt][ntl], ah[mt], bl[ntl]);
                        mma16816(acc[mt][ntl], al[mt], bh[ntl]);
                    }
                }
        }

        int nx = it + NST - 1;
        if (nx < nt) {
            int nstage = stage + NST - 1;
            if (nstage >= NST) nstage -= NST;
            ISSUE(nstage, nx * GBK);
        }
        CP_COMMIT();
        if (++stage == NST) stage = 0;
    }

#pragma unroll
    for (int mt = 0; mt < 4; mt++)
#pragma unroll
        for (int ntl = 0; ntl < 4; ntl++) {
            int row = m0 + wm + mt * 16 + g;
            int col = n0 + wn + ntl * 8 + 2 * t;
            size_t i0 = (size_t)row * ldc + col;
            size_t i1 = (size_t)(row + 8) * ldc + col;
            float a0 = acc[mt][ntl][0], a1 = acc[mt][ntl][1];
            float a2 = acc[mt][ntl][2], a3 = acc[mt][ntl][3];
            if (RELU) {
                a0 = fmaxf(a0, 0.f); a1 = fmaxf(a1, 0.f);
                a2 = fmaxf(a2, 0.f); a3 = fmaxf(a3, 0.f);
            }
            if (EPI == 0) {
                float2 v0 = make_float2(a0, a1), v1 = make_float2(a2, a3);
                if (ADD) {
                    float2 c0 = *(const float2*)&C0[i0];
                    float2 c1 = *(const float2*)&C0[i1];
                    v0.x += c0.x; v0.y += c0.y; v1.x += c1.x; v1.y += c1.y;
                }
                *(float2*)&Cf[i0] = v0;
                *(float2*)&Cf[i1] = v1;
            } else if (EPI == 1) {
                *(uint32_t*)&Ch[i0] = hi2(a0, a1);
                *(uint32_t*)&Ch[i1] = hi2(a2, a3);
            } else {
                uint32_t h, l;
                split2(a0, a1, h, l);
                *(uint32_t*)&Ch[i0] = h; *(uint32_t*)&Cl[i0] = l;
                split2(a2, a3, h, l);
                *(uint32_t*)&Ch[i1] = h; *(uint32_t*)&Cl[i1] = l;
            }
        }
}

// ---------------------------------------------------------------------------
// Scratch
// ---------------------------------------------------------------------------
__device__ float g_scratch[(size_t)7 * BT_ * E_ + (size_t)BT_ * FF_ +
                           (3 * E_ * E_ + 2 * E_ * FF_)];

// ---------------------------------------------------------------------------
// pos-encode: qin fp32 (residual) + qin/kin hi/lo fp16 planes
// ---------------------------------------------------------------------------
__global__ void add_pos_kernel(const float4* __restrict__ q,
                               const float4* __restrict__ k,
                               const float4* __restrict__ pq,
                               const float4* __restrict__ pk,
                               float4* __restrict__ qin,
                               __half* __restrict__ qin_h, __half* __restrict__ qin_l,
                               __half* __restrict__ kin_h, __half* __restrict__ kin_l) {
    int i  = blockIdx.x * 256 + threadIdx.x;
    int pi = i % (T_ * E_ / 4);
    const float s = 22.62741699796952f;
    size_t off = (size_t)i * 4;
    float4 a = q[i], p = pq[pi];
    float4 r;
    r.x = a.x + p.x * s; r.y = a.y + p.y * s;
    r.z = a.z + p.z * s; r.w = a.w + p.w * s;
    qin[i] = r;
    uint32_t h01, l01, h23, l23;
    split2(r.x, r.y, h01, l01); split2(r.z, r.w, h23, l23);
    *(uint2*)&qin_h[off] = make_uint2(h01, h23);
    *(uint2*)&qin_l[off] = make_uint2(l01, l23);
    a = k[i]; p = pk[pi];
    r.x = a.x + p.x * s; r.y = a.y + p.y * s;
    r.z = a.z + p.z * s; r.w = a.w + p.w * s;
    split2(r.x, r.y, h01, l01); split2(r.z, r.w, h23, l23);
    *(uint2*)&kin_h[off] = make_uint2(h01, h23);
    *(uint2*)&kin_l[off] = make_uint2(l01, l23);
}

// ---------------------------------------------------------------------------
// all weight transposes -> fp16 hi(/lo) planes.  WT[n,k] = W[k,n]
// ---------------------------------------------------------------------------
__global__ void transpose_all_kernel(
    const float* __restrict__ WQ, const float* __restrict__ WK,
    const float* __restrict__ WV, const float* __restrict__ F1,
    const float* __restrict__ F2,
    __half* __restrict__ wqT_h, __half* __restrict__ wqT_l,
    __half* __restrict__ wkT_h, __half* __restrict__ wkT_l,
    __half* __restrict__ wvT_h,
    __half* __restrict__ f1T_h, __half* __restrict__ f2T_h) {
    __shared__ float t[32][33];
    int bid = blockIdx.x;
    const float* W; __half* WTh; __half* WTl = nullptr; int K, N, tile;
    if (bid < 256)       { W = WQ; WTh = wqT_h; WTl = wqT_l; K = E_;  N = E_;  tile = bid; }
    else if (bid < 512)  { W = WK; WTh = wkT_h; WTl = wkT_l; K = E_;  N = E_;  tile = bid - 256; }
    else if (bid < 768)  { W = WV; WTh = wvT_h;              K = E_;  N = E_;  tile = bid - 512; }
    else if (bid < 1792) { W = F1; WTh = f1T_h;              K = E_;  N = FF_; tile = bid - 768; }
    else                 { W = F2; WTh = f2T_h;              K = FF_; N = E_;  tile = bid - 1792; }
    int ntx = N / 32;
    int bn = (tile % ntx) * 32, bk = (tile / ntx) * 32;
    for (int j = threadIdx.y; j < 32; j += 8)
        t[j][threadIdx.x] = W[(size_t)(bk + j) * N + bn + threadIdx.x];
    __syncthreads();
    for (int j = threadIdx.y; j < 32; j += 8) {
        float x = t[threadIdx.x][j];
        __half hx = __float2half_rn(x);
        size_t idx = (size_t)(bn + j) * K + bk + threadIdx.x;
        WTh[idx] = hx;
        if (WTl) WTl[idx] = __float2half_rn(x - __half2float(hx));
    }
}

// ---------------------------------------------------------------------------
// A1: S = Q K^T (3-term) + softmax -> normalized P fp16 in gmem.
// ---------------------------------------------------------------------------
#define A1_KPB 144
#define A1_SCP 224
#define A1_OFF_KHI 0
#define A1_OFF_KLO 32256
#define A1_OFF_QHI 64512
#define A1_OFF_QLO 69120
#define A1_OFF_SC  73728
#define A1_SMEM    102400
#define PW  224
#define PBH (T_ * PW)

__global__ void __launch_bounds__(256, 2)
attn_sm_kernel(const int* __restrict__ qlen, const int* __restrict__ klen,
               const __half* __restrict__ Qh, const __half* __restrict__ Ql,
               const __half* __restrict__ Kh, const __half* __restrict__ Kl,
               __half* __restrict__ Pg) {
    extern __shared__ char sm[];
    const uint32_t smb = (uint32_t)__cvta_generic_to_shared(sm);
    float* Sc = (float*)(sm + A1_OFF_SC);

    const int h = blockIdx.x, b = blockIdx.y;
    const int tid = threadIdx.x, w = tid >> 5, lane = tid & 31;
    const int kl = klen[b], ql = qlen[b];
    const int kbmax = (kl + 31) >> 5;
    const int lim = kbmax * 32;
    const int g = lane >> 2, t = lane & 3;
    const int mat = lane >> 3, jr = lane & 7;
    const int a_r    = ((mat & 1) << 3) + jr;
    const int a_koff = (mat >> 1) << 3;
    const int b_koff = (mat & 1) << 3;
    const int b_n    = ((mat >> 1) << 3) + jr;
    const size_t pbase = (size_t)(b * H_ + h) * PBH;

    for (int i = tid; i < 224 * 8; i += 256) {
        int tt = i >> 3, c8 = i & 7;
        uint4 vh = make_uint4(0u, 0u, 0u, 0u), vl = vh;
        if (tt < T_) {
            size_t gi = (size_t)(b * T_ + tt) * E_ + h * DH_ + c8 * 8;
            vh = *(const uint4*)&Kh[gi];
            vl = *(const uint4*)&Kl[gi];
        }
        *(uint4*)(sm + A1_OFF_KHI + tt * A1_KPB + c8 * 16) = vh;
        *(uint4*)(sm + A1_OFF_KLO + tt * A1_KPB + c8 * 16) = vl;
    }

    for (int qb = 0; qb < 7; qb++) {
        const int qb0 = qb * 32;
        __syncthreads();
        for (int i = tid; i < 32 * 8; i += 256) {
            int r = i >> 3, c8 = i & 7;
            int qq = qb0 + r;
            uint4 vh = make_uint4(0u, 0u, 0u, 0u), vl = vh;
            if (qq < T_) {
                size_t gi = (size_t)(b * T_ + qq) * E_ + h * DH_ + c8 * 8;
                vh = *(const uint4*)&Qh[gi];
                vl = *(const uint4*)&Ql[gi];
            }
            *(uint4*)(sm + A1_OFF_QHI + r * A1_KPB + c8 * 16) = vh;
            *(uint4*)(sm + A1_OFF_QLO + r * A1_KPB + c8 * 16) = vl;
        }
        __syncthreads();

        {
            const int mt = w >> 2, ns = w & 3;
            uint32_t ah[4][4], al[4][4];
            const uint32_t abase  = smb + A1_OFF_QHI + (mt * 16 + a_r) * A1_KPB + a_koff * 2;
            const uint32_t abasel = abase + (A1_OFF_QLO - A1_OFF_QHI);
#pragma unroll
            for (int ks = 0; ks < 4; ks++) {
                ldsm_x4(ah[ks], abase + ks * 32);
                ldsm_x4(al[ks], abasel + ks * 32);
            }
            for (int p = 0; p < 4; p++) {
                const int np = ns * 64 + p * 16;
                if (np >= lim) break;
                float acc0[4] = {0.f, 0.f, 0.f, 0.f};
                float acc1[4] = {0.f, 0.f, 0.f, 0.f};
#pragma unroll
                for (int ks = 0; ks < 4; ks++) {
                    uint32_t bh[4], bl[4];
                    const uint32_t boff = (np + b_n) * A1_KPB + (ks * 16 + b_koff) * 2;
                    ldsm_x4(bh, smb + A1_OFF_KHI + boff);
                    ldsm_x4(bl, smb + A1_OFF_KLO + boff);
                    mma16816(acc0, ah[ks], bh);
                    mma16816(acc0, ah[ks], bl);
                    mma16816(acc0, al[ks], bh);
                    mma16816(acc1, ah[ks], bh + 2);
                    mma16816(acc1, ah[ks], bl + 2);
                    mma16816(acc1, al[ks], bh + 2);
                }
                const int lr = mt * 16 + g;
                const int q0 = qb0 + lr, q1 = q0 + 8;
#pragma unroll
                for (int hf = 0; hf < 2; hf++) {
                    const float* ac = hf ? acc1 : acc0;
                    const int c = np + hf * 8 + 2 * t;
                    float2 v;
                    v.x = (c     < kl && c     != q0) ? ac[0] * 0.125f : NEGV;
                    v.y = (c + 1 < kl && c + 1 != q0) ? ac[1] * 0.125f : NEGV;
                    *(float2*)&Sc[lr * A1_SCP + c] = v;
                    v.x = (c     < kl && c     != q1) ? ac[2] * 0.125f : NEGV;
                    v.y = (c + 1 < kl && c + 1 != q1) ? ac[3] * 0.125f : NEGV;
                    *(float2*)&Sc[(lr + 8) * A1_SCP + c] = v;
                }
            }
        }
        __syncthreads();

        {
            const int r0 = w * 4;
            float mx[4] = {-INFINITY, -INFINITY, -INFINITY, -INFINITY};
            for (int kb = 0; kb < kbmax; kb++) {
                int kk = kb * 32 + lane;
#pragma unroll
                for (int r = 0; r < 4; r++)
                    mx[r] = fmaxf(mx[r], Sc[(r0 + r) * A1_SCP + kk]);
            }
#pragma unroll
            for (int r = 0; r < 4; r++)
#pragma unroll
                for (int off = 16; off; off >>= 1)
                    mx[r] = fmaxf(mx[r], __shfl_xor_sync(0xffffffff, mx[r], off));

            float sum[4] = {0.f, 0.f, 0.f, 0.f};
            for (int kb = 0; kb < kbmax; kb++) {
                int kk = kb * 32 + lane;
#pragma unroll
                for (int r = 0; r < 4; r++) {
                    float e = __expf(Sc[(r0 + r) * A1_SCP + kk] - mx[r]);
                    Sc[(r0 + r) * A1_SCP + kk] = e;
                    sum[r] += e;
                }
            }
            if (kl == 1) {
                for (int kb = 1; kb < 7; kb++) {
                    int kk = kb * 32 + lane;
#pragma unroll
                    for (int r = 0; r < 4; r++) {
                        float v = (mx[r] == NEGV && kk < T_) ? 1.f : 0.f;
                        Sc[(r0 + r) * A1_SCP + kk] = v;
                        sum[r] += v;
                    }
                }
            }
#pragma unroll
            for (int r = 0; r < 4; r++)
#pragma unroll
                for (int off = 16; off; off >>= 1)
                    sum[r] += __shfl_xor_sync(0xffffffff, sum[r], off);

            const int cmax = (kl == 1) ? 7 : kbmax;
#pragma unroll
            for (int r = 0; r < 4; r++) {
                int qq = qb0 + r0 + r;
                if (qq < T_) {
                    float inv = (qq < ql) ? (1.f / sum[r]) : 0.f;
                    for (int kb = 0; kb < cmax; kb++) {
                        int kk = kb * 32 + lane;
                        Pg[pbase + (size_t)qq * PW + kk] =
                            __float2half_rn(Sc[(r0 + r) * A1_SCP + kk] * inv);
                    }
                }
            }
        }
    }
}

// ---------------------------------------------------------------------------
// A2: O = P V + qin residual; writes ctx fp32 + ctx_h fp16.
// ---------------------------------------------------------------------------
#define A2_VP 232
#define A2_VPB (A2_VP * 2)
#define A2_OFF_VT 0
#define A2_OFF_P  29696
#define A2_SMEM   (A2_OFF_P + 32 * A2_VPB)

__global__ void __launch_bounds__(256, 2)
attn_av_kernel(const int* __restrict__ qlen, const int* __restrict__ klen,
               const __half* __restrict__ Pg, const __half* __restrict__ Vh,
               const float* __restrict__ qin,
               float* __restrict__ ctx, __half* __restrict__ ctx_h) {
    extern __shared__ char sm[];
    const uint32_t smb = (uint32_t)__cvta_generic_to_shared(sm);
    __half* vt = (__half*)(sm + A2_OFF_VT);

    const int h = blockIdx.x, b = blockIdx.y;
    const int tid = threadIdx.x, w = tid >> 5, lane = tid & 31;
    const int kl = klen[b];
    const int kbmax = (kl + 31) >> 5;
    const int kks = (kl == 1) ? 14 : 2 * kbmax;
    const int g = lane >> 2, t = lane & 3;
    const int mat = lane >> 3, jr = lane & 7;
    const int a_r    = ((mat & 1) << 3) + jr;
    const int a_koff = (mat >> 1) << 3;
    const int b_koff = (mat & 1) << 3;
    const int b_n    = ((mat >> 1) << 3) + jr;
    const size_t pbase = (size_t)(b * H_ + h) * PBH;

    for (int i = tid; i < 224 * 8; i += 256) {
        int tt = i >> 3, c8 = i & 7;
        uint4 v = make_uint4(0u, 0u, 0u, 0u);
        if (tt < T_)
            v = *(const uint4*)&Vh[(size_t)(b * T_ + tt) * E_ + h * DH_ + c8 * 8];
        const __half* hp = (const __half*)&v;
#pragma unroll
        for (int d = 0; d < 8; d++)
            vt[(c8 * 8 + d) * A2_VP + tt] = hp[d];
    }

    for (int qb = 0; qb < 7; qb++) {
        const int qb0 = qb * 32;
        __syncthreads();
        for (int i = tid; i < 32 * 28; i += 256) {
            int r = i / 28, c4 = i % 28;
            int qq = qb0 + r;
            uint4 v = make_uint4(0u, 0u, 0u, 0u);
            if (qq < T_)
                v = *(const uint4*)&Pg[pbase + (size_t)qq * PW + c4 * 8];
            *(uint4*)(sm + A2_OFF_P + r * A2_VPB + c4 * 16) = v;
        }
        __syncthreads();

        const int mt = w >> 2, nq = w & 3;
        float acc[2][4];
#pragma unroll
        for (int j = 0; j < 2; j++)
#pragma unroll
            for (int k = 0; k < 4; k++) acc[j][k] = 0.f;
        for (int ks = 0; ks < kks; ks++) {
            uint32_t ap[4];
            ldsm_x4(ap, smb + A2_OFF_P + (mt * 16 + a_r) * A2_VPB + (ks * 16 + a_koff) * 2);
            uint32_t bv[4];
            ldsm_x4(bv, smb + A2_OFF_VT + (nq * 16 + b_n) * A2_VPB + (ks * 16 + b_koff) * 2);
            mma16816(acc[0], ap, bv);
            mma16816(acc[1], ap, bv + 2);
        }
        const int lr = mt * 16 + g;
        const int q0 = qb0 + lr, q1 = q0 + 8;
#pragma unroll
        for (int j = 0; j < 2; j++) {
            const int dh = nq * 16 + j * 8 + 2 * t;
            if (q0 < T_) {
                size_t base = (size_t)(b * T_ + q0) * E_ + h * DH_ + dh;
                float2 qi = *(const float2*)&qin[base];
                float2 o = make_float2(acc[j][0] + qi.x, acc[j][1] + qi.y);
                *(float2*)&ctx[base] = o;
                *(uint32_t*)&ctx_h[base] = hi2(o.x, o.y);
            }
            if (q1 < T_) {
                size_t base = (size_t)(b * T_ + q1) * E_ + h * DH_ + dh;
                float2 qi = *(const float2*)&qin[base];
                float2 o = make_float2(acc[j][2] + qi.x, acc[j][3] + qi.y);
                *(float2*)&ctx[base] = o;
                *(uint32_t*)&ctx_h[base] = hi2(o.x, o.y);
            }
        }
    }
}

// ---------------------------------------------------------------------------
// mean over T -> (B,1,E)
// ---------------------------------------------------------------------------
__global__ void mean_kernel(const float* __restrict__ o2, float* __restrict__ out) {
    int b = blockIdx.x, e = threadIdx.x;
    float s = 0.f;
    for (int t = 0; t < T_; t++)
        s += o2[(size_t)(b * T_ + t) * E_ + e];
    out[b * E_ + e] = s * (1.0f / T_);
}

// ---------------------------------------------------------------------------
// Launch
// ---------------------------------------------------------------------------
extern "C" void kernel_launch(void* const* d_in, const int* in_sizes, int n_in,
                              void* d_out, int out_size) {
    const float* queries = (const float*)d_in[0];
    const float* keys    = (const float*)d_in[1];
    const int*   qlen    = (const int*)d_in[2];
    const int*   klen    = (const int*)d_in[3];
    const float* pos_q   = (const float*)d_in[4];
    const float* pos_k   = (const float*)d_in[5];
    const float* W_Q     = (const float*)d_in[6];
    const float* W_K     = (const float*)d_in[7];
    const float* W_V     = (const float*)d_in[8];
    const float* fw1     = (const float*)d_in[9];
    const float* fw2     = (const float*)d_in[10];
    float*       out     = (float*)d_out;

    float* base = nullptr;
    cudaGetSymbolAddress((void**)&base, g_scratch);
    const size_t BTE = (size_t)BT_ * E_;

    float* qin = base;
    float* ctx = base + BTE;
    float* o2  = base + 2 * BTE;
    __half* hb = (__half*)(base + 3 * BTE);
    __half* qin_h = hb + 0 * BTE;
    __half* qin_l = hb + 1 * BTE;
    __half* kin_h = hb + 2 * BTE;
    __half* kin_l = hb + 3 * BTE;
    __half* Qp_h  = hb + 4 * BTE;
    __half* Qp_l  = hb + 5 * BTE;
    __half* Kp_h  = hb + 6 * BTE;
    __half* Kp_l  = hb + 7 * BTE;
    __half* Vp_h  = hb + 8 * BTE;
    __half* ctx_h = hb + 9 * BTE;
    __half* hid_h = hb + 10 * BTE;
    __half* Pg    = hid_h;
    __half* wq_h  = hid_h + (size_t)BT_ * FF_;
    __half* wq_l  = wq_h + E_ * E_;
    __half* wk_h  = wq_l + E_ * E_;
    __half* wk_l  = wk_h + E_ * E_;
    __half* wv_h  = wk_l + E_ * E_;
    __half* f1_h  = wv_h + E_ * E_;
    __half* f2_h  = f1_h + (size_t)E_ * FF_;

    const int DS3 = 3 * 4 * P16;   // MODE=3: 3 stages x 4 planes = 122880
    const int DS1 = 4 * 2 * P16;   // MODE=1: 4 stages x 2 planes = 81920
    cudaFuncSetAttribute(hgemm16_kernel<false, false, 3, 2, 1>,
                         cudaFuncAttributeMaxDynamicSharedMemorySize, DS3);
    cudaFuncSetAttribute(hgemm16_kernel<false, false, 1, 1, 2>,
                         cudaFuncAttributeMaxDynamicSharedMemorySize, DS1);
    cudaFuncSetAttribute(hgemm16_kernel<true, false, 1, 1, 2>,
                         cudaFuncAttributeMaxDynamicSharedMemorySize, DS1);
    cudaFuncSetAttribute(hgemm16_kernel<false, true, 1, 0, 2>,
                         cudaFuncAttributeMaxDynamicSharedMemorySize, DS1);
    cudaFuncSetAttribute(attn_sm_kernel,
                         cudaFuncAttributeMaxDynamicSharedMemorySize, A1_SMEM);
    cudaFuncSetAttribute(attn_av_kernel,
                         cudaFuncAttributeMaxDynamicSharedMemorySize, A2_SMEM);

    // 1. weight transposes -> fp16 planes
    transpose_all_kernel<<<2816, dim3(32, 8)>>>(W_Q, W_K, W_V, fw1, fw2,
                                                wq_h, wq_l, wk_h, wk_l, wv_h,
                                                f1_h, f2_h);
    // 2. pos-encode -> qin fp32 + hi/lo planes
    add_pos_kernel<<<(BT_ * E_ / 4) / 256, 256>>>(
        (const float4*)queries, (const float4*)keys,
        (const float4*)pos_q, (const float4*)pos_k,
        (float4*)qin, qin_h, qin_l, kin_h, kin_l);

    dim3 gp(E_ / GBN, BT_ / GBM);
    // 3. Q projection (3-term) -> Qp hi/lo
    hgemm16_kernel<false, false, 3, 2, 1><<<gp, 256, DS3>>>(
        qin_h, qin_l, wq_h, wq_l, nullptr, Qp_h, Qp_l, nullptr, BT_, E_, E_, E_);
    // 4. K projection (3-term) -> Kp hi/lo
    hgemm16_kernel<false, false, 3, 2, 1><<<gp, 256, DS3>>>(
        kin_h, kin_l, wk_h, wk_l, nullptr, Kp_h, Kp_l, nullptr, BT_, E_, E_, E_);
    // 5. V projection (1-term) -> Vp hi
    hgemm16_kernel<false, false, 1, 1, 2><<<gp, 256, DS1>>>(
        kin_h, nullptr, wv_h, nullptr, nullptr, Vp_h, nullptr, nullptr, BT_, E_, E_, E_);

    // 6. attention scores + softmax -> P
    attn_sm_kernel<<<dim3(H_, B_), 256, A1_SMEM>>>(qlen, klen, Qp_h, Qp_l,
                                                   Kp_h, Kp_l, Pg);
    // 7. attention O = P V + residual -> ctx fp32 + ctx_h
    attn_av_kernel<<<dim3(H_, B_), 256, A2_SMEM>>>(qlen, klen, Pg, Vp_h, qin,
                                                   ctx, ctx_h);

    // 8. FFN up + ReLU (1-term) -> hid_h
    hgemm16_kernel<true, false, 1, 1, 2><<<dim3(FF_ / GBN, BT_ / GBM), 256, DS1>>>(
        ctx_h, nullptr, f1_h, nullptr, nullptr, hid_h, nullptr, nullptr,
        BT_, FF_, E_, FF_);
    // 9. FFN down + residual (1-term) -> o2 fp32
    hgemm16_kernel<false, true, 1, 0, 2><<<dim3(E_ / GBN, BT_ / GBM), 256, DS1>>>(
        hid_h, nullptr, f2_h, nullptr, ctx, nullptr, nullptr, o2,
        BT_, E_, FF_, E_);

    // 10. mean over time
    mean_kernel<<<B_, E_>>>(o2, out);
}